// round 5
// baseline (speedup 1.0000x reference)
#include <cuda_runtime.h>
#include <cuda_bf16.h>
#include <math.h>
#include <stdint.h>

#define MROWS 16384
#define DIMX 1024
#define DPROJ 4192
#define DIN 2048
#define NH 32
#define HD 64
#define DS 32
#define LSEQ 4096
#define NC 64
#define NPAD_IN 4224

// ---------------- scratch ----------------
__device__ float g_zx[(size_t)MROWS * DPROJ];
__device__ float g_Brot[(size_t)MROWS * DS];
__device__ float g_Crot[(size_t)MROWS * DS];
__device__ float g_states[(size_t)4 * NC * NH * HD * DS];
__device__ float g_stin[(size_t)4 * NC * NH * HD * DS];
__device__ float g_csum[4 * NH * NC];
__device__ float g_y[(size_t)MROWS * DIN];
__device__ unsigned short g_Ahi[(size_t)MROWS * DIN];     // bf16 bits
__device__ unsigned short g_Alo[(size_t)MROWS * DIN];
__device__ unsigned short g_Bthi[(size_t)NPAD_IN * 1024];
__device__ unsigned short g_Btlo[(size_t)NPAD_IN * 1024];

__device__ __forceinline__ float siluf(float x) { return x / (1.f + __expf(-x)); }

__device__ __forceinline__ void splitbf(float f, unsigned short& hi, unsigned short& lo) {
    __nv_bfloat16 h = __float2bfloat16(f);
    float r = f - __bfloat162float(h);
    __nv_bfloat16 l = __float2bfloat16(r);
    hi = *reinterpret_cast<unsigned short*>(&h);
    lo = *reinterpret_cast<unsigned short*>(&l);
}

__device__ __forceinline__ uint32_t smem_u32(const void* p) {
    uint32_t a;
    asm("{ .reg .u64 t; cvta.to.shared.u64 t, %1; cvt.u32.u64 %0, t; }" : "=r"(a) : "l"(p));
    return a;
}
__device__ __forceinline__ void cpasync16(uint32_t dst, const void* src) {
    asm volatile("cp.async.cg.shared.global [%0], [%1], 16;" :: "r"(dst), "l"(src) : "memory");
}
__device__ __forceinline__ void mma16816(float* c, const uint32_t* a, const uint32_t* b) {
    asm volatile(
        "mma.sync.aligned.m16n8k16.row.col.f32.bf16.bf16.f32 "
        "{%0,%1,%2,%3}, {%4,%5,%6,%7}, {%8,%9}, {%0,%1,%2,%3};\n"
        : "+f"(c[0]), "+f"(c[1]), "+f"(c[2]), "+f"(c[3])
        : "r"(a[0]), "r"(a[1]), "r"(a[2]), "r"(a[3]), "r"(b[0]), "r"(b[1]));
}

// ---------------- LayerNorm ----------------
__global__ __launch_bounds__(256) void ln_kernel(const float* __restrict__ x,
                                                 const float* __restrict__ w,
                                                 const float* __restrict__ b)
{
    int row = blockIdx.x;
    int tid = threadIdx.x;
    const float* xr = x + (size_t)row * DIMX;
    float4 v = *(const float4*)(xr + tid * 4);
    float s  = v.x + v.y + v.z + v.w;
    float s2 = v.x*v.x + v.y*v.y + v.z*v.z + v.w*v.w;
    for (int o = 16; o; o >>= 1) {
        s  += __shfl_down_sync(0xffffffffu, s,  o);
        s2 += __shfl_down_sync(0xffffffffu, s2, o);
    }
    __shared__ float ss[8], ss2[8];
    if ((tid & 31) == 0) { ss[tid >> 5] = s; ss2[tid >> 5] = s2; }
    __syncthreads();
    if (tid == 0) {
        float t = 0.f, t2 = 0.f;
        for (int i = 0; i < 8; i++) { t += ss[i]; t2 += ss2[i]; }
        float mu = t / DIMX;
        ss[0]  = mu;
        ss2[0] = rsqrtf(t2 / DIMX - mu * mu + 1e-6f);
    }
    __syncthreads();
    float mu = ss[0], inv = ss2[0];
    int i0 = tid * 4;
    float4 wv = *(const float4*)(w + i0);
    float4 bv = *(const float4*)(b + i0);
    float o0 = (v.x - mu) * inv * wv.x + bv.x;
    float o1 = (v.y - mu) * inv * wv.y + bv.y;
    float o2 = (v.z - mu) * inv * wv.z + bv.z;
    float o3 = (v.w - mu) * inv * wv.w + bv.w;
    ushort4 hv, lv;
    splitbf(o0, hv.x, lv.x); splitbf(o1, hv.y, lv.y);
    splitbf(o2, hv.z, lv.z); splitbf(o3, hv.w, lv.w);
    *(ushort4*)(g_Ahi + (size_t)row * DIMX + i0) = hv;
    *(ushort4*)(g_Alo + (size_t)row * DIMX + i0) = lv;
}

// ---------------- W[K,N] -> Bt[n][k] bf16 hi/lo ----------------
__global__ __launch_bounds__(1024) void cvtT_kernel(const float* __restrict__ W, int K, int N)
{
    __shared__ float t[32][33];
    int k0 = blockIdx.x * 32, n0 = blockIdx.y * 32;
    int tx = threadIdx.x, ty = threadIdx.y;
    int n = n0 + tx;
    t[ty][tx] = (n < N) ? W[(size_t)(k0 + ty) * N + n] : 0.f;
    __syncthreads();
    float v = t[tx][ty];
    unsigned short hi, lo;
    splitbf(v, hi, lo);
    size_t o = (size_t)(n0 + ty) * K + k0 + tx;
    g_Bthi[o] = hi;
    g_Btlo[o] = lo;
}

// ---------------- mma.sync bf16 GEMM, hi/lo 3-pass ----------------
#define KSTAGE 40960
#define SMEM_GEMM (2 * KSTAGE)
__global__ __launch_bounds__(256, 1) void mma_gemm(
    const unsigned short* __restrict__ Ahi, const unsigned short* __restrict__ Alo,
    const unsigned short* __restrict__ Bhi, const unsigned short* __restrict__ Blo,
    const float* __restrict__ R, float* __restrict__ C, int N, int K)
{
    extern __shared__ char sm[];
    int tid = threadIdx.x, lane = tid & 31, wid = tid >> 5;
    int col0 = blockIdx.x * 128, row0 = blockIdx.y * 128;
    int g = lane >> 2, tig = lane & 3;
    int m0 = (wid >> 2) * 64, n0 = (wid & 3) * 32;
    uint32_t sb = smem_u32(sm);

    float acc[4][4][4];
#pragma unroll
    for (int i = 0; i < 4; i++)
#pragma unroll
        for (int j = 0; j < 4; j++)
#pragma unroll
            for (int q = 0; q < 4; q++) acc[i][j][q] = 0.f;

    const unsigned short* srcs[4] = {Ahi, Alo, Bhi, Blo};
    int rbs[4] = {row0, row0, col0, col0};

    int KT = K >> 5;
    {
#pragma unroll
        for (int t = 0; t < 4; t++) {
#pragma unroll
            for (int cc = 0; cc < 2; cc++) {
                int chunk = tid + cc * 256;
                int row = chunk >> 2, c4 = chunk & 3;
                const void* src = srcs[t] + (size_t)(rbs[t] + row) * K + c4 * 8;
                cpasync16(sb + t * 10240 + row * 80 + c4 * 16, src);
            }
        }
        asm volatile("cp.async.commit_group;" ::: "memory");
    }

    for (int kt = 0; kt < KT; kt++) {
        if (kt + 1 < KT) {
            int buf = (kt + 1) & 1;
#pragma unroll
            for (int t = 0; t < 4; t++) {
#pragma unroll
                for (int cc = 0; cc < 2; cc++) {
                    int chunk = tid + cc * 256;
                    int row = chunk >> 2, c4 = chunk & 3;
                    const void* src = srcs[t] + (size_t)(rbs[t] + row) * K + (kt + 1) * 32 + c4 * 8;
                    cpasync16(sb + buf * KSTAGE + t * 10240 + row * 80 + c4 * 16, src);
                }
            }
            asm volatile("cp.async.commit_group;" ::: "memory");
            asm volatile("cp.async.wait_group 1;" ::: "memory");
        } else {
            asm volatile("cp.async.wait_group 0;" ::: "memory");
        }
        __syncthreads();

        const char* stb = sm + (kt & 1) * KSTAGE;
#pragma unroll
        for (int ks = 0; ks < 2; ks++) {
            int wb = (ks * 8 + tig) * 4;
            uint32_t bh[4][2], bl[4][2];
#pragma unroll
            for (int nt = 0; nt < 4; nt++) {
                const char* pb = stb + 20480 + (n0 + nt * 8 + g) * 80 + wb;
                bh[nt][0] = *(const uint32_t*)(pb);
                bh[nt][1] = *(const uint32_t*)(pb + 16);
                bl[nt][0] = *(const uint32_t*)(pb + 10240);
                bl[nt][1] = *(const uint32_t*)(pb + 10240 + 16);
            }
#pragma unroll
            for (int mt = 0; mt < 4; mt++) {
                const char* pa = stb + (m0 + mt * 16 + g) * 80 + wb;
                uint32_t ah[4], al[4];
                ah[0] = *(const uint32_t*)(pa);
                ah[1] = *(const uint32_t*)(pa + 8 * 80);
                ah[2] = *(const uint32_t*)(pa + 16);
                ah[3] = *(const uint32_t*)(pa + 8 * 80 + 16);
                al[0] = *(const uint32_t*)(pa + 10240);
                al[1] = *(const uint32_t*)(pa + 10240 + 8 * 80);
                al[2] = *(const uint32_t*)(pa + 10240 + 16);
                al[3] = *(const uint32_t*)(pa + 10240 + 8 * 80 + 16);
#pragma unroll
                for (int nt = 0; nt < 4; nt++) {
                    mma16816(acc[mt][nt], ah, bh[nt]);
                    mma16816(acc[mt][nt], ah, bl[nt]);
                    mma16816(acc[mt][nt], al, bh[nt]);
                }
            }
        }
        __syncthreads();
    }

#pragma unroll
    for (int mt = 0; mt < 4; mt++) {
        int r0i = row0 + m0 + mt * 16 + g;
#pragma unroll
        for (int nt = 0; nt < 4; nt++) {
            int cc = col0 + n0 + nt * 8 + tig * 2;
            if (cc < N) {
                float* p0 = C + (size_t)r0i * N + cc;
                float* p1 = C + (size_t)(r0i + 8) * N + cc;
                float2 v0 = make_float2(acc[mt][nt][0], acc[mt][nt][1]);
                float2 v1 = make_float2(acc[mt][nt][2], acc[mt][nt][3]);
                if (R) {
                    const float* q0 = R + (size_t)r0i * N + cc;
                    const float* q1 = R + (size_t)(r0i + 8) * N + cc;
                    v0.x += q0[0]; v0.y += q0[1];
                    v1.x += q1[0]; v1.y += q1[1];
                }
                *(float2*)p0 = v0;
                *(float2*)p1 = v1;
            }
        }
    }
}

// ---------------- silu + RoPE ----------------
__global__ __launch_bounds__(256) void bcrope_kernel()
{
    int tid = threadIdx.x;
    int r8 = tid >> 5, n = tid & 31;
    int row = blockIdx.x * 8 + r8;
    int t = row & (LSEQ - 1);
    const float* base = g_zx + (size_t)row * DPROJ;
    float bo, co;
    if (n < 16) {
        int j = n >> 1;
        double invd = exp(-((double)j) * (log(10000.0) / 8.0));
        float inv = (float)invd;
        float ang = (float)t * inv;
        float sn, cs;
        sincosf(ang, &sn, &cs);
        float b1 = siluf(base[4096 + 2 * j]);
        float b2 = siluf(base[4096 + 2 * j + 1]);
        float c1 = siluf(base[4128 + 2 * j]);
        float c2 = siluf(base[4128 + 2 * j + 1]);
        if (n & 1) { bo = b1 * sn + b2 * cs; co = c1 * sn + c2 * cs; }
        else       { bo = b1 * cs - b2 * sn; co = c1 * cs - c2 * sn; }
    } else {
        bo = siluf(base[4096 + n]);
        co = siluf(base[4128 + n]);
    }
    g_Brot[(size_t)row * DS + n] = bo;
    g_Crot[(size_t)row * DS + n] = co;
}

// ---------------- SSD intra-chunk (float4-vectorized smem) ----------------
__global__ __launch_bounds__(256) void chunk_kernel(
    const float* __restrict__ dt_bias, const float* __restrict__ A_log,
    const float* __restrict__ Dv)
{
    int blk = blockIdx.x;
    int h = blk & 31; int bcid = blk >> 5; int c = bcid & 63; int b = bcid >> 6;
    __shared__ float Cs[64][36], Bsm[64][36], xh[64][68], Pt[64][17];
    __shared__ float acs[64], dtv[64], wv[64];
    int tid = threadIdx.x;
    int rowbase = b * LSEQ + c * 64;

    if (tid < 64) {
        float raw = g_zx[(size_t)(rowbase + tid) * DPROJ + 4160 + h] + dt_bias[h];
        dtv[tid] = (raw > 20.f) ? raw : log1pf(__expf(raw));
    }
    __syncthreads();
    if (tid == 0) {
        float A = -__expf(A_log[h]);
        float s = 0.f;
        for (int l = 0; l < 64; l++) { s += dtv[l] * A; acs[l] = s; }
    }
    for (int i = tid; i < 64 * 32; i += 256) {
        int l = i >> 5, n = i & 31;
        Bsm[l][n] = g_Brot[(size_t)(rowbase + l) * DS + n];
        Cs[l][n]  = g_Crot[(size_t)(rowbase + l) * DS + n];
    }
    for (int i = tid; i < 64 * 64; i += 256) {
        int l = i >> 6, p = i & 63;
        float v = g_zx[(size_t)(rowbase + l) * DPROJ + 2048 + h * 64 + p];
        xh[l][p] = siluf(v);
    }
    __syncthreads();

    int l  = tid >> 2;
    int pb = (tid & 3) << 4;
    float acc[16];
#pragma unroll
    for (int j = 0; j < 16; j++) acc[j] = 0.f;

    const float4* CsV  = (const float4*)&Cs[l][0];
    for (int st = 0; st < 4; st++) {
#pragma unroll
        for (int i = 0; i < 4; i++) {
            int ss = ((tid & 3) << 2) + i;
            int s  = (st << 4) + ss;
            float v = 0.f;
            if (s <= l) {
                const float4* BsV = (const float4*)&Bsm[s][0];
                float d = 0.f;
#pragma unroll
                for (int q = 0; q < 8; q++) {
                    float4 cv = CsV[q];
                    float4 bv = BsV[q];
                    d = fmaf(cv.x, bv.x, d); d = fmaf(cv.y, bv.y, d);
                    d = fmaf(cv.z, bv.z, d); d = fmaf(cv.w, bv.w, d);
                }
                v = d * __expf(acs[l] - acs[s]) * dtv[s];
            }
            Pt[l][ss] = v;
        }
        __syncthreads();
#pragma unroll
        for (int ss = 0; ss < 16; ss++) {
            float m = Pt[l][ss];
            int s = (st << 4) + ss;
            const float4* xv4 = (const float4*)&xh[s][pb];
#pragma unroll
            for (int q = 0; q < 4; q++) {
                float4 xv = xv4[q];
                acc[q * 4 + 0] = fmaf(m, xv.x, acc[q * 4 + 0]);
                acc[q * 4 + 1] = fmaf(m, xv.y, acc[q * 4 + 1]);
                acc[q * 4 + 2] = fmaf(m, xv.z, acc[q * 4 + 2]);
                acc[q * 4 + 3] = fmaf(m, xv.w, acc[q * 4 + 3]);
            }
        }
        __syncthreads();
    }

    float Dh = Dv[h];
    float* yrow = g_y + (size_t)(rowbase + l) * DIN + h * HD + pb;
#pragma unroll
    for (int j = 0; j < 16; j++) yrow[j] = acc[j] + Dh * xh[l][pb + j];

    if (tid < 64) wv[tid] = dtv[tid] * __expf(acs[63] - acs[tid]);
    __syncthreads();
    for (int i = tid; i < 64 * 32; i += 256) { int ll = i >> 5, n = i & 31; Bsm[ll][n] *= wv[ll]; }
    __syncthreads();
    int p  = tid >> 2;
    int nb = (tid & 3) << 3;
    float st8[8];
#pragma unroll
    for (int j = 0; j < 8; j++) st8[j] = 0.f;
    for (int l2 = 0; l2 < 64; l2 += 2) {
        float xv0 = xh[l2][p], xv1 = xh[l2 + 1][p];
        const float4* b0 = (const float4*)&Bsm[l2][nb];
        const float4* b1 = (const float4*)&Bsm[l2 + 1][nb];
        float4 b00 = b0[0], b01 = b0[1], b10 = b1[0], b11 = b1[1];
        st8[0] = fmaf(xv0, b00.x, st8[0]); st8[1] = fmaf(xv0, b00.y, st8[1]);
        st8[2] = fmaf(xv0, b00.z, st8[2]); st8[3] = fmaf(xv0, b00.w, st8[3]);
        st8[4] = fmaf(xv0, b01.x, st8[4]); st8[5] = fmaf(xv0, b01.y, st8[5]);
        st8[6] = fmaf(xv0, b01.z, st8[6]); st8[7] = fmaf(xv0, b01.w, st8[7]);
        st8[0] = fmaf(xv1, b10.x, st8[0]); st8[1] = fmaf(xv1, b10.y, st8[1]);
        st8[2] = fmaf(xv1, b10.z, st8[2]); st8[3] = fmaf(xv1, b10.w, st8[3]);
        st8[4] = fmaf(xv1, b11.x, st8[4]); st8[5] = fmaf(xv1, b11.y, st8[5]);
        st8[6] = fmaf(xv1, b11.z, st8[6]); st8[7] = fmaf(xv1, b11.w, st8[7]);
    }
    size_t sbase = ((size_t)((b * NC + c) * NH + h)) * (HD * DS);
#pragma unroll
    for (int j = 0; j < 8; j++) g_states[sbase + p * DS + nb + j] = st8[j];
    if (tid == 0) g_csum[(b * NH + h) * NC + c] = acs[63];
}

// ---------------- inter-chunk scan (1 elem/thread, 1024 blocks) ----------------
__global__ __launch_bounds__(256) void scan_kernel()
{
    int bh = blockIdx.x >> 3;               // b*NH + h
    int part = blockIdx.x & 7;
    int e = part * 256 + threadIdx.x;       // 0..2047
    int b = bh >> 5, h = bh & 31;
    size_t stride = (size_t)NH * HD * DS;
    size_t base = ((size_t)(b * NC) * NH + h) * (HD * DS) + e;
    float S = 0.f;
    for (int c = 0; c < NC; c++) {
        g_stin[base] = S;
        float e1 = __expf(g_csum[bh * NC + c]);
        S = S * e1 + g_states[base];
        base += stride;
    }
}

// ---------------- Yo (float4-vectorized smem) ----------------
__global__ __launch_bounds__(256) void yo_kernel(
    const float* __restrict__ dt_bias, const float* __restrict__ A_log)
{
    int blk = blockIdx.x;
    int h = blk & 31; int bcid = blk >> 5; int c = bcid & 63; int b = bcid >> 6;
    __shared__ float Cs[64][36], Sm[64][36];
    __shared__ float acs[64], dtv[64];
    int tid = threadIdx.x;
    int rowbase = b * LSEQ + c * 64;

    if (tid < 64) {
        float raw = g_zx[(size_t)(rowbase + tid) * DPROJ + 4160 + h] + dt_bias[h];
        dtv[tid] = (raw > 20.f) ? raw : log1pf(__expf(raw));
    }
    __syncthreads();
    if (tid == 0) {
        float A = -__expf(A_log[h]);
        float s = 0.f;
        for (int l = 0; l < 64; l++) { s += dtv[l] * A; acs[l] = s; }
    }
    size_t sbase = ((size_t)((b * NC + c) * NH + h)) * (HD * DS);
    for (int i = tid; i < 64 * 32; i += 256) {
        int l = i >> 5, n = i & 31;
        Cs[l][n] = g_Crot[(size_t)(rowbase + l) * DS + n];
        Sm[l][n] = g_stin[sbase + i];
    }
    __syncthreads();

    int l  = tid >> 2;
    int pb = (tid & 3) << 4;
    float el = __expf(acs[l]);
    float* yrow = g_y + (size_t)(rowbase + l) * DIN + h * HD;
    float4 cv[8];
    const float4* CsV = (const float4*)&Cs[l][0];
#pragma unroll
    for (int q = 0; q < 8; q++) cv[q] = CsV[q];
#pragma unroll
    for (int j = 0; j < 16; j++) {
        int p = pb + j;
        const float4* SmV = (const float4*)&Sm[p][0];
        float d = 0.f;
#pragma unroll
        for (int q = 0; q < 8; q++) {
            float4 sv = SmV[q];
            d = fmaf(cv[q].x, sv.x, d); d = fmaf(cv[q].y, sv.y, d);
            d = fmaf(cv[q].z, sv.z, d); d = fmaf(cv[q].w, sv.w, d);
        }
        yrow[p] += el * d;
    }
}

// ---------------- gate + RMSNorm ----------------
__global__ __launch_bounds__(256) void gate_kernel(const float* __restrict__ rms_w)
{
    int row = blockIdx.x;
    int tid = threadIdx.x;
    const float* yr = g_y + (size_t)row * DIN;
    const float* zr = g_zx + (size_t)row * DPROJ;
    float v[8]; float s2 = 0.f;
#pragma unroll
    for (int i = 0; i < 8; i++) {
        int idx = tid + i * 256;
        float y = yr[idx];
        float z = zr[idx];
        y *= siluf(z);
        v[i] = y;
        s2 = fmaf(y, y, s2);
    }
    for (int o = 16; o; o >>= 1) s2 += __shfl_down_sync(0xffffffffu, s2, o);
    __shared__ float red[8];
    if ((tid & 31) == 0) red[tid >> 5] = s2;
    __syncthreads();
    if (tid == 0) {
        float t = 0.f;
        for (int i = 0; i < 8; i++) t += red[i];
        red[0] = rsqrtf(t / DIN + 1e-6f);
    }
    __syncthreads();
    float sc = red[0];
    size_t base = (size_t)row * DIN;
#pragma unroll
    for (int i = 0; i < 8; i++) {
        int idx = tid + i * 256;
        float f = v[i] * sc * rms_w[idx];
        unsigned short hi, lo;
        splitbf(f, hi, lo);
        g_Ahi[base + idx] = hi;
        g_Alo[base + idx] = lo;
    }
}

// ---------------- launch ----------------
extern "C" void kernel_launch(void* const* d_in, const int* in_sizes, int n_in,
                              void* d_out, int out_size)
{
    (void)in_sizes; (void)n_in; (void)out_size;
    const float* x       = (const float*)d_in[0];
    const float* ln_w    = (const float*)d_in[1];
    const float* ln_b    = (const float*)d_in[2];
    const float* W_in    = (const float*)d_in[3];
    const float* dt_bias = (const float*)d_in[4];
    const float* A_log   = (const float*)d_in[5];
    const float* Dv      = (const float*)d_in[6];
    const float* rms_w   = (const float*)d_in[7];
    const float* W_out   = (const float*)d_in[8];
    float* out = (float*)d_out;

    void *pzx, *pAhi, *pAlo, *pBhi, *pBlo;
    cudaGetSymbolAddress(&pzx,  g_zx);
    cudaGetSymbolAddress(&pAhi, g_Ahi);
    cudaGetSymbolAddress(&pAlo, g_Alo);
    cudaGetSymbolAddress(&pBhi, g_Bthi);
    cudaGetSymbolAddress(&pBlo, g_Btlo);

    static int attr_done = 0;
    if (!attr_done) {
        cudaFuncSetAttribute(mma_gemm, cudaFuncAttributeMaxDynamicSharedMemorySize, SMEM_GEMM);
        attr_done = 1;
    }

    ln_kernel<<<MROWS, 256>>>(x, ln_w, ln_b);
    cvtT_kernel<<<dim3(DIMX / 32, NPAD_IN / 32), dim3(32, 32)>>>(W_in, DIMX, DPROJ);
    mma_gemm<<<dim3(33, 128), 256, SMEM_GEMM>>>(
        (const unsigned short*)pAhi, (const unsigned short*)pAlo,
        (const unsigned short*)pBhi, (const unsigned short*)pBlo,
        (const float*)0, (float*)pzx, DPROJ, DIMX);
    bcrope_kernel<<<MROWS / 8, 256>>>();
    chunk_kernel<<<4 * NC * NH, 256>>>(dt_bias, A_log, Dv);
    scan_kernel<<<4 * NH * 8, 256>>>();
    yo_kernel<<<4 * NC * NH, 256>>>(dt_bias, A_log);
    gate_kernel<<<MROWS, 256>>>(rms_w);
    cvtT_kernel<<<dim3(DIN / 32, DIMX / 32), dim3(32, 32)>>>(W_out, DIN, DIMX);
    mma_gemm<<<dim3(8, 128), 256, SMEM_GEMM>>>(
        (const unsigned short*)pAhi, (const unsigned short*)pAlo,
        (const unsigned short*)pBhi, (const unsigned short*)pBlo,
        x, out, DIMX, DIN);
}

// round 6
// speedup vs baseline: 1.0891x; 1.0891x over previous
#include <cuda_runtime.h>
#include <cuda_bf16.h>
#include <math.h>
#include <stdint.h>

#define MROWS 16384
#define DIMX 1024
#define DPROJ 4192
#define DIN 2048
#define NH 32
#define HD 64
#define DS 32
#define LSEQ 4096
#define NC 64
#define NPAD_IN 4224

// ---------------- scratch ----------------
__device__ float g_zx[(size_t)MROWS * DPROJ];
__device__ float g_Brot[(size_t)MROWS * DS];
__device__ float g_Crot[(size_t)MROWS * DS];
__device__ float g_states[(size_t)4 * NC * NH * HD * DS];
__device__ float g_stin[(size_t)4 * NC * NH * HD * DS];
__device__ float g_csum[4 * NH * NC];
__device__ float g_y[(size_t)MROWS * DIN];
__device__ float g_scores[(size_t)4 * NC * 64 * 64];      // per (b,c): 64x64 masked C.B^T
__device__ float g_dtv[(size_t)4 * NH * LSEQ];
__device__ float g_acs[(size_t)4 * NH * LSEQ];
__device__ unsigned short g_Ahi[(size_t)MROWS * DIN];
__device__ unsigned short g_Alo[(size_t)MROWS * DIN];
__device__ unsigned short g_Bthi[(size_t)NPAD_IN * 1024];
__device__ unsigned short g_Btlo[(size_t)NPAD_IN * 1024];

__device__ __forceinline__ float siluf(float x) { return x / (1.f + __expf(-x)); }

__device__ __forceinline__ void splitbf(float f, unsigned short& hi, unsigned short& lo) {
    __nv_bfloat16 h = __float2bfloat16(f);
    float r = f - __bfloat162float(h);
    __nv_bfloat16 l = __float2bfloat16(r);
    hi = *reinterpret_cast<unsigned short*>(&h);
    lo = *reinterpret_cast<unsigned short*>(&l);
}

__device__ __forceinline__ uint32_t smem_u32(const void* p) {
    uint32_t a;
    asm("{ .reg .u64 t; cvta.to.shared.u64 t, %1; cvt.u32.u64 %0, t; }" : "=r"(a) : "l"(p));
    return a;
}
__device__ __forceinline__ void cpasync16(uint32_t dst, const void* src) {
    asm volatile("cp.async.cg.shared.global [%0], [%1], 16;" :: "r"(dst), "l"(src) : "memory");
}
__device__ __forceinline__ void mma16816(float* c, const uint32_t* a, const uint32_t* b) {
    asm volatile(
        "mma.sync.aligned.m16n8k16.row.col.f32.bf16.bf16.f32 "
        "{%0,%1,%2,%3}, {%4,%5,%6,%7}, {%8,%9}, {%0,%1,%2,%3};\n"
        : "+f"(c[0]), "+f"(c[1]), "+f"(c[2]), "+f"(c[3])
        : "r"(a[0]), "r"(a[1]), "r"(a[2]), "r"(a[3]), "r"(b[0]), "r"(b[1]));
}

// ---------------- LayerNorm ----------------
__global__ __launch_bounds__(256) void ln_kernel(const float* __restrict__ x,
                                                 const float* __restrict__ w,
                                                 const float* __restrict__ b)
{
    int row = blockIdx.x;
    int tid = threadIdx.x;
    const float* xr = x + (size_t)row * DIMX;
    float4 v = *(const float4*)(xr + tid * 4);
    float s  = v.x + v.y + v.z + v.w;
    float s2 = v.x*v.x + v.y*v.y + v.z*v.z + v.w*v.w;
    for (int o = 16; o; o >>= 1) {
        s  += __shfl_down_sync(0xffffffffu, s,  o);
        s2 += __shfl_down_sync(0xffffffffu, s2, o);
    }
    __shared__ float ss[8], ss2[8];
    if ((tid & 31) == 0) { ss[tid >> 5] = s; ss2[tid >> 5] = s2; }
    __syncthreads();
    if (tid == 0) {
        float t = 0.f, t2 = 0.f;
        for (int i = 0; i < 8; i++) { t += ss[i]; t2 += ss2[i]; }
        float mu = t / DIMX;
        ss[0]  = mu;
        ss2[0] = rsqrtf(t2 / DIMX - mu * mu + 1e-6f);
    }
    __syncthreads();
    float mu = ss[0], inv = ss2[0];
    int i0 = tid * 4;
    float4 wv = *(const float4*)(w + i0);
    float4 bv = *(const float4*)(b + i0);
    float o0 = (v.x - mu) * inv * wv.x + bv.x;
    float o1 = (v.y - mu) * inv * wv.y + bv.y;
    float o2 = (v.z - mu) * inv * wv.z + bv.z;
    float o3 = (v.w - mu) * inv * wv.w + bv.w;
    ushort4 hv, lv;
    splitbf(o0, hv.x, lv.x); splitbf(o1, hv.y, lv.y);
    splitbf(o2, hv.z, lv.z); splitbf(o3, hv.w, lv.w);
    *(ushort4*)(g_Ahi + (size_t)row * DIMX + i0) = hv;
    *(ushort4*)(g_Alo + (size_t)row * DIMX + i0) = lv;
}

// ---------------- W[K,N] -> Bt[n][k] bf16 hi/lo ----------------
__global__ __launch_bounds__(1024) void cvtT_kernel(const float* __restrict__ W, int K, int N)
{
    __shared__ float t[32][33];
    int k0 = blockIdx.x * 32, n0 = blockIdx.y * 32;
    int tx = threadIdx.x, ty = threadIdx.y;
    int n = n0 + tx;
    t[ty][tx] = (n < N) ? W[(size_t)(k0 + ty) * N + n] : 0.f;
    __syncthreads();
    float v = t[tx][ty];
    unsigned short hi, lo;
    splitbf(v, hi, lo);
    size_t o = (size_t)(n0 + ty) * K + k0 + tx;
    g_Bthi[o] = hi;
    g_Btlo[o] = lo;
}

// ---------------- mma.sync bf16 GEMM, hi/lo 3-pass ----------------
#define KSTAGE 40960
#define SMEM_GEMM (2 * KSTAGE)
__global__ __launch_bounds__(256, 1) void mma_gemm(
    const unsigned short* __restrict__ Ahi, const unsigned short* __restrict__ Alo,
    const unsigned short* __restrict__ Bhi, const unsigned short* __restrict__ Blo,
    const float* __restrict__ R, float* __restrict__ C, int N, int K)
{
    extern __shared__ char sm[];
    int tid = threadIdx.x, lane = tid & 31, wid = tid >> 5;
    int col0 = blockIdx.x * 128, row0 = blockIdx.y * 128;
    int g = lane >> 2, tig = lane & 3;
    int m0 = (wid >> 2) * 64, n0 = (wid & 3) * 32;
    uint32_t sb = smem_u32(sm);

    float acc[4][4][4];
#pragma unroll
    for (int i = 0; i < 4; i++)
#pragma unroll
        for (int j = 0; j < 4; j++)
#pragma unroll
            for (int q = 0; q < 4; q++) acc[i][j][q] = 0.f;

    const unsigned short* srcs[4] = {Ahi, Alo, Bhi, Blo};
    int rbs[4] = {row0, row0, col0, col0};

    int KT = K >> 5;
    {
#pragma unroll
        for (int t = 0; t < 4; t++) {
#pragma unroll
            for (int cc = 0; cc < 2; cc++) {
                int chunk = tid + cc * 256;
                int row = chunk >> 2, c4 = chunk & 3;
                const void* src = srcs[t] + (size_t)(rbs[t] + row) * K + c4 * 8;
                cpasync16(sb + t * 10240 + row * 80 + c4 * 16, src);
            }
        }
        asm volatile("cp.async.commit_group;" ::: "memory");
    }

    for (int kt = 0; kt < KT; kt++) {
        if (kt + 1 < KT) {
            int buf = (kt + 1) & 1;
#pragma unroll
            for (int t = 0; t < 4; t++) {
#pragma unroll
                for (int cc = 0; cc < 2; cc++) {
                    int chunk = tid + cc * 256;
                    int row = chunk >> 2, c4 = chunk & 3;
                    const void* src = srcs[t] + (size_t)(rbs[t] + row) * K + (kt + 1) * 32 + c4 * 8;
                    cpasync16(sb + buf * KSTAGE + t * 10240 + row * 80 + c4 * 16, src);
                }
            }
            asm volatile("cp.async.commit_group;" ::: "memory");
            asm volatile("cp.async.wait_group 1;" ::: "memory");
        } else {
            asm volatile("cp.async.wait_group 0;" ::: "memory");
        }
        __syncthreads();

        const char* stb = sm + (kt & 1) * KSTAGE;
#pragma unroll
        for (int ks = 0; ks < 2; ks++) {
            int wb = (ks * 8 + tig) * 4;
            uint32_t bh[4][2], bl[4][2];
#pragma unroll
            for (int nt = 0; nt < 4; nt++) {
                const char* pb = stb + 20480 + (n0 + nt * 8 + g) * 80 + wb;
                bh[nt][0] = *(const uint32_t*)(pb);
                bh[nt][1] = *(const uint32_t*)(pb + 16);
                bl[nt][0] = *(const uint32_t*)(pb + 10240);
                bl[nt][1] = *(const uint32_t*)(pb + 10240 + 16);
            }
#pragma unroll
            for (int mt = 0; mt < 4; mt++) {
                const char* pa = stb + (m0 + mt * 16 + g) * 80 + wb;
                uint32_t ah[4], al[4];
                ah[0] = *(const uint32_t*)(pa);
                ah[1] = *(const uint32_t*)(pa + 8 * 80);
                ah[2] = *(const uint32_t*)(pa + 16);
                ah[3] = *(const uint32_t*)(pa + 8 * 80 + 16);
                al[0] = *(const uint32_t*)(pa + 10240);
                al[1] = *(const uint32_t*)(pa + 10240 + 8 * 80);
                al[2] = *(const uint32_t*)(pa + 10240 + 16);
                al[3] = *(const uint32_t*)(pa + 10240 + 8 * 80 + 16);
#pragma unroll
                for (int nt = 0; nt < 4; nt++) {
                    mma16816(acc[mt][nt], ah, bh[nt]);
                    mma16816(acc[mt][nt], ah, bl[nt]);
                    mma16816(acc[mt][nt], al, bh[nt]);
                }
            }
        }
        __syncthreads();
    }

#pragma unroll
    for (int mt = 0; mt < 4; mt++) {
        int r0i = row0 + m0 + mt * 16 + g;
#pragma unroll
        for (int nt = 0; nt < 4; nt++) {
            int cc = col0 + n0 + nt * 8 + tig * 2;
            if (cc < N) {
                float* p0 = C + (size_t)r0i * N + cc;
                float* p1 = C + (size_t)(r0i + 8) * N + cc;
                float2 v0 = make_float2(acc[mt][nt][0], acc[mt][nt][1]);
                float2 v1 = make_float2(acc[mt][nt][2], acc[mt][nt][3]);
                if (R) {
                    const float* q0 = R + (size_t)r0i * N + cc;
                    const float* q1 = R + (size_t)(r0i + 8) * N + cc;
                    v0.x += q0[0]; v0.y += q0[1];
                    v1.x += q1[0]; v1.y += q1[1];
                }
                *(float2*)p0 = v0;
                *(float2*)p1 = v1;
            }
        }
    }
}

// ---------------- silu + RoPE ----------------
__global__ __launch_bounds__(256) void bcrope_kernel()
{
    int tid = threadIdx.x;
    int r8 = tid >> 5, n = tid & 31;
    int row = blockIdx.x * 8 + r8;
    int t = row & (LSEQ - 1);
    const float* base = g_zx + (size_t)row * DPROJ;
    float bo, co;
    if (n < 16) {
        int j = n >> 1;
        double invd = exp(-((double)j) * (log(10000.0) / 8.0));
        float inv = (float)invd;
        float ang = (float)t * inv;
        float sn, cs;
        sincosf(ang, &sn, &cs);
        float b1 = siluf(base[4096 + 2 * j]);
        float b2 = siluf(base[4096 + 2 * j + 1]);
        float c1 = siluf(base[4128 + 2 * j]);
        float c2 = siluf(base[4128 + 2 * j + 1]);
        if (n & 1) { bo = b1 * sn + b2 * cs; co = c1 * sn + c2 * cs; }
        else       { bo = b1 * cs - b2 * sn; co = c1 * cs - c2 * sn; }
    } else {
        bo = siluf(base[4096 + n]);
        co = siluf(base[4128 + n]);
    }
    g_Brot[(size_t)row * DS + n] = bo;
    g_Crot[(size_t)row * DS + n] = co;
}

// ---------------- dt + A-cumsum precompute: per (b,c), all heads ----------------
__global__ __launch_bounds__(256) void dtacs_kernel(const float* __restrict__ dt_bias,
                                                    const float* __restrict__ A_log)
{
    int bc = blockIdx.x;              // b*NC + c
    int b = bc >> 6, c = bc & 63;
    int warp = threadIdx.x >> 5, lane = threadIdx.x & 31;
    int rowbase = b * LSEQ + c * 64;
#pragma unroll
    for (int i = 0; i < 4; i++) {
        int h = warp * 4 + i;
        float A = -__expf(A_log[h]);
        float bias = dt_bias[h];
        float raw0 = g_zx[(size_t)(rowbase + lane) * DPROJ + 4160 + h] + bias;
        float raw1 = g_zx[(size_t)(rowbase + 32 + lane) * DPROJ + 4160 + h] + bias;
        float dt0 = (raw0 > 20.f) ? raw0 : log1pf(__expf(raw0));
        float dt1 = (raw1 > 20.f) ? raw1 : log1pf(__expf(raw1));
        float a0 = dt0 * A, a1 = dt1 * A;
#pragma unroll
        for (int o = 1; o < 32; o <<= 1) {
            float t = __shfl_up_sync(0xffffffffu, a0, o);
            if (lane >= o) a0 += t;
        }
#pragma unroll
        for (int o = 1; o < 32; o <<= 1) {
            float t = __shfl_up_sync(0xffffffffu, a1, o);
            if (lane >= o) a1 += t;
        }
        a1 += __shfl_sync(0xffffffffu, a0, 31);
        size_t base = ((size_t)(b * NH + h)) * LSEQ + c * 64;
        g_dtv[base + lane] = dt0;      g_dtv[base + 32 + lane] = dt1;
        g_acs[base + lane] = a0;       g_acs[base + 32 + lane] = a1;
    }
}

// ---------------- scores: per (b,c), masked C.B^T (head-independent) ----------------
__global__ __launch_bounds__(256) void score_kernel()
{
    int bc = blockIdx.x;              // b*NC + c
    int b = bc >> 6, c = bc & 63;
    __shared__ float Cs[64][33], Bsm[64][33];
    int tid = threadIdx.x;
    int rowbase = b * LSEQ + c * 64;
    for (int i = tid; i < 64 * 32; i += 256) {
        int l = i >> 5, n = i & 31;
        Bsm[l][n] = g_Brot[(size_t)(rowbase + l) * DS + n];
        Cs[l][n]  = g_Crot[(size_t)(rowbase + l) * DS + n];
    }
    __syncthreads();
    int l = tid >> 2, sq = tid & 3;
    float cr[32];
#pragma unroll
    for (int n = 0; n < 32; n++) cr[n] = Cs[l][n];
    float out[16];
#pragma unroll
    for (int k = 0; k < 16; k++) {
        int s = sq * 16 + k;
        float d = 0.f;
        if (s <= l) {
#pragma unroll
            for (int n = 0; n < 32; n++) d = fmaf(cr[n], Bsm[s][n], d);
        }
        out[k] = d;
    }
    float* dst = g_scores + (size_t)bc * 4096 + l * 64 + sq * 16;
#pragma unroll
    for (int k = 0; k < 16; k += 4)
        *(float4*)(dst + k) = make_float4(out[k], out[k + 1], out[k + 2], out[k + 3]);
}

// ---------------- SSD intra-chunk (scores + dt/acs precomputed) ----------------
__global__ __launch_bounds__(256) void chunk_kernel(const float* __restrict__ Dv)
{
    int blk = blockIdx.x;
    int h = blk & 31; int bcid = blk >> 5; int c = bcid & 63; int b = bcid >> 6;
    __shared__ float Psm[64][68], Bsm[64][33], xh[64][65], Pt[64][17];
    __shared__ float acs[64], dtv[64], wv[64];
    int tid = threadIdx.x;
    int rowbase = b * LSEQ + c * 64;

    if (tid < 64) {
        size_t dbase = ((size_t)(b * NH + h)) * LSEQ + c * 64;
        dtv[tid] = g_dtv[dbase + tid];
        acs[tid] = g_acs[dbase + tid];
    }
    {
        const float* psrc = g_scores + (size_t)(b * NC + c) * 4096;
        for (int i = tid; i < 64 * 16; i += 256) {
            int l = i >> 4, sq = i & 15;
            float4 v = *(const float4*)(psrc + l * 64 + sq * 4);
            *(float4*)&Psm[l][sq * 4] = v;
        }
    }
    for (int i = tid; i < 64 * 32; i += 256) {
        int l = i >> 5, n = i & 31;
        Bsm[l][n] = g_Brot[(size_t)(rowbase + l) * DS + n];
    }
    for (int i = tid; i < 64 * 64; i += 256) {
        int l = i >> 6, p = i & 63;
        float v = g_zx[(size_t)(rowbase + l) * DPROJ + 2048 + h * 64 + p];
        xh[l][p] = siluf(v);
    }
    __syncthreads();

    int l  = tid >> 2;
    int pb = (tid & 3) << 4;
    float acc[16];
#pragma unroll
    for (int j = 0; j < 16; j++) acc[j] = 0.f;

    for (int st = 0; st < 4; st++) {
#pragma unroll
        for (int i = 0; i < 4; i++) {
            int ss = ((tid & 3) << 2) + i;
            int s  = (st << 4) + ss;
            float v = 0.f;
            if (s <= l)
                v = Psm[l][s] * __expf(acs[l] - acs[s]) * dtv[s];
            Pt[l][ss] = v;
        }
        __syncthreads();
#pragma unroll
        for (int ss = 0; ss < 16; ss++) {
            float m = Pt[l][ss];
            int s = (st << 4) + ss;
#pragma unroll
            for (int j = 0; j < 16; j++) acc[j] = fmaf(m, xh[s][pb + j], acc[j]);
        }
        __syncthreads();
    }

    float Dh = Dv[h];
    float* yrow = g_y + (size_t)(rowbase + l) * DIN + h * HD + pb;
#pragma unroll
    for (int j = 0; j < 16; j++) yrow[j] = acc[j] + Dh * xh[l][pb + j];

    if (tid < 64) wv[tid] = dtv[tid] * __expf(acs[63] - acs[tid]);
    __syncthreads();
    for (int i = tid; i < 64 * 32; i += 256) { int ll = i >> 5, n = i & 31; Bsm[ll][n] *= wv[ll]; }
    __syncthreads();
    int p  = tid >> 2;
    int nb = (tid & 3) << 3;
    float st8[8];
#pragma unroll
    for (int j = 0; j < 8; j++) st8[j] = 0.f;
    for (int l2 = 0; l2 < 64; l2++) {
        float xv = xh[l2][p];
#pragma unroll
        for (int j = 0; j < 8; j++) st8[j] = fmaf(xv, Bsm[l2][nb + j], st8[j]);
    }
    size_t sbase = ((size_t)((b * NC + c) * NH + h)) * (HD * DS);
#pragma unroll
    for (int j = 0; j < 8; j++) g_states[sbase + p * DS + nb + j] = st8[j];
    if (tid == 0) g_csum[(b * NH + h) * NC + c] = acs[63];
}

// ---------------- inter-chunk scan (R4 version) ----------------
__global__ __launch_bounds__(256) void scan_kernel()
{
    int bh = blockIdx.x;
    int b = bh >> 5, h = bh & 31;
    int tid = threadIdx.x;
    float S[8];
#pragma unroll
    for (int j = 0; j < 8; j++) S[j] = 0.f;
    for (int c = 0; c < NC; c++) {
        size_t base = ((size_t)((b * NC + c) * NH + h)) * (HD * DS);
#pragma unroll
        for (int j = 0; j < 8; j++) g_stin[base + tid + j * 256] = S[j];
        float e = __expf(g_csum[bh * NC + c]);
#pragma unroll
        for (int j = 0; j < 8; j++) S[j] = S[j] * e + g_states[base + tid + j * 256];
    }
}

// ---------------- Yo (acs precomputed) ----------------
__global__ __launch_bounds__(256) void yo_kernel()
{
    int blk = blockIdx.x;
    int h = blk & 31; int bcid = blk >> 5; int c = bcid & 63; int b = bcid >> 6;
    __shared__ float Cs[64][33], Sm[64][33];
    __shared__ float acs[64];
    int tid = threadIdx.x;
    int rowbase = b * LSEQ + c * 64;

    if (tid < 64) {
        size_t dbase = ((size_t)(b * NH + h)) * LSEQ + c * 64;
        acs[tid] = g_acs[dbase + tid];
    }
    size_t sbase = ((size_t)((b * NC + c) * NH + h)) * (HD * DS);
    for (int i = tid; i < 64 * 32; i += 256) {
        int l = i >> 5, n = i & 31;
        Cs[l][n] = g_Crot[(size_t)(rowbase + l) * DS + n];
        Sm[l][n] = g_stin[sbase + i];
    }
    __syncthreads();

    int l  = tid >> 2;
    int pb = (tid & 3) << 4;
    float el = __expf(acs[l]);
    float* yrow = g_y + (size_t)(rowbase + l) * DIN + h * HD;
#pragma unroll
    for (int j = 0; j < 16; j++) {
        int p = pb + j;
        float d = 0.f;
#pragma unroll
        for (int n = 0; n < 32; n++) d = fmaf(Cs[l][n], Sm[p][n], d);
        yrow[p] += el * d;
    }
}

// ---------------- gate + RMSNorm ----------------
__global__ __launch_bounds__(256) void gate_kernel(const float* __restrict__ rms_w)
{
    int row = blockIdx.x;
    int tid = threadIdx.x;
    const float* yr = g_y + (size_t)row * DIN;
    const float* zr = g_zx + (size_t)row * DPROJ;
    float v[8]; float s2 = 0.f;
#pragma unroll
    for (int i = 0; i < 8; i++) {
        int idx = tid + i * 256;
        float y = yr[idx];
        float z = zr[idx];
        y *= siluf(z);
        v[i] = y;
        s2 = fmaf(y, y, s2);
    }
    for (int o = 16; o; o >>= 1) s2 += __shfl_down_sync(0xffffffffu, s2, o);
    __shared__ float red[8];
    if ((tid & 31) == 0) red[tid >> 5] = s2;
    __syncthreads();
    if (tid == 0) {
        float t = 0.f;
        for (int i = 0; i < 8; i++) t += red[i];
        red[0] = rsqrtf(t / DIN + 1e-6f);
    }
    __syncthreads();
    float sc = red[0];
    size_t base = (size_t)row * DIN;
#pragma unroll
    for (int i = 0; i < 8; i++) {
        int idx = tid + i * 256;
        float f = v[i] * sc * rms_w[idx];
        unsigned short hi, lo;
        splitbf(f, hi, lo);
        g_Ahi[base + idx] = hi;
        g_Alo[base + idx] = lo;
    }
}

// ---------------- launch ----------------
extern "C" void kernel_launch(void* const* d_in, const int* in_sizes, int n_in,
                              void* d_out, int out_size)
{
    (void)in_sizes; (void)n_in; (void)out_size;
    const float* x       = (const float*)d_in[0];
    const float* ln_w    = (const float*)d_in[1];
    const float* ln_b    = (const float*)d_in[2];
    const float* W_in    = (const float*)d_in[3];
    const float* dt_bias = (const float*)d_in[4];
    const float* A_log   = (const float*)d_in[5];
    const float* Dv      = (const float*)d_in[6];
    const float* rms_w   = (const float*)d_in[7];
    const float* W_out   = (const float*)d_in[8];
    float* out = (float*)d_out;

    void *pzx, *pAhi, *pAlo, *pBhi, *pBlo;
    cudaGetSymbolAddress(&pzx,  g_zx);
    cudaGetSymbolAddress(&pAhi, g_Ahi);
    cudaGetSymbolAddress(&pAlo, g_Alo);
    cudaGetSymbolAddress(&pBhi, g_Bthi);
    cudaGetSymbolAddress(&pBlo, g_Btlo);

    static int attr_done = 0;
    if (!attr_done) {
        cudaFuncSetAttribute(mma_gemm, cudaFuncAttributeMaxDynamicSharedMemorySize, SMEM_GEMM);
        attr_done = 1;
    }

    ln_kernel<<<MROWS, 256>>>(x, ln_w, ln_b);
    cvtT_kernel<<<dim3(DIMX / 32, NPAD_IN / 32), dim3(32, 32)>>>(W_in, DIMX, DPROJ);
    mma_gemm<<<dim3(33, 128), 256, SMEM_GEMM>>>(
        (const unsigned short*)pAhi, (const unsigned short*)pAlo,
        (const unsigned short*)pBhi, (const unsigned short*)pBlo,
        (const float*)0, (float*)pzx, DPROJ, DIMX);
    bcrope_kernel<<<MROWS / 8, 256>>>();
    dtacs_kernel<<<4 * NC, 256>>>(dt_bias, A_log);
    score_kernel<<<4 * NC, 256>>>();
    chunk_kernel<<<4 * NC * NH, 256>>>(Dv);
    scan_kernel<<<4 * NH, 256>>>();
    yo_kernel<<<4 * NC * NH, 256>>>();
    gate_kernel<<<MROWS, 256>>>(rms_w);
    cvtT_kernel<<<dim3(DIN / 32, DIMX / 32), dim3(32, 32)>>>(W_out, DIN, DIMX);
    mma_gemm<<<dim3(8, 128), 256, SMEM_GEMM>>>(
        (const unsigned short*)pAhi, (const unsigned short*)pAlo,
        (const unsigned short*)pBhi, (const unsigned short*)pBlo,
        x, out, DIMX, DIN);
}

// round 7
// speedup vs baseline: 1.3954x; 1.2812x over previous
#include <cuda_runtime.h>
#include <cuda_bf16.h>
#include <math.h>
#include <stdint.h>

#define MROWS 16384
#define DIMX 1024
#define DPROJ 4192
#define DIN 2048
#define NH 32
#define HD 64
#define DS 32
#define LSEQ 4096
#define NC 64
#define NPAD_IN 4224

// ---------------- scratch ----------------
__device__ float g_zx[(size_t)MROWS * DPROJ];
__device__ float g_Brot[(size_t)MROWS * DS];
__device__ float g_Crot[(size_t)MROWS * DS];
__device__ float g_states[(size_t)4 * NC * NH * HD * DS];
__device__ float g_stin[(size_t)4 * NC * NH * HD * DS];
__device__ float g_csum[4 * NH * NC];
__device__ float g_y[(size_t)MROWS * DIN];
__device__ float g_scores[(size_t)4 * NC * 64 * 64];
__device__ float g_dtv[(size_t)4 * NH * LSEQ];
__device__ float g_acs[(size_t)4 * NH * LSEQ];
__device__ unsigned short g_Ahi[(size_t)MROWS * DIN];
__device__ unsigned short g_Alo[(size_t)MROWS * DIN];
__device__ unsigned short g_Bthi[(size_t)NPAD_IN * 1024];
__device__ unsigned short g_Btlo[(size_t)NPAD_IN * 1024];

__device__ __forceinline__ float siluf(float x) { return x / (1.f + __expf(-x)); }

__device__ __forceinline__ void splitbf(float f, unsigned short& hi, unsigned short& lo) {
    __nv_bfloat16 h = __float2bfloat16(f);
    float r = f - __bfloat162float(h);
    __nv_bfloat16 l = __float2bfloat16(r);
    hi = *reinterpret_cast<unsigned short*>(&h);
    lo = *reinterpret_cast<unsigned short*>(&l);
}
__device__ __forceinline__ float bf2f(unsigned short u) {
    __nv_bfloat16 h = *reinterpret_cast<__nv_bfloat16*>(&u);
    return __bfloat162float(h);
}

__device__ __forceinline__ uint32_t smem_u32(const void* p) {
    uint32_t a;
    asm("{ .reg .u64 t; cvta.to.shared.u64 t, %1; cvt.u32.u64 %0, t; }" : "=r"(a) : "l"(p));
    return a;
}
__device__ __forceinline__ void cpasync16(uint32_t dst, const void* src) {
    asm volatile("cp.async.cg.shared.global [%0], [%1], 16;" :: "r"(dst), "l"(src) : "memory");
}
__device__ __forceinline__ void mma16816(float* c, const uint32_t* a, const uint32_t* b) {
    asm volatile(
        "mma.sync.aligned.m16n8k16.row.col.f32.bf16.bf16.f32 "
        "{%0,%1,%2,%3}, {%4,%5,%6,%7}, {%8,%9}, {%0,%1,%2,%3};\n"
        : "+f"(c[0]), "+f"(c[1]), "+f"(c[2]), "+f"(c[3])
        : "r"(a[0]), "r"(a[1]), "r"(a[2]), "r"(a[3]), "r"(b[0]), "r"(b[1]));
}
// A fragment (16x16) from pitch-P ushort smem array
template<int P>
__device__ __forceinline__ void ldfragA(uint32_t* a, const unsigned short (*S)[P], int row, int col) {
    a[0] = *(const uint32_t*)&S[row][col];
    a[1] = *(const uint32_t*)&S[row + 8][col];
    a[2] = *(const uint32_t*)&S[row][col + 8];
    a[3] = *(const uint32_t*)&S[row + 8][col + 8];
}
template<int P>
__device__ __forceinline__ void ldfragB(uint32_t* bb, const unsigned short (*S)[P], int row, int col) {
    bb[0] = *(const uint32_t*)&S[row][col];
    bb[1] = *(const uint32_t*)&S[row][col + 8];
}

// ---------------- LayerNorm ----------------
__global__ __launch_bounds__(256) void ln_kernel(const float* __restrict__ x,
                                                 const float* __restrict__ w,
                                                 const float* __restrict__ b)
{
    int row = blockIdx.x;
    int tid = threadIdx.x;
    const float* xr = x + (size_t)row * DIMX;
    float4 v = *(const float4*)(xr + tid * 4);
    float s  = v.x + v.y + v.z + v.w;
    float s2 = v.x*v.x + v.y*v.y + v.z*v.z + v.w*v.w;
    for (int o = 16; o; o >>= 1) {
        s  += __shfl_down_sync(0xffffffffu, s,  o);
        s2 += __shfl_down_sync(0xffffffffu, s2, o);
    }
    __shared__ float ss[8], ss2[8];
    if ((tid & 31) == 0) { ss[tid >> 5] = s; ss2[tid >> 5] = s2; }
    __syncthreads();
    if (tid == 0) {
        float t = 0.f, t2 = 0.f;
        for (int i = 0; i < 8; i++) { t += ss[i]; t2 += ss2[i]; }
        float mu = t / DIMX;
        ss[0]  = mu;
        ss2[0] = rsqrtf(t2 / DIMX - mu * mu + 1e-6f);
    }
    __syncthreads();
    float mu = ss[0], inv = ss2[0];
    int i0 = tid * 4;
    float4 wv = *(const float4*)(w + i0);
    float4 bv = *(const float4*)(b + i0);
    float o0 = (v.x - mu) * inv * wv.x + bv.x;
    float o1 = (v.y - mu) * inv * wv.y + bv.y;
    float o2 = (v.z - mu) * inv * wv.z + bv.z;
    float o3 = (v.w - mu) * inv * wv.w + bv.w;
    ushort4 hv, lv;
    splitbf(o0, hv.x, lv.x); splitbf(o1, hv.y, lv.y);
    splitbf(o2, hv.z, lv.z); splitbf(o3, hv.w, lv.w);
    *(ushort4*)(g_Ahi + (size_t)row * DIMX + i0) = hv;
    *(ushort4*)(g_Alo + (size_t)row * DIMX + i0) = lv;
}

// ---------------- W[K,N] -> Bt[n][k] bf16 hi/lo ----------------
__global__ __launch_bounds__(1024) void cvtT_kernel(const float* __restrict__ W, int K, int N)
{
    __shared__ float t[32][33];
    int k0 = blockIdx.x * 32, n0 = blockIdx.y * 32;
    int tx = threadIdx.x, ty = threadIdx.y;
    int n = n0 + tx;
    t[ty][tx] = (n < N) ? W[(size_t)(k0 + ty) * N + n] : 0.f;
    __syncthreads();
    float v = t[tx][ty];
    unsigned short hi, lo;
    splitbf(v, hi, lo);
    size_t o = (size_t)(n0 + ty) * K + k0 + tx;
    g_Bthi[o] = hi;
    g_Btlo[o] = lo;
}

// ---------------- mma.sync bf16 GEMM, hi/lo 3-pass ----------------
#define KSTAGE 40960
#define SMEM_GEMM (2 * KSTAGE)
__global__ __launch_bounds__(256, 1) void mma_gemm(
    const unsigned short* __restrict__ Ahi, const unsigned short* __restrict__ Alo,
    const unsigned short* __restrict__ Bhi, const unsigned short* __restrict__ Blo,
    const float* __restrict__ R, float* __restrict__ C, int N, int K)
{
    extern __shared__ char sm[];
    int tid = threadIdx.x, lane = tid & 31, wid = tid >> 5;
    int col0 = blockIdx.x * 128, row0 = blockIdx.y * 128;
    int g = lane >> 2, tig = lane & 3;
    int m0 = (wid >> 2) * 64, n0 = (wid & 3) * 32;
    uint32_t sb = smem_u32(sm);

    float acc[4][4][4];
#pragma unroll
    for (int i = 0; i < 4; i++)
#pragma unroll
        for (int j = 0; j < 4; j++)
#pragma unroll
            for (int q = 0; q < 4; q++) acc[i][j][q] = 0.f;

    const unsigned short* srcs[4] = {Ahi, Alo, Bhi, Blo};
    int rbs[4] = {row0, row0, col0, col0};

    int KT = K >> 5;
    {
#pragma unroll
        for (int t = 0; t < 4; t++) {
#pragma unroll
            for (int cc = 0; cc < 2; cc++) {
                int chunk = tid + cc * 256;
                int row = chunk >> 2, c4 = chunk & 3;
                const void* src = srcs[t] + (size_t)(rbs[t] + row) * K + c4 * 8;
                cpasync16(sb + t * 10240 + row * 80 + c4 * 16, src);
            }
        }
        asm volatile("cp.async.commit_group;" ::: "memory");
    }

    for (int kt = 0; kt < KT; kt++) {
        if (kt + 1 < KT) {
            int buf = (kt + 1) & 1;
#pragma unroll
            for (int t = 0; t < 4; t++) {
#pragma unroll
                for (int cc = 0; cc < 2; cc++) {
                    int chunk = tid + cc * 256;
                    int row = chunk >> 2, c4 = chunk & 3;
                    const void* src = srcs[t] + (size_t)(rbs[t] + row) * K + (kt + 1) * 32 + c4 * 8;
                    cpasync16(sb + buf * KSTAGE + t * 10240 + row * 80 + c4 * 16, src);
                }
            }
            asm volatile("cp.async.commit_group;" ::: "memory");
            asm volatile("cp.async.wait_group 1;" ::: "memory");
        } else {
            asm volatile("cp.async.wait_group 0;" ::: "memory");
        }
        __syncthreads();

        const char* stb = sm + (kt & 1) * KSTAGE;
#pragma unroll
        for (int ks = 0; ks < 2; ks++) {
            int wb = (ks * 8 + tig) * 4;
            uint32_t bh[4][2], bl[4][2];
#pragma unroll
            for (int nt = 0; nt < 4; nt++) {
                const char* pb = stb + 20480 + (n0 + nt * 8 + g) * 80 + wb;
                bh[nt][0] = *(const uint32_t*)(pb);
                bh[nt][1] = *(const uint32_t*)(pb + 16);
                bl[nt][0] = *(const uint32_t*)(pb + 10240);
                bl[nt][1] = *(const uint32_t*)(pb + 10240 + 16);
            }
#pragma unroll
            for (int mt = 0; mt < 4; mt++) {
                const char* pa = stb + (m0 + mt * 16 + g) * 80 + wb;
                uint32_t ah[4], al[4];
                ah[0] = *(const uint32_t*)(pa);
                ah[1] = *(const uint32_t*)(pa + 8 * 80);
                ah[2] = *(const uint32_t*)(pa + 16);
                ah[3] = *(const uint32_t*)(pa + 8 * 80 + 16);
                al[0] = *(const uint32_t*)(pa + 10240);
                al[1] = *(const uint32_t*)(pa + 10240 + 8 * 80);
                al[2] = *(const uint32_t*)(pa + 10240 + 16);
                al[3] = *(const uint32_t*)(pa + 10240 + 8 * 80 + 16);
#pragma unroll
                for (int nt = 0; nt < 4; nt++) {
                    mma16816(acc[mt][nt], ah, bh[nt]);
                    mma16816(acc[mt][nt], ah, bl[nt]);
                    mma16816(acc[mt][nt], al, bh[nt]);
                }
            }
        }
        __syncthreads();
    }

#pragma unroll
    for (int mt = 0; mt < 4; mt++) {
        int r0i = row0 + m0 + mt * 16 + g;
#pragma unroll
        for (int nt = 0; nt < 4; nt++) {
            int cc = col0 + n0 + nt * 8 + tig * 2;
            if (cc < N) {
                float* p0 = C + (size_t)r0i * N + cc;
                float* p1 = C + (size_t)(r0i + 8) * N + cc;
                float2 v0 = make_float2(acc[mt][nt][0], acc[mt][nt][1]);
                float2 v1 = make_float2(acc[mt][nt][2], acc[mt][nt][3]);
                if (R) {
                    const float* q0 = R + (size_t)r0i * N + cc;
                    const float* q1 = R + (size_t)(r0i + 8) * N + cc;
                    v0.x += q0[0]; v0.y += q0[1];
                    v1.x += q1[0]; v1.y += q1[1];
                }
                *(float2*)p0 = v0;
                *(float2*)p1 = v1;
            }
        }
    }
}

// ---------------- silu + RoPE ----------------
__global__ __launch_bounds__(256) void bcrope_kernel()
{
    int tid = threadIdx.x;
    int r8 = tid >> 5, n = tid & 31;
    int row = blockIdx.x * 8 + r8;
    int t = row & (LSEQ - 1);
    const float* base = g_zx + (size_t)row * DPROJ;
    float bo, co;
    if (n < 16) {
        int j = n >> 1;
        double invd = exp(-((double)j) * (log(10000.0) / 8.0));
        float inv = (float)invd;
        float ang = (float)t * inv;
        float sn, cs;
        sincosf(ang, &sn, &cs);
        float b1 = siluf(base[4096 + 2 * j]);
        float b2 = siluf(base[4096 + 2 * j + 1]);
        float c1 = siluf(base[4128 + 2 * j]);
        float c2 = siluf(base[4128 + 2 * j + 1]);
        if (n & 1) { bo = b1 * sn + b2 * cs; co = c1 * sn + c2 * cs; }
        else       { bo = b1 * cs - b2 * sn; co = c1 * cs - c2 * sn; }
    } else {
        bo = siluf(base[4096 + n]);
        co = siluf(base[4128 + n]);
    }
    g_Brot[(size_t)row * DS + n] = bo;
    g_Crot[(size_t)row * DS + n] = co;
}

// ---------------- dt + A-cumsum precompute ----------------
__global__ __launch_bounds__(256) void dtacs_kernel(const float* __restrict__ dt_bias,
                                                    const float* __restrict__ A_log)
{
    int bc = blockIdx.x;
    int b = bc >> 6, c = bc & 63;
    int warp = threadIdx.x >> 5, lane = threadIdx.x & 31;
    int rowbase = b * LSEQ + c * 64;
#pragma unroll
    for (int i = 0; i < 4; i++) {
        int h = warp * 4 + i;
        float A = -__expf(A_log[h]);
        float bias = dt_bias[h];
        float raw0 = g_zx[(size_t)(rowbase + lane) * DPROJ + 4160 + h] + bias;
        float raw1 = g_zx[(size_t)(rowbase + 32 + lane) * DPROJ + 4160 + h] + bias;
        float dt0 = (raw0 > 20.f) ? raw0 : log1pf(__expf(raw0));
        float dt1 = (raw1 > 20.f) ? raw1 : log1pf(__expf(raw1));
        float a0 = dt0 * A, a1 = dt1 * A;
#pragma unroll
        for (int o = 1; o < 32; o <<= 1) {
            float t = __shfl_up_sync(0xffffffffu, a0, o);
            if (lane >= o) a0 += t;
        }
#pragma unroll
        for (int o = 1; o < 32; o <<= 1) {
            float t = __shfl_up_sync(0xffffffffu, a1, o);
            if (lane >= o) a1 += t;
        }
        a1 += __shfl_sync(0xffffffffu, a0, 31);
        size_t base = ((size_t)(b * NH + h)) * LSEQ + c * 64;
        g_dtv[base + lane] = dt0;      g_dtv[base + 32 + lane] = dt1;
        g_acs[base + lane] = a0;       g_acs[base + 32 + lane] = a1;
    }
}

// ---------------- scores: per (b,c), masked C.B^T ----------------
__global__ __launch_bounds__(256) void score_kernel()
{
    int bc = blockIdx.x;
    int b = bc >> 6, c = bc & 63;
    __shared__ float Cs[64][33], Bsm[64][33];
    int tid = threadIdx.x;
    int rowbase = b * LSEQ + c * 64;
    for (int i = tid; i < 64 * 32; i += 256) {
        int l = i >> 5, n = i & 31;
        Bsm[l][n] = g_Brot[(size_t)(rowbase + l) * DS + n];
        Cs[l][n]  = g_Crot[(size_t)(rowbase + l) * DS + n];
    }
    __syncthreads();
    int l = tid >> 2, sq = tid & 3;
    float cr[32];
#pragma unroll
    for (int n = 0; n < 32; n++) cr[n] = Cs[l][n];
    float out[16];
#pragma unroll
    for (int k = 0; k < 16; k++) {
        int s = sq * 16 + k;
        float d = 0.f;
        if (s <= l) {
#pragma unroll
            for (int n = 0; n < 32; n++) d = fmaf(cr[n], Bsm[s][n], d);
        }
        out[k] = d;
    }
    float* dst = g_scores + (size_t)bc * 4096 + l * 64 + sq * 16;
#pragma unroll
    for (int k = 0; k < 16; k += 4)
        *(float4*)(dst + k) = make_float4(out[k], out[k + 1], out[k + 2], out[k + 3]);
}

// ---------------- SSD intra-chunk: tensor-core Yd + states ----------------
__global__ __launch_bounds__(256) void chunk_kernel(const float* __restrict__ Dv)
{
    int blk = blockIdx.x;
    int h = blk & 31; int bcid = blk >> 5; int c = bcid & 63; int b = bcid >> 6;
    __shared__ unsigned short Mhi[64][72], Mlo[64][72];
    __shared__ unsigned short XThi[64][72], XTlo[64][72];   // [p][l]
    __shared__ unsigned short BwThi[32][72], BwTlo[32][72]; // [n][l]
    __shared__ float acs[64], dtv[64], wvv[64];
    int tid = threadIdx.x;
    int rowbase = b * LSEQ + c * 64;

    if (tid < 64) {
        size_t dbase = ((size_t)(b * NH + h)) * LSEQ + c * 64;
        dtv[tid] = g_dtv[dbase + tid];
        acs[tid] = g_acs[dbase + tid];
    }
    __syncthreads();
    if (tid < 64) wvv[tid] = dtv[tid] * __expf(acs[63] - acs[tid]);
    for (int i = tid; i < 4096; i += 256) {
        int l = i >> 6, p = i & 63;
        float v = siluf(g_zx[(size_t)(rowbase + l) * DPROJ + 2048 + h * 64 + p]);
        unsigned short hi, lo; splitbf(v, hi, lo);
        XThi[p][l] = hi; XTlo[p][l] = lo;
    }
    const float* psrc = g_scores + (size_t)(b * NC + c) * 4096;
    for (int i = tid; i < 4096; i += 256) {
        int l = i >> 6, s = i & 63;
        float m = 0.f;
        if (s <= l) m = psrc[i] * __expf(acs[l] - acs[s]) * dtv[s];
        unsigned short hi, lo; splitbf(m, hi, lo);
        Mhi[l][s] = hi; Mlo[l][s] = lo;
    }
    __syncthreads();   // wvv ready
    for (int i = tid; i < 2048; i += 256) {
        int l = i >> 5, n = i & 31;
        float v = g_Brot[(size_t)(rowbase + l) * DS + n] * wvv[l];
        unsigned short hi, lo; splitbf(v, hi, lo);
        BwThi[n][l] = hi; BwTlo[n][l] = lo;
    }
    __syncthreads();

    int lane = tid & 31, w = tid >> 5;
    int g = lane >> 2, tig = lane & 3;

    // ---- Yd = M @ X (64x64x64), 3-pass ----
    {
        int m0 = (w & 3) * 16, n0 = (w >> 2) * 32;
        float acc[4][4];
#pragma unroll
        for (int i = 0; i < 4; i++)
#pragma unroll
            for (int q = 0; q < 4; q++) acc[i][q] = 0.f;
#pragma unroll
        for (int kt = 0; kt < 4; kt++) {
            int col = kt * 16 + 2 * tig;
            uint32_t ah[4], al[4];
            ldfragA<72>(ah, Mhi, m0 + g, col);
            ldfragA<72>(al, Mlo, m0 + g, col);
#pragma unroll
            for (int nt = 0; nt < 4; nt++) {
                uint32_t bh[2], bl[2];
                ldfragB<72>(bh, XThi, n0 + nt * 8 + g, col);
                ldfragB<72>(bl, XTlo, n0 + nt * 8 + g, col);
                mma16816(acc[nt], ah, bh);
                mma16816(acc[nt], ah, bl);
                mma16816(acc[nt], al, bh);
            }
        }
        float Dh = Dv[h];
#pragma unroll
        for (int nt = 0; nt < 4; nt++) {
            int p0 = n0 + nt * 8 + 2 * tig;
            int l0 = m0 + g, l1 = l0 + 8;
            float x00 = bf2f(XThi[p0][l0]) + bf2f(XTlo[p0][l0]);
            float x01 = bf2f(XThi[p0 + 1][l0]) + bf2f(XTlo[p0 + 1][l0]);
            float x10 = bf2f(XThi[p0][l1]) + bf2f(XTlo[p0][l1]);
            float x11 = bf2f(XThi[p0 + 1][l1]) + bf2f(XTlo[p0 + 1][l1]);
            float* y0 = g_y + (size_t)(rowbase + l0) * DIN + h * HD + p0;
            float* y1 = g_y + (size_t)(rowbase + l1) * DIN + h * HD + p0;
            y0[0] = acc[nt][0] + Dh * x00;
            y0[1] = acc[nt][1] + Dh * x01;
            y1[0] = acc[nt][2] + Dh * x10;
            y1[1] = acc[nt][3] + Dh * x11;
        }
    }

    // ---- states = X^T @ Bw (64x32x64), 3-pass ----
    {
        int m0 = (w & 3) * 16;       // p
        int n0 = (w >> 2) * 16;      // n
        float acc[2][4];
#pragma unroll
        for (int i = 0; i < 2; i++)
#pragma unroll
            for (int q = 0; q < 4; q++) acc[i][q] = 0.f;
#pragma unroll
        for (int kt = 0; kt < 4; kt++) {
            int col = kt * 16 + 2 * tig;
            uint32_t ah[4], al[4];
            ldfragA<72>(ah, XThi, m0 + g, col);
            ldfragA<72>(al, XTlo, m0 + g, col);
#pragma unroll
            for (int nt = 0; nt < 2; nt++) {
                uint32_t bh[2], bl[2];
                ldfragB<72>(bh, BwThi, n0 + nt * 8 + g, col);
                ldfragB<72>(bl, BwTlo, n0 + nt * 8 + g, col);
                mma16816(acc[nt], ah, bh);
                mma16816(acc[nt], ah, bl);
                mma16816(acc[nt], al, bh);
            }
        }
        size_t sbase = ((size_t)((b * NC + c) * NH + h)) * (HD * DS);
#pragma unroll
        for (int nt = 0; nt < 2; nt++) {
            int nn = n0 + nt * 8 + 2 * tig;
            int p0 = m0 + g, p1 = p0 + 8;
            g_states[sbase + p0 * DS + nn]     = acc[nt][0];
            g_states[sbase + p0 * DS + nn + 1] = acc[nt][1];
            g_states[sbase + p1 * DS + nn]     = acc[nt][2];
            g_states[sbase + p1 * DS + nn + 1] = acc[nt][3];
        }
    }
    if (tid == 0) g_csum[(b * NH + h) * NC + c] = acs[63];
}

// ---------------- inter-chunk scan ----------------
__global__ __launch_bounds__(256) void scan_kernel()
{
    int bh = blockIdx.x;
    int b = bh >> 5, h = bh & 31;
    int tid = threadIdx.x;
    float S[8];
#pragma unroll
    for (int j = 0; j < 8; j++) S[j] = 0.f;
    for (int c = 0; c < NC; c++) {
        size_t base = ((size_t)((b * NC + c) * NH + h)) * (HD * DS);
#pragma unroll
        for (int j = 0; j < 8; j++) g_stin[base + tid + j * 256] = S[j];
        float e = __expf(g_csum[bh * NC + c]);
#pragma unroll
        for (int j = 0; j < 8; j++) S[j] = S[j] * e + g_states[base + tid + j * 256];
    }
}

// ---------------- Yo = C @ S^T (64x64x32), 3-pass, y += exp(acs)*Yo ----------------
__global__ __launch_bounds__(256) void yo_kernel()
{
    int blk = blockIdx.x;
    int h = blk & 31; int bcid = blk >> 5; int c = bcid & 63; int b = bcid >> 6;
    __shared__ unsigned short Chi[64][40], Clo[64][40];   // [l][n]
    __shared__ unsigned short Shi[64][40], Slo[64][40];   // [p][n]
    __shared__ float acs[64];
    int tid = threadIdx.x;
    int rowbase = b * LSEQ + c * 64;

    if (tid < 64) {
        size_t dbase = ((size_t)(b * NH + h)) * LSEQ + c * 64;
        acs[tid] = g_acs[dbase + tid];
    }
    size_t sbase = ((size_t)((b * NC + c) * NH + h)) * (HD * DS);
    for (int i = tid; i < 2048; i += 256) {
        int l = i >> 5, n = i & 31;
        unsigned short hi, lo;
        splitbf(g_Crot[(size_t)(rowbase + l) * DS + n], hi, lo);
        Chi[l][n] = hi; Clo[l][n] = lo;
        splitbf(g_stin[sbase + i], hi, lo);
        Shi[l][n] = hi; Slo[l][n] = lo;
    }
    __syncthreads();

    int lane = tid & 31, w = tid >> 5;
    int g = lane >> 2, tig = lane & 3;
    int m0 = (w & 3) * 16, n0 = (w >> 2) * 32;
    float acc[4][4];
#pragma unroll
    for (int i = 0; i < 4; i++)
#pragma unroll
        for (int q = 0; q < 4; q++) acc[i][q] = 0.f;
#pragma unroll
    for (int kt = 0; kt < 2; kt++) {
        int col = kt * 16 + 2 * tig;
        uint32_t ah[4], al[4];
        ldfragA<40>(ah, Chi, m0 + g, col);
        ldfragA<40>(al, Clo, m0 + g, col);
#pragma unroll
        for (int nt = 0; nt < 4; nt++) {
            uint32_t bh[2], bl[2];
            ldfragB<40>(bh, Shi, n0 + nt * 8 + g, col);
            ldfragB<40>(bl, Slo, n0 + nt * 8 + g, col);
            mma16816(acc[nt], ah, bh);
            mma16816(acc[nt], ah, bl);
            mma16816(acc[nt], al, bh);
        }
    }
    int l0 = m0 + g, l1 = l0 + 8;
    float el0 = __expf(acs[l0]), el1 = __expf(acs[l1]);
#pragma unroll
    for (int nt = 0; nt < 4; nt++) {
        int p0 = n0 + nt * 8 + 2 * tig;
        float* y0 = g_y + (size_t)(rowbase + l0) * DIN + h * HD + p0;
        float* y1 = g_y + (size_t)(rowbase + l1) * DIN + h * HD + p0;
        y0[0] += el0 * acc[nt][0];
        y0[1] += el0 * acc[nt][1];
        y1[0] += el1 * acc[nt][2];
        y1[1] += el1 * acc[nt][3];
    }
}

// ---------------- gate + RMSNorm ----------------
__global__ __launch_bounds__(256) void gate_kernel(const float* __restrict__ rms_w)
{
    int row = blockIdx.x;
    int tid = threadIdx.x;
    const float* yr = g_y + (size_t)row * DIN;
    const float* zr = g_zx + (size_t)row * DPROJ;
    float v[8]; float s2 = 0.f;
#pragma unroll
    for (int i = 0; i < 8; i++) {
        int idx = tid + i * 256;
        float y = yr[idx];
        float z = zr[idx];
        y *= siluf(z);
        v[i] = y;
        s2 = fmaf(y, y, s2);
    }
    for (int o = 16; o; o >>= 1) s2 += __shfl_down_sync(0xffffffffu, s2, o);
    __shared__ float red[8];
    if ((tid & 31) == 0) red[tid >> 5] = s2;
    __syncthreads();
    if (tid == 0) {
        float t = 0.f;
        for (int i = 0; i < 8; i++) t += red[i];
        red[0] = rsqrtf(t / DIN + 1e-6f);
    }
    __syncthreads();
    float sc = red[0];
    size_t base = (size_t)row * DIN;
#pragma unroll
    for (int i = 0; i < 8; i++) {
        int idx = tid + i * 256;
        float f = v[i] * sc * rms_w[idx];
        unsigned short hi, lo;
        splitbf(f, hi, lo);
        g_Ahi[base + idx] = hi;
        g_Alo[base + idx] = lo;
    }
}

// ---------------- launch ----------------
extern "C" void kernel_launch(void* const* d_in, const int* in_sizes, int n_in,
                              void* d_out, int out_size)
{
    (void)in_sizes; (void)n_in; (void)out_size;
    const float* x       = (const float*)d_in[0];
    const float* ln_w    = (const float*)d_in[1];
    const float* ln_b    = (const float*)d_in[2];
    const float* W_in    = (const float*)d_in[3];
    const float* dt_bias = (const float*)d_in[4];
    const float* A_log   = (const float*)d_in[5];
    const float* Dv      = (const float*)d_in[6];
    const float* rms_w   = (const float*)d_in[7];
    const float* W_out   = (const float*)d_in[8];
    float* out = (float*)d_out;

    void *pzx, *pAhi, *pAlo, *pBhi, *pBlo;
    cudaGetSymbolAddress(&pzx,  g_zx);
    cudaGetSymbolAddress(&pAhi, g_Ahi);
    cudaGetSymbolAddress(&pAlo, g_Alo);
    cudaGetSymbolAddress(&pBhi, g_Bthi);
    cudaGetSymbolAddress(&pBlo, g_Btlo);

    static int attr_done = 0;
    if (!attr_done) {
        cudaFuncSetAttribute(mma_gemm, cudaFuncAttributeMaxDynamicSharedMemorySize, SMEM_GEMM);
        attr_done = 1;
    }

    ln_kernel<<<MROWS, 256>>>(x, ln_w, ln_b);
    cvtT_kernel<<<dim3(DIMX / 32, NPAD_IN / 32), dim3(32, 32)>>>(W_in, DIMX, DPROJ);
    mma_gemm<<<dim3(33, 128), 256, SMEM_GEMM>>>(
        (const unsigned short*)pAhi, (const unsigned short*)pAlo,
        (const unsigned short*)pBhi, (const unsigned short*)pBlo,
        (const float*)0, (float*)pzx, DPROJ, DIMX);
    bcrope_kernel<<<MROWS / 8, 256>>>();
    dtacs_kernel<<<4 * NC, 256>>>(dt_bias, A_log);
    score_kernel<<<4 * NC, 256>>>();
    chunk_kernel<<<4 * NC * NH, 256>>>(Dv);
    scan_kernel<<<4 * NH, 256>>>();
    yo_kernel<<<4 * NC * NH, 256>>>();
    gate_kernel<<<MROWS, 256>>>(rms_w);
    cvtT_kernel<<<dim3(DIN / 32, DIMX / 32), dim3(32, 32)>>>(W_out, DIN, DIMX);
    mma_gemm<<<dim3(8, 128), 256, SMEM_GEMM>>>(
        (const unsigned short*)pAhi, (const unsigned short*)pAlo,
        (const unsigned short*)pBhi, (const unsigned short*)pBlo,
        x, out, DIMX, DIN);
}

// round 8
// speedup vs baseline: 1.5882x; 1.1381x over previous
#include <cuda_runtime.h>
#include <cuda_bf16.h>
#include <math.h>
#include <stdint.h>

#define MROWS 16384
#define DIMX 1024
#define DPROJ 4192
#define DIN 2048
#define NH 32
#define HD 64
#define DS 32
#define LSEQ 4096
#define NC 64
#define NPAD_IN 4224

// ---------------- scratch ----------------
__device__ float g_zx[(size_t)MROWS * DPROJ];
__device__ float g_Brot[(size_t)MROWS * DS];
__device__ float g_Crot[(size_t)MROWS * DS];
__device__ float g_states[(size_t)4 * NC * NH * HD * DS];
__device__ float g_stin[(size_t)4 * NC * NH * HD * DS];
__device__ float g_csum[4 * NH * NC];
__device__ float g_y[(size_t)MROWS * DIN];
__device__ float g_scores[(size_t)4 * NC * 64 * 64];
__device__ float g_dtv[(size_t)4 * NH * LSEQ];
__device__ float g_acs[(size_t)4 * NH * LSEQ];
__device__ unsigned short g_Ahi[(size_t)MROWS * DIN];
__device__ unsigned short g_Alo[(size_t)MROWS * DIN];
__device__ unsigned short g_Bthi[(size_t)NPAD_IN * 1024];
__device__ unsigned short g_Btlo[(size_t)NPAD_IN * 1024];

__device__ __forceinline__ float siluf(float x) { return x / (1.f + __expf(-x)); }

__device__ __forceinline__ void splitbf(float f, unsigned short& hi, unsigned short& lo) {
    __nv_bfloat16 h = __float2bfloat16(f);
    float r = f - __bfloat162float(h);
    __nv_bfloat16 l = __float2bfloat16(r);
    hi = *reinterpret_cast<unsigned short*>(&h);
    lo = *reinterpret_cast<unsigned short*>(&l);
}
__device__ __forceinline__ float bf2f(unsigned short u) {
    __nv_bfloat16 h = *reinterpret_cast<__nv_bfloat16*>(&u);
    return __bfloat162float(h);
}

__device__ __forceinline__ uint32_t smem_u32(const void* p) {
    uint32_t a;
    asm("{ .reg .u64 t; cvta.to.shared.u64 t, %1; cvt.u32.u64 %0, t; }" : "=r"(a) : "l"(p));
    return a;
}
__device__ __forceinline__ void cpasync16(uint32_t dst, const void* src) {
    asm volatile("cp.async.cg.shared.global [%0], [%1], 16;" :: "r"(dst), "l"(src) : "memory");
}
__device__ __forceinline__ void mma16816(float* c, const uint32_t* a, const uint32_t* b) {
    asm volatile(
        "mma.sync.aligned.m16n8k16.row.col.f32.bf16.bf16.f32 "
        "{%0,%1,%2,%3}, {%4,%5,%6,%7}, {%8,%9}, {%0,%1,%2,%3};\n"
        : "+f"(c[0]), "+f"(c[1]), "+f"(c[2]), "+f"(c[3])
        : "r"(a[0]), "r"(a[1]), "r"(a[2]), "r"(a[3]), "r"(b[0]), "r"(b[1]));
}
template<int P>
__device__ __forceinline__ void ldfragA(uint32_t* a, const unsigned short (*S)[P], int row, int col) {
    a[0] = *(const uint32_t*)&S[row][col];
    a[1] = *(const uint32_t*)&S[row + 8][col];
    a[2] = *(const uint32_t*)&S[row][col + 8];
    a[3] = *(const uint32_t*)&S[row + 8][col + 8];
}
template<int P>
__device__ __forceinline__ void ldfragB(uint32_t* bb, const unsigned short (*S)[P], int row, int col) {
    bb[0] = *(const uint32_t*)&S[row][col];
    bb[1] = *(const uint32_t*)&S[row][col + 8];
}

// ---------------- LayerNorm ----------------
__global__ __launch_bounds__(256) void ln_kernel(const float* __restrict__ x,
                                                 const float* __restrict__ w,
                                                 const float* __restrict__ b)
{
    int row = blockIdx.x;
    int tid = threadIdx.x;
    const float* xr = x + (size_t)row * DIMX;
    float4 v = *(const float4*)(xr + tid * 4);
    float s  = v.x + v.y + v.z + v.w;
    float s2 = v.x*v.x + v.y*v.y + v.z*v.z + v.w*v.w;
    for (int o = 16; o; o >>= 1) {
        s  += __shfl_down_sync(0xffffffffu, s,  o);
        s2 += __shfl_down_sync(0xffffffffu, s2, o);
    }
    __shared__ float ss[8], ss2[8];
    if ((tid & 31) == 0) { ss[tid >> 5] = s; ss2[tid >> 5] = s2; }
    __syncthreads();
    if (tid == 0) {
        float t = 0.f, t2 = 0.f;
        for (int i = 0; i < 8; i++) { t += ss[i]; t2 += ss2[i]; }
        float mu = t / DIMX;
        ss[0]  = mu;
        ss2[0] = rsqrtf(t2 / DIMX - mu * mu + 1e-6f);
    }
    __syncthreads();
    float mu = ss[0], inv = ss2[0];
    int i0 = tid * 4;
    float4 wv = *(const float4*)(w + i0);
    float4 bv = *(const float4*)(b + i0);
    float o0 = (v.x - mu) * inv * wv.x + bv.x;
    float o1 = (v.y - mu) * inv * wv.y + bv.y;
    float o2 = (v.z - mu) * inv * wv.z + bv.z;
    float o3 = (v.w - mu) * inv * wv.w + bv.w;
    ushort4 hv, lv;
    splitbf(o0, hv.x, lv.x); splitbf(o1, hv.y, lv.y);
    splitbf(o2, hv.z, lv.z); splitbf(o3, hv.w, lv.w);
    *(ushort4*)(g_Ahi + (size_t)row * DIMX + i0) = hv;
    *(ushort4*)(g_Alo + (size_t)row * DIMX + i0) = lv;
}

// ---------------- W[K,N] -> Bt[n][k] bf16 hi/lo ----------------
__global__ __launch_bounds__(1024) void cvtT_kernel(const float* __restrict__ W, int K, int N)
{
    __shared__ float t[32][33];
    int k0 = blockIdx.x * 32, n0 = blockIdx.y * 32;
    int tx = threadIdx.x, ty = threadIdx.y;
    int n = n0 + tx;
    t[ty][tx] = (n < N) ? W[(size_t)(k0 + ty) * N + n] : 0.f;
    __syncthreads();
    float v = t[tx][ty];
    unsigned short hi, lo;
    splitbf(v, hi, lo);
    size_t o = (size_t)(n0 + ty) * K + k0 + tx;
    g_Bthi[o] = hi;
    g_Btlo[o] = lo;
}

// ---------------- mma.sync bf16 GEMM, hi/lo 3-pass; 2 CTAs/SM ----------------
#define KSTAGE 40960
#define SMEM_GEMM (2 * KSTAGE)
__global__ __launch_bounds__(256, 2) void mma_gemm(
    const unsigned short* __restrict__ Ahi, const unsigned short* __restrict__ Alo,
    const unsigned short* __restrict__ Bhi, const unsigned short* __restrict__ Blo,
    const float* __restrict__ R, float* __restrict__ C, int N, int K)
{
    extern __shared__ char sm[];
    int tid = threadIdx.x, lane = tid & 31, wid = tid >> 5;
    int col0 = blockIdx.x * 128, row0 = blockIdx.y * 128;
    int g = lane >> 2, tig = lane & 3;
    int m0 = (wid >> 2) * 64, n0 = (wid & 3) * 32;
    uint32_t sb = smem_u32(sm);

    float acc[4][4][4];
#pragma unroll
    for (int i = 0; i < 4; i++)
#pragma unroll
        for (int j = 0; j < 4; j++)
#pragma unroll
            for (int q = 0; q < 4; q++) acc[i][j][q] = 0.f;

    const unsigned short* srcs[4] = {Ahi, Alo, Bhi, Blo};
    int rbs[4] = {row0, row0, col0, col0};

    int KT = K >> 5;
    {
#pragma unroll
        for (int t = 0; t < 4; t++) {
#pragma unroll
            for (int cc = 0; cc < 2; cc++) {
                int chunk = tid + cc * 256;
                int row = chunk >> 2, c4 = chunk & 3;
                const void* src = srcs[t] + (size_t)(rbs[t] + row) * K + c4 * 8;
                cpasync16(sb + t * 10240 + row * 80 + c4 * 16, src);
            }
        }
        asm volatile("cp.async.commit_group;" ::: "memory");
    }

    for (int kt = 0; kt < KT; kt++) {
        if (kt + 1 < KT) {
            int buf = (kt + 1) & 1;
#pragma unroll
            for (int t = 0; t < 4; t++) {
#pragma unroll
                for (int cc = 0; cc < 2; cc++) {
                    int chunk = tid + cc * 256;
                    int row = chunk >> 2, c4 = chunk & 3;
                    const void* src = srcs[t] + (size_t)(rbs[t] + row) * K + (kt + 1) * 32 + c4 * 8;
                    cpasync16(sb + buf * KSTAGE + t * 10240 + row * 80 + c4 * 16, src);
                }
            }
            asm volatile("cp.async.commit_group;" ::: "memory");
            asm volatile("cp.async.wait_group 1;" ::: "memory");
        } else {
            asm volatile("cp.async.wait_group 0;" ::: "memory");
        }
        __syncthreads();

        const char* stb = sm + (kt & 1) * KSTAGE;
#pragma unroll
        for (int ks = 0; ks < 2; ks++) {
            int wb = (ks * 8 + tig) * 4;
            uint32_t bh[4][2], bl[4][2];
#pragma unroll
            for (int nt = 0; nt < 4; nt++) {
                const char* pb = stb + 20480 + (n0 + nt * 8 + g) * 80 + wb;
                bh[nt][0] = *(const uint32_t*)(pb);
                bh[nt][1] = *(const uint32_t*)(pb + 16);
                bl[nt][0] = *(const uint32_t*)(pb + 10240);
                bl[nt][1] = *(const uint32_t*)(pb + 10240 + 16);
            }
#pragma unroll
            for (int mt = 0; mt < 4; mt++) {
                const char* pa = stb + (m0 + mt * 16 + g) * 80 + wb;
                uint32_t ah[4], al[4];
                ah[0] = *(const uint32_t*)(pa);
                ah[1] = *(const uint32_t*)(pa + 8 * 80);
                ah[2] = *(const uint32_t*)(pa + 16);
                ah[3] = *(const uint32_t*)(pa + 8 * 80 + 16);
                al[0] = *(const uint32_t*)(pa + 10240);
                al[1] = *(const uint32_t*)(pa + 10240 + 8 * 80);
                al[2] = *(const uint32_t*)(pa + 10240 + 16);
                al[3] = *(const uint32_t*)(pa + 10240 + 8 * 80 + 16);
#pragma unroll
                for (int nt = 0; nt < 4; nt++) {
                    mma16816(acc[mt][nt], ah, bh[nt]);
                    mma16816(acc[mt][nt], ah, bl[nt]);
                    mma16816(acc[mt][nt], al, bh[nt]);
                }
            }
        }
        __syncthreads();
    }

#pragma unroll
    for (int mt = 0; mt < 4; mt++) {
        int r0i = row0 + m0 + mt * 16 + g;
#pragma unroll
        for (int nt = 0; nt < 4; nt++) {
            int cc = col0 + n0 + nt * 8 + tig * 2;
            if (cc < N) {
                float* p0 = C + (size_t)r0i * N + cc;
                float* p1 = C + (size_t)(r0i + 8) * N + cc;
                float2 v0 = make_float2(acc[mt][nt][0], acc[mt][nt][1]);
                float2 v1 = make_float2(acc[mt][nt][2], acc[mt][nt][3]);
                if (R) {
                    const float* q0 = R + (size_t)r0i * N + cc;
                    const float* q1 = R + (size_t)(r0i + 8) * N + cc;
                    v0.x += q0[0]; v0.y += q0[1];
                    v1.x += q1[0]; v1.y += q1[1];
                }
                *(float2*)p0 = v0;
                *(float2*)p1 = v1;
            }
        }
    }
}

// ---------------- silu + RoPE ----------------
__global__ __launch_bounds__(256) void bcrope_kernel()
{
    int tid = threadIdx.x;
    int r8 = tid >> 5, n = tid & 31;
    int row = blockIdx.x * 8 + r8;
    int t = row & (LSEQ - 1);
    const float* base = g_zx + (size_t)row * DPROJ;
    float bo, co;
    if (n < 16) {
        int j = n >> 1;
        double invd = exp(-((double)j) * (log(10000.0) / 8.0));
        float inv = (float)invd;
        float ang = (float)t * inv;
        float sn, cs;
        sincosf(ang, &sn, &cs);
        float b1 = siluf(base[4096 + 2 * j]);
        float b2 = siluf(base[4096 + 2 * j + 1]);
        float c1 = siluf(base[4128 + 2 * j]);
        float c2 = siluf(base[4128 + 2 * j + 1]);
        if (n & 1) { bo = b1 * sn + b2 * cs; co = c1 * sn + c2 * cs; }
        else       { bo = b1 * cs - b2 * sn; co = c1 * cs - c2 * sn; }
    } else {
        bo = siluf(base[4096 + n]);
        co = siluf(base[4128 + n]);
    }
    g_Brot[(size_t)row * DS + n] = bo;
    g_Crot[(size_t)row * DS + n] = co;
}

// ---------------- dt + A-cumsum precompute ----------------
__global__ __launch_bounds__(256) void dtacs_kernel(const float* __restrict__ dt_bias,
                                                    const float* __restrict__ A_log)
{
    int bc = blockIdx.x;
    int b = bc >> 6, c = bc & 63;
    int warp = threadIdx.x >> 5, lane = threadIdx.x & 31;
    int rowbase = b * LSEQ + c * 64;
#pragma unroll
    for (int i = 0; i < 4; i++) {
        int h = warp * 4 + i;
        float A = -__expf(A_log[h]);
        float bias = dt_bias[h];
        float raw0 = g_zx[(size_t)(rowbase + lane) * DPROJ + 4160 + h] + bias;
        float raw1 = g_zx[(size_t)(rowbase + 32 + lane) * DPROJ + 4160 + h] + bias;
        float dt0 = (raw0 > 20.f) ? raw0 : log1pf(__expf(raw0));
        float dt1 = (raw1 > 20.f) ? raw1 : log1pf(__expf(raw1));
        float a0 = dt0 * A, a1 = dt1 * A;
#pragma unroll
        for (int o = 1; o < 32; o <<= 1) {
            float t = __shfl_up_sync(0xffffffffu, a0, o);
            if (lane >= o) a0 += t;
        }
#pragma unroll
        for (int o = 1; o < 32; o <<= 1) {
            float t = __shfl_up_sync(0xffffffffu, a1, o);
            if (lane >= o) a1 += t;
        }
        a1 += __shfl_sync(0xffffffffu, a0, 31);
        size_t base = ((size_t)(b * NH + h)) * LSEQ + c * 64;
        g_dtv[base + lane] = dt0;      g_dtv[base + 32 + lane] = dt1;
        g_acs[base + lane] = a0;       g_acs[base + 32 + lane] = a1;
    }
}

// ---------------- scores: per (b,c), masked C.B^T ----------------
__global__ __launch_bounds__(256) void score_kernel()
{
    int bc = blockIdx.x;
    int b = bc >> 6, c = bc & 63;
    __shared__ float Cs[64][33], Bsm[64][33];
    int tid = threadIdx.x;
    int rowbase = b * LSEQ + c * 64;
    for (int i = tid; i < 64 * 32; i += 256) {
        int l = i >> 5, n = i & 31;
        Bsm[l][n] = g_Brot[(size_t)(rowbase + l) * DS + n];
        Cs[l][n]  = g_Crot[(size_t)(rowbase + l) * DS + n];
    }
    __syncthreads();
    int l = tid >> 2, sq = tid & 3;
    float cr[32];
#pragma unroll
    for (int n = 0; n < 32; n++) cr[n] = Cs[l][n];
    float out[16];
#pragma unroll
    for (int k = 0; k < 16; k++) {
        int s = sq * 16 + k;
        float d = 0.f;
        if (s <= l) {
#pragma unroll
            for (int n = 0; n < 32; n++) d = fmaf(cr[n], Bsm[s][n], d);
        }
        out[k] = d;
    }
    float* dst = g_scores + (size_t)bc * 4096 + l * 64 + sq * 16;
#pragma unroll
    for (int k = 0; k < 16; k += 4)
        *(float4*)(dst + k) = make_float4(out[k], out[k + 1], out[k + 2], out[k + 3]);
}

// ---------------- SSD intra-chunk: tensor-core Yd + states ----------------
__global__ __launch_bounds__(256) void chunk_kernel(const float* __restrict__ Dv)
{
    int blk = blockIdx.x;
    int h = blk & 31; int bcid = blk >> 5; int c = bcid & 63; int b = bcid >> 6;
    __shared__ unsigned short Mhi[64][72], Mlo[64][72];
    __shared__ unsigned short XThi[64][72], XTlo[64][72];   // [p][l]
    __shared__ unsigned short BwThi[32][72], BwTlo[32][72]; // [n][l]
    __shared__ float acs[64], dtv[64], wvv[64];
    int tid = threadIdx.x;
    int rowbase = b * LSEQ + c * 64;

    if (tid < 64) {
        size_t dbase = ((size_t)(b * NH + h)) * LSEQ + c * 64;
        dtv[tid] = g_dtv[dbase + tid];
        acs[tid] = g_acs[dbase + tid];
    }
    __syncthreads();
    if (tid < 64) wvv[tid] = dtv[tid] * __expf(acs[63] - acs[tid]);
    for (int i = tid; i < 4096; i += 256) {
        int l = i >> 6, p = i & 63;
        float v = siluf(g_zx[(size_t)(rowbase + l) * DPROJ + 2048 + h * 64 + p]);
        unsigned short hi, lo; splitbf(v, hi, lo);
        XThi[p][l] = hi; XTlo[p][l] = lo;
    }
    const float* psrc = g_scores + (size_t)(b * NC + c) * 4096;
    for (int i = tid; i < 4096; i += 256) {
        int l = i >> 6, s = i & 63;
        float m = 0.f;
        if (s <= l) m = psrc[i] * __expf(acs[l] - acs[s]) * dtv[s];
        unsigned short hi, lo; splitbf(m, hi, lo);
        Mhi[l][s] = hi; Mlo[l][s] = lo;
    }
    __syncthreads();   // wvv ready
    for (int i = tid; i < 2048; i += 256) {
        int l = i >> 5, n = i & 31;
        float v = g_Brot[(size_t)(rowbase + l) * DS + n] * wvv[l];
        unsigned short hi, lo; splitbf(v, hi, lo);
        BwThi[n][l] = hi; BwTlo[n][l] = lo;
    }
    __syncthreads();

    int lane = tid & 31, w = tid >> 5;
    int g = lane >> 2, tig = lane & 3;

    // ---- Yd = M @ X (64x64x64), 3-pass ----
    {
        int m0 = (w & 3) * 16, n0 = (w >> 2) * 32;
        float acc[4][4];
#pragma unroll
        for (int i = 0; i < 4; i++)
#pragma unroll
            for (int q = 0; q < 4; q++) acc[i][q] = 0.f;
#pragma unroll
        for (int kt = 0; kt < 4; kt++) {
            int col = kt * 16 + 2 * tig;
            uint32_t ah[4], al[4];
            ldfragA<72>(ah, Mhi, m0 + g, col);
            ldfragA<72>(al, Mlo, m0 + g, col);
#pragma unroll
            for (int nt = 0; nt < 4; nt++) {
                uint32_t bh[2], bl[2];
                ldfragB<72>(bh, XThi, n0 + nt * 8 + g, col);
                ldfragB<72>(bl, XTlo, n0 + nt * 8 + g, col);
                mma16816(acc[nt], ah, bh);
                mma16816(acc[nt], ah, bl);
                mma16816(acc[nt], al, bh);
            }
        }
        float Dh = Dv[h];
#pragma unroll
        for (int nt = 0; nt < 4; nt++) {
            int p0 = n0 + nt * 8 + 2 * tig;
            int l0 = m0 + g, l1 = l0 + 8;
            float x00 = bf2f(XThi[p0][l0]) + bf2f(XTlo[p0][l0]);
            float x01 = bf2f(XThi[p0 + 1][l0]) + bf2f(XTlo[p0 + 1][l0]);
            float x10 = bf2f(XThi[p0][l1]) + bf2f(XTlo[p0][l1]);
            float x11 = bf2f(XThi[p0 + 1][l1]) + bf2f(XTlo[p0 + 1][l1]);
            float* y0 = g_y + (size_t)(rowbase + l0) * DIN + h * HD + p0;
            float* y1 = g_y + (size_t)(rowbase + l1) * DIN + h * HD + p0;
            *(float2*)y0 = make_float2(acc[nt][0] + Dh * x00, acc[nt][1] + Dh * x01);
            *(float2*)y1 = make_float2(acc[nt][2] + Dh * x10, acc[nt][3] + Dh * x11);
        }
    }

    // ---- states = X^T @ Bw (64x32x64), 3-pass ----
    {
        int m0 = (w & 3) * 16;       // p
        int n0 = (w >> 2) * 16;      // n
        float acc[2][4];
#pragma unroll
        for (int i = 0; i < 2; i++)
#pragma unroll
            for (int q = 0; q < 4; q++) acc[i][q] = 0.f;
#pragma unroll
        for (int kt = 0; kt < 4; kt++) {
            int col = kt * 16 + 2 * tig;
            uint32_t ah[4], al[4];
            ldfragA<72>(ah, XThi, m0 + g, col);
            ldfragA<72>(al, XTlo, m0 + g, col);
#pragma unroll
            for (int nt = 0; nt < 2; nt++) {
                uint32_t bh[2], bl[2];
                ldfragB<72>(bh, BwThi, n0 + nt * 8 + g, col);
                ldfragB<72>(bl, BwTlo, n0 + nt * 8 + g, col);
                mma16816(acc[nt], ah, bh);
                mma16816(acc[nt], ah, bl);
                mma16816(acc[nt], al, bh);
            }
        }
        size_t sbase = ((size_t)((b * NC + c) * NH + h)) * (HD * DS);
#pragma unroll
        for (int nt = 0; nt < 2; nt++) {
            int nn = n0 + nt * 8 + 2 * tig;
            int p0 = m0 + g, p1 = p0 + 8;
            *(float2*)&g_states[sbase + p0 * DS + nn] = make_float2(acc[nt][0], acc[nt][1]);
            *(float2*)&g_states[sbase + p1 * DS + nn] = make_float2(acc[nt][2], acc[nt][3]);
        }
    }
    if (tid == 0) g_csum[(b * NH + h) * NC + c] = acs[63];
}

// ---------------- inter-chunk scan ----------------
__global__ __launch_bounds__(256) void scan_kernel()
{
    int bh = blockIdx.x;
    int b = bh >> 5, h = bh & 31;
    int tid = threadIdx.x;
    float S[8];
#pragma unroll
    for (int j = 0; j < 8; j++) S[j] = 0.f;
    for (int c = 0; c < NC; c++) {
        size_t base = ((size_t)((b * NC + c) * NH + h)) * (HD * DS);
#pragma unroll
        for (int j = 0; j < 8; j++) g_stin[base + tid + j * 256] = S[j];
        float e = __expf(g_csum[bh * NC + c]);
#pragma unroll
        for (int j = 0; j < 8; j++) S[j] = S[j] * e + g_states[base + tid + j * 256];
    }
}

// ---------------- Yo = C @ S^T (64x64x32), 3-pass, y += exp(acs)*Yo ----------------
__global__ __launch_bounds__(256) void yo_kernel()
{
    int blk = blockIdx.x;
    int h = blk & 31; int bcid = blk >> 5; int c = bcid & 63; int b = bcid >> 6;
    __shared__ unsigned short Chi[64][40], Clo[64][40];   // [l][n]
    __shared__ unsigned short Shi[64][40], Slo[64][40];   // [p][n]
    __shared__ float acs[64];
    int tid = threadIdx.x;
    int rowbase = b * LSEQ + c * 64;

    if (tid < 64) {
        size_t dbase = ((size_t)(b * NH + h)) * LSEQ + c * 64;
        acs[tid] = g_acs[dbase + tid];
    }
    size_t sbase = ((size_t)((b * NC + c) * NH + h)) * (HD * DS);
    for (int i = tid; i < 2048; i += 256) {
        int l = i >> 5, n = i & 31;
        unsigned short hi, lo;
        splitbf(g_Crot[(size_t)(rowbase + l) * DS + n], hi, lo);
        Chi[l][n] = hi; Clo[l][n] = lo;
        splitbf(g_stin[sbase + i], hi, lo);
        Shi[l][n] = hi; Slo[l][n] = lo;
    }
    __syncthreads();

    int lane = tid & 31, w = tid >> 5;
    int g = lane >> 2, tig = lane & 3;
    int m0 = (w & 3) * 16, n0 = (w >> 2) * 32;
    float acc[4][4];
#pragma unroll
    for (int i = 0; i < 4; i++)
#pragma unroll
        for (int q = 0; q < 4; q++) acc[i][q] = 0.f;
#pragma unroll
    for (int kt = 0; kt < 2; kt++) {
        int col = kt * 16 + 2 * tig;
        uint32_t ah[4], al[4];
        ldfragA<40>(ah, Chi, m0 + g, col);
        ldfragA<40>(al, Clo, m0 + g, col);
#pragma unroll
        for (int nt = 0; nt < 4; nt++) {
            uint32_t bh[2], bl[2];
            ldfragB<40>(bh, Shi, n0 + nt * 8 + g, col);
            ldfragB<40>(bl, Slo, n0 + nt * 8 + g, col);
            mma16816(acc[nt], ah, bh);
            mma16816(acc[nt], ah, bl);
            mma16816(acc[nt], al, bh);
        }
    }
    int l0 = m0 + g, l1 = l0 + 8;
    float el0 = __expf(acs[l0]), el1 = __expf(acs[l1]);
#pragma unroll
    for (int nt = 0; nt < 4; nt++) {
        int p0 = n0 + nt * 8 + 2 * tig;
        float* y0 = g_y + (size_t)(rowbase + l0) * DIN + h * HD + p0;
        float* y1 = g_y + (size_t)(rowbase + l1) * DIN + h * HD + p0;
        float2 v0 = *(float2*)y0, v1 = *(float2*)y1;
        v0.x += el0 * acc[nt][0]; v0.y += el0 * acc[nt][1];
        v1.x += el1 * acc[nt][2]; v1.y += el1 * acc[nt][3];
        *(float2*)y0 = v0;
        *(float2*)y1 = v1;
    }
}

// ---------------- gate + RMSNorm ----------------
__global__ __launch_bounds__(256) void gate_kernel(const float* __restrict__ rms_w)
{
    int row = blockIdx.x;
    int tid = threadIdx.x;
    const float* yr = g_y + (size_t)row * DIN;
    const float* zr = g_zx + (size_t)row * DPROJ;
    float v[8]; float s2 = 0.f;
#pragma unroll
    for (int i = 0; i < 8; i++) {
        int idx = tid + i * 256;
        float y = yr[idx];
        float z = zr[idx];
        y *= siluf(z);
        v[i] = y;
        s2 = fmaf(y, y, s2);
    }
    for (int o = 16; o; o >>= 1) s2 += __shfl_down_sync(0xffffffffu, s2, o);
    __shared__ float red[8];
    if ((tid & 31) == 0) red[tid >> 5] = s2;
    __syncthreads();
    if (tid == 0) {
        float t = 0.f;
        for (int i = 0; i < 8; i++) t += red[i];
        red[0] = rsqrtf(t / DIN + 1e-6f);
    }
    __syncthreads();
    float sc = red[0];
    size_t base = (size_t)row * DIN;
#pragma unroll
    for (int i = 0; i < 8; i++) {
        int idx = tid + i * 256;
        float f = v[i] * sc * rms_w[idx];
        unsigned short hi, lo;
        splitbf(f, hi, lo);
        g_Ahi[base + idx] = hi;
        g_Alo[base + idx] = lo;
    }
}

// ---------------- launch ----------------
extern "C" void kernel_launch(void* const* d_in, const int* in_sizes, int n_in,
                              void* d_out, int out_size)
{
    (void)in_sizes; (void)n_in; (void)out_size;
    const float* x       = (const float*)d_in[0];
    const float* ln_w    = (const float*)d_in[1];
    const float* ln_b    = (const float*)d_in[2];
    const float* W_in    = (const float*)d_in[3];
    const float* dt_bias = (const float*)d_in[4];
    const float* A_log   = (const float*)d_in[5];
    const float* Dv      = (const float*)d_in[6];
    const float* rms_w   = (const float*)d_in[7];
    const float* W_out   = (const float*)d_in[8];
    float* out = (float*)d_out;

    void *pzx, *pAhi, *pAlo, *pBhi, *pBlo;
    cudaGetSymbolAddress(&pzx,  g_zx);
    cudaGetSymbolAddress(&pAhi, g_Ahi);
    cudaGetSymbolAddress(&pAlo, g_Alo);
    cudaGetSymbolAddress(&pBhi, g_Bthi);
    cudaGetSymbolAddress(&pBlo, g_Btlo);

    static int attr_done = 0;
    if (!attr_done) {
        cudaFuncSetAttribute(mma_gemm, cudaFuncAttributeMaxDynamicSharedMemorySize, SMEM_GEMM);
        attr_done = 1;
    }

    ln_kernel<<<MROWS, 256>>>(x, ln_w, ln_b);
    cvtT_kernel<<<dim3(DIMX / 32, NPAD_IN / 32), dim3(32, 32)>>>(W_in, DIMX, DPROJ);
    mma_gemm<<<dim3(33, 128), 256, SMEM_GEMM>>>(
        (const unsigned short*)pAhi, (const unsigned short*)pAlo,
        (const unsigned short*)pBhi, (const unsigned short*)pBlo,
        (const float*)0, (float*)pzx, DPROJ, DIMX);
    bcrope_kernel<<<MROWS / 8, 256>>>();
    dtacs_kernel<<<4 * NC, 256>>>(dt_bias, A_log);
    score_kernel<<<4 * NC, 256>>>();
    chunk_kernel<<<4 * NC * NH, 256>>>(Dv);
    scan_kernel<<<4 * NH, 256>>>();
    yo_kernel<<<4 * NC * NH, 256>>>();
    gate_kernel<<<MROWS, 256>>>(rms_w);
    cvtT_kernel<<<dim3(DIN / 32, DIMX / 32), dim3(32, 32)>>>(W_out, DIN, DIMX);
    mma_gemm<<<dim3(8, 128), 256, SMEM_GEMM>>>(
        (const unsigned short*)pAhi, (const unsigned short*)pAlo,
        (const unsigned short*)pBhi, (const unsigned short*)pBlo,
        x, out, DIMX, DIN);
}

// round 9
// speedup vs baseline: 1.6012x; 1.0082x over previous
#include <cuda_runtime.h>
#include <cuda_bf16.h>
#include <math.h>
#include <stdint.h>

#define MROWS 16384
#define DIMX 1024
#define DPROJ 4192
#define DIN 2048
#define NH 32
#define HD 64
#define DS 32
#define LSEQ 4096
#define NC 64
#define NPAD_IN 4224

// ---------------- scratch ----------------
__device__ float g_zx[(size_t)MROWS * DPROJ];
__device__ float g_Brot[(size_t)MROWS * DS];
__device__ float g_Crot[(size_t)MROWS * DS];
__device__ float g_states[(size_t)4 * NC * NH * HD * DS];
__device__ float g_stin[(size_t)4 * NC * NH * HD * DS];
__device__ float g_y[(size_t)MROWS * DIN];
__device__ float g_scores[(size_t)4 * NC * 64 * 64];
__device__ float g_dtv[(size_t)4 * NH * LSEQ];
__device__ float g_acs[(size_t)4 * NH * LSEQ];
__device__ unsigned short g_Ahi[(size_t)MROWS * DIN];
__device__ unsigned short g_Alo[(size_t)MROWS * DIN];
__device__ unsigned short g_Bthi[(size_t)NPAD_IN * 1024];
__device__ unsigned short g_Btlo[(size_t)NPAD_IN * 1024];

__device__ __forceinline__ float siluf(float x) { return x / (1.f + __expf(-x)); }

__device__ __forceinline__ void splitbf(float f, unsigned short& hi, unsigned short& lo) {
    __nv_bfloat16 h = __float2bfloat16(f);
    float r = f - __bfloat162float(h);
    __nv_bfloat16 l = __float2bfloat16(r);
    hi = *reinterpret_cast<unsigned short*>(&h);
    lo = *reinterpret_cast<unsigned short*>(&l);
}
__device__ __forceinline__ float bf2f(unsigned short u) {
    __nv_bfloat16 h = *reinterpret_cast<__nv_bfloat16*>(&u);
    return __bfloat162float(h);
}

__device__ __forceinline__ uint32_t smem_u32(const void* p) {
    uint32_t a;
    asm("{ .reg .u64 t; cvta.to.shared.u64 t, %1; cvt.u32.u64 %0, t; }" : "=r"(a) : "l"(p));
    return a;
}
__device__ __forceinline__ void cpasync16(uint32_t dst, const void* src) {
    asm volatile("cp.async.cg.shared.global [%0], [%1], 16;" :: "r"(dst), "l"(src) : "memory");
}
__device__ __forceinline__ void mma16816(float* c, const uint32_t* a, const uint32_t* b) {
    asm volatile(
        "mma.sync.aligned.m16n8k16.row.col.f32.bf16.bf16.f32 "
        "{%0,%1,%2,%3}, {%4,%5,%6,%7}, {%8,%9}, {%0,%1,%2,%3};\n"
        : "+f"(c[0]), "+f"(c[1]), "+f"(c[2]), "+f"(c[3])
        : "r"(a[0]), "r"(a[1]), "r"(a[2]), "r"(a[3]), "r"(b[0]), "r"(b[1]));
}
template<int P>
__device__ __forceinline__ void ldfragA(uint32_t* a, const unsigned short (*S)[P], int row, int col) {
    a[0] = *(const uint32_t*)&S[row][col];
    a[1] = *(const uint32_t*)&S[row + 8][col];
    a[2] = *(const uint32_t*)&S[row][col + 8];
    a[3] = *(const uint32_t*)&S[row + 8][col + 8];
}
template<int P>
__device__ __forceinline__ void ldfragB(uint32_t* bb, const unsigned short (*S)[P], int row, int col) {
    bb[0] = *(const uint32_t*)&S[row][col];
    bb[1] = *(const uint32_t*)&S[row][col + 8];
}

// ---------------- LayerNorm ----------------
__global__ __launch_bounds__(256) void ln_kernel(const float* __restrict__ x,
                                                 const float* __restrict__ w,
                                                 const float* __restrict__ b)
{
    int row = blockIdx.x;
    int tid = threadIdx.x;
    const float* xr = x + (size_t)row * DIMX;
    float4 v = *(const float4*)(xr + tid * 4);
    float s  = v.x + v.y + v.z + v.w;
    float s2 = v.x*v.x + v.y*v.y + v.z*v.z + v.w*v.w;
    for (int o = 16; o; o >>= 1) {
        s  += __shfl_down_sync(0xffffffffu, s,  o);
        s2 += __shfl_down_sync(0xffffffffu, s2, o);
    }
    __shared__ float ss[8], ss2[8];
    if ((tid & 31) == 0) { ss[tid >> 5] = s; ss2[tid >> 5] = s2; }
    __syncthreads();
    if (tid == 0) {
        float t = 0.f, t2 = 0.f;
        for (int i = 0; i < 8; i++) { t += ss[i]; t2 += ss2[i]; }
        float mu = t / DIMX;
        ss[0]  = mu;
        ss2[0] = rsqrtf(t2 / DIMX - mu * mu + 1e-6f);
    }
    __syncthreads();
    float mu = ss[0], inv = ss2[0];
    int i0 = tid * 4;
    float4 wv = *(const float4*)(w + i0);
    float4 bv = *(const float4*)(b + i0);
    float o0 = (v.x - mu) * inv * wv.x + bv.x;
    float o1 = (v.y - mu) * inv * wv.y + bv.y;
    float o2 = (v.z - mu) * inv * wv.z + bv.z;
    float o3 = (v.w - mu) * inv * wv.w + bv.w;
    ushort4 hv, lv;
    splitbf(o0, hv.x, lv.x); splitbf(o1, hv.y, lv.y);
    splitbf(o2, hv.z, lv.z); splitbf(o3, hv.w, lv.w);
    *(ushort4*)(g_Ahi + (size_t)row * DIMX + i0) = hv;
    *(ushort4*)(g_Alo + (size_t)row * DIMX + i0) = lv;
}

// ---------------- W[K,N] -> Bt[n][k] bf16 hi/lo ----------------
__global__ __launch_bounds__(1024) void cvtT_kernel(const float* __restrict__ W, int K, int N)
{
    __shared__ float t[32][33];
    int k0 = blockIdx.x * 32, n0 = blockIdx.y * 32;
    int tx = threadIdx.x, ty = threadIdx.y;
    int n = n0 + tx;
    t[ty][tx] = (n < N) ? W[(size_t)(k0 + ty) * N + n] : 0.f;
    __syncthreads();
    float v = t[tx][ty];
    unsigned short hi, lo;
    splitbf(v, hi, lo);
    size_t o = (size_t)(n0 + ty) * K + k0 + tx;
    g_Bthi[o] = hi;
    g_Btlo[o] = lo;
}

// ---------------- mma.sync bf16 GEMM, hi/lo 3-pass; 2 CTAs/SM ----------------
#define KSTAGE 40960
#define SMEM_GEMM (2 * KSTAGE)
__global__ __launch_bounds__(256, 2) void mma_gemm(
    const unsigned short* __restrict__ Ahi, const unsigned short* __restrict__ Alo,
    const unsigned short* __restrict__ Bhi, const unsigned short* __restrict__ Blo,
    const float* __restrict__ R, float* __restrict__ C, int N, int K)
{
    extern __shared__ char sm[];
    int tid = threadIdx.x, lane = tid & 31, wid = tid >> 5;
    int col0 = blockIdx.x * 128, row0 = blockIdx.y * 128;
    int g = lane >> 2, tig = lane & 3;
    int m0 = (wid >> 2) * 64, n0 = (wid & 3) * 32;
    uint32_t sb = smem_u32(sm);

    float acc[4][4][4];
#pragma unroll
    for (int i = 0; i < 4; i++)
#pragma unroll
        for (int j = 0; j < 4; j++)
#pragma unroll
            for (int q = 0; q < 4; q++) acc[i][j][q] = 0.f;

    const unsigned short* srcs[4] = {Ahi, Alo, Bhi, Blo};
    int rbs[4] = {row0, row0, col0, col0};

    int KT = K >> 5;
    {
#pragma unroll
        for (int t = 0; t < 4; t++) {
#pragma unroll
            for (int cc = 0; cc < 2; cc++) {
                int chunk = tid + cc * 256;
                int row = chunk >> 2, c4 = chunk & 3;
                const void* src = srcs[t] + (size_t)(rbs[t] + row) * K + c4 * 8;
                cpasync16(sb + t * 10240 + row * 80 + c4 * 16, src);
            }
        }
        asm volatile("cp.async.commit_group;" ::: "memory");
    }

    for (int kt = 0; kt < KT; kt++) {
        if (kt + 1 < KT) {
            int buf = (kt + 1) & 1;
#pragma unroll
            for (int t = 0; t < 4; t++) {
#pragma unroll
                for (int cc = 0; cc < 2; cc++) {
                    int chunk = tid + cc * 256;
                    int row = chunk >> 2, c4 = chunk & 3;
                    const void* src = srcs[t] + (size_t)(rbs[t] + row) * K + (kt + 1) * 32 + c4 * 8;
                    cpasync16(sb + buf * KSTAGE + t * 10240 + row * 80 + c4 * 16, src);
                }
            }
            asm volatile("cp.async.commit_group;" ::: "memory");
            asm volatile("cp.async.wait_group 1;" ::: "memory");
        } else {
            asm volatile("cp.async.wait_group 0;" ::: "memory");
        }
        __syncthreads();

        const char* stb = sm + (kt & 1) * KSTAGE;
#pragma unroll
        for (int ks = 0; ks < 2; ks++) {
            int wb = (ks * 8 + tig) * 4;
            uint32_t bh[4][2], bl[4][2];
#pragma unroll
            for (int nt = 0; nt < 4; nt++) {
                const char* pb = stb + 20480 + (n0 + nt * 8 + g) * 80 + wb;
                bh[nt][0] = *(const uint32_t*)(pb);
                bh[nt][1] = *(const uint32_t*)(pb + 16);
                bl[nt][0] = *(const uint32_t*)(pb + 10240);
                bl[nt][1] = *(const uint32_t*)(pb + 10240 + 16);
            }
#pragma unroll
            for (int mt = 0; mt < 4; mt++) {
                const char* pa = stb + (m0 + mt * 16 + g) * 80 + wb;
                uint32_t ah[4], al[4];
                ah[0] = *(const uint32_t*)(pa);
                ah[1] = *(const uint32_t*)(pa + 8 * 80);
                ah[2] = *(const uint32_t*)(pa + 16);
                ah[3] = *(const uint32_t*)(pa + 8 * 80 + 16);
                al[0] = *(const uint32_t*)(pa + 10240);
                al[1] = *(const uint32_t*)(pa + 10240 + 8 * 80);
                al[2] = *(const uint32_t*)(pa + 10240 + 16);
                al[3] = *(const uint32_t*)(pa + 10240 + 8 * 80 + 16);
#pragma unroll
                for (int nt = 0; nt < 4; nt++) {
                    mma16816(acc[mt][nt], ah, bh[nt]);
                    mma16816(acc[mt][nt], ah, bl[nt]);
                    mma16816(acc[mt][nt], al, bh[nt]);
                }
            }
        }
        __syncthreads();
    }

#pragma unroll
    for (int mt = 0; mt < 4; mt++) {
        int r0i = row0 + m0 + mt * 16 + g;
#pragma unroll
        for (int nt = 0; nt < 4; nt++) {
            int cc = col0 + n0 + nt * 8 + tig * 2;
            if (cc < N) {
                float* p0 = C + (size_t)r0i * N + cc;
                float* p1 = C + (size_t)(r0i + 8) * N + cc;
                float2 v0 = make_float2(acc[mt][nt][0], acc[mt][nt][1]);
                float2 v1 = make_float2(acc[mt][nt][2], acc[mt][nt][3]);
                if (R) {
                    const float* q0 = R + (size_t)r0i * N + cc;
                    const float* q1 = R + (size_t)(r0i + 8) * N + cc;
                    v0.x += q0[0]; v0.y += q0[1];
                    v1.x += q1[0]; v1.y += q1[1];
                }
                *(float2*)p0 = v0;
                *(float2*)p1 = v1;
            }
        }
    }
}

// ---------------- silu + RoPE ----------------
__global__ __launch_bounds__(256) void bcrope_kernel()
{
    int tid = threadIdx.x;
    int r8 = tid >> 5, n = tid & 31;
    int row = blockIdx.x * 8 + r8;
    int t = row & (LSEQ - 1);
    const float* base = g_zx + (size_t)row * DPROJ;
    float bo, co;
    if (n < 16) {
        int j = n >> 1;
        double invd = exp(-((double)j) * (log(10000.0) / 8.0));
        float inv = (float)invd;
        float ang = (float)t * inv;
        float sn, cs;
        sincosf(ang, &sn, &cs);
        float b1 = siluf(base[4096 + 2 * j]);
        float b2 = siluf(base[4096 + 2 * j + 1]);
        float c1 = siluf(base[4128 + 2 * j]);
        float c2 = siluf(base[4128 + 2 * j + 1]);
        if (n & 1) { bo = b1 * sn + b2 * cs; co = c1 * sn + c2 * cs; }
        else       { bo = b1 * cs - b2 * sn; co = c1 * cs - c2 * sn; }
    } else {
        bo = siluf(base[4096 + n]);
        co = siluf(base[4128 + n]);
    }
    g_Brot[(size_t)row * DS + n] = bo;
    g_Crot[(size_t)row * DS + n] = co;
}

// ---------------- dt + A-cumsum precompute ----------------
__global__ __launch_bounds__(256) void dtacs_kernel(const float* __restrict__ dt_bias,
                                                    const float* __restrict__ A_log)
{
    int bc = blockIdx.x;
    int b = bc >> 6, c = bc & 63;
    int warp = threadIdx.x >> 5, lane = threadIdx.x & 31;
    int rowbase = b * LSEQ + c * 64;
#pragma unroll
    for (int i = 0; i < 4; i++) {
        int h = warp * 4 + i;
        float A = -__expf(A_log[h]);
        float bias = dt_bias[h];
        float raw0 = g_zx[(size_t)(rowbase + lane) * DPROJ + 4160 + h] + bias;
        float raw1 = g_zx[(size_t)(rowbase + 32 + lane) * DPROJ + 4160 + h] + bias;
        float dt0 = (raw0 > 20.f) ? raw0 : log1pf(__expf(raw0));
        float dt1 = (raw1 > 20.f) ? raw1 : log1pf(__expf(raw1));
        float a0 = dt0 * A, a1 = dt1 * A;
#pragma unroll
        for (int o = 1; o < 32; o <<= 1) {
            float t = __shfl_up_sync(0xffffffffu, a0, o);
            if (lane >= o) a0 += t;
        }
#pragma unroll
        for (int o = 1; o < 32; o <<= 1) {
            float t = __shfl_up_sync(0xffffffffu, a1, o);
            if (lane >= o) a1 += t;
        }
        a1 += __shfl_sync(0xffffffffu, a0, 31);
        size_t base = ((size_t)(b * NH + h)) * LSEQ + c * 64;
        g_dtv[base + lane] = dt0;      g_dtv[base + 32 + lane] = dt1;
        g_acs[base + lane] = a0;       g_acs[base + 32 + lane] = a1;
    }
}

// ---------------- scores: per (b,c), masked C.B^T ----------------
__global__ __launch_bounds__(256) void score_kernel()
{
    int bc = blockIdx.x;
    int b = bc >> 6, c = bc & 63;
    __shared__ float Cs[64][33], Bsm[64][33];
    int tid = threadIdx.x;
    int rowbase = b * LSEQ + c * 64;
    for (int i = tid; i < 64 * 32; i += 256) {
        int l = i >> 5, n = i & 31;
        Bsm[l][n] = g_Brot[(size_t)(rowbase + l) * DS + n];
        Cs[l][n]  = g_Crot[(size_t)(rowbase + l) * DS + n];
    }
    __syncthreads();
    int l = tid >> 2, sq = tid & 3;
    float cr[32];
#pragma unroll
    for (int n = 0; n < 32; n++) cr[n] = Cs[l][n];
    float out[16];
#pragma unroll
    for (int k = 0; k < 16; k++) {
        int s = sq * 16 + k;
        float d = 0.f;
        if (s <= l) {
#pragma unroll
            for (int n = 0; n < 32; n++) d = fmaf(cr[n], Bsm[s][n], d);
        }
        out[k] = d;
    }
    float* dst = g_scores + (size_t)bc * 4096 + l * 64 + sq * 16;
#pragma unroll
    for (int k = 0; k < 16; k += 4)
        *(float4*)(dst + k) = make_float4(out[k], out[k + 1], out[k + 2], out[k + 3]);
}

// ---------------- SSD intra-chunk: tensor-core Yd + states ----------------
__global__ __launch_bounds__(256) void chunk_kernel(const float* __restrict__ Dv)
{
    int blk = blockIdx.x;
    int h = blk & 31; int bcid = blk >> 5; int c = bcid & 63; int b = bcid >> 6;
    __shared__ unsigned short Mhi[64][72], Mlo[64][72];
    __shared__ unsigned short XThi[64][72], XTlo[64][72];   // [p][l]
    __shared__ unsigned short BwThi[32][72], BwTlo[32][72]; // [n][l]
    __shared__ float acs[64], dtv[64], wvv[64];
    int tid = threadIdx.x;
    int rowbase = b * LSEQ + c * 64;

    if (tid < 64) {
        size_t dbase = ((size_t)(b * NH + h)) * LSEQ + c * 64;
        dtv[tid] = g_dtv[dbase + tid];
        acs[tid] = g_acs[dbase + tid];
    }
    __syncthreads();
    if (tid < 64) wvv[tid] = dtv[tid] * __expf(acs[63] - acs[tid]);
    for (int i = tid; i < 4096; i += 256) {
        int l = i >> 6, p = i & 63;
        float v = siluf(g_zx[(size_t)(rowbase + l) * DPROJ + 2048 + h * 64 + p]);
        unsigned short hi, lo; splitbf(v, hi, lo);
        XThi[p][l] = hi; XTlo[p][l] = lo;
    }
    const float* psrc = g_scores + (size_t)(b * NC + c) * 4096;
    for (int i = tid; i < 4096; i += 256) {
        int l = i >> 6, s = i & 63;
        float m = 0.f;
        if (s <= l) m = psrc[i] * __expf(acs[l] - acs[s]) * dtv[s];
        unsigned short hi, lo; splitbf(m, hi, lo);
        Mhi[l][s] = hi; Mlo[l][s] = lo;
    }
    __syncthreads();   // wvv ready
    for (int i = tid; i < 2048; i += 256) {
        int l = i >> 5, n = i & 31;
        float v = g_Brot[(size_t)(rowbase + l) * DS + n] * wvv[l];
        unsigned short hi, lo; splitbf(v, hi, lo);
        BwThi[n][l] = hi; BwTlo[n][l] = lo;
    }
    __syncthreads();

    int lane = tid & 31, w = tid >> 5;
    int g = lane >> 2, tig = lane & 3;

    // ---- Yd = M @ X (64x64x64), 3-pass ----
    {
        int m0 = (w & 3) * 16, n0 = (w >> 2) * 32;
        float acc[4][4];
#pragma unroll
        for (int i = 0; i < 4; i++)
#pragma unroll
            for (int q = 0; q < 4; q++) acc[i][q] = 0.f;
#pragma unroll
        for (int kt = 0; kt < 4; kt++) {
            int col = kt * 16 + 2 * tig;
            uint32_t ah[4], al[4];
            ldfragA<72>(ah, Mhi, m0 + g, col);
            ldfragA<72>(al, Mlo, m0 + g, col);
#pragma unroll
            for (int nt = 0; nt < 4; nt++) {
                uint32_t bh[2], bl[2];
                ldfragB<72>(bh, XThi, n0 + nt * 8 + g, col);
                ldfragB<72>(bl, XTlo, n0 + nt * 8 + g, col);
                mma16816(acc[nt], ah, bh);
                mma16816(acc[nt], ah, bl);
                mma16816(acc[nt], al, bh);
            }
        }
        float Dh = Dv[h];
#pragma unroll
        for (int nt = 0; nt < 4; nt++) {
            int p0 = n0 + nt * 8 + 2 * tig;
            int l0 = m0 + g, l1 = l0 + 8;
            float x00 = bf2f(XThi[p0][l0]) + bf2f(XTlo[p0][l0]);
            float x01 = bf2f(XThi[p0 + 1][l0]) + bf2f(XTlo[p0 + 1][l0]);
            float x10 = bf2f(XThi[p0][l1]) + bf2f(XTlo[p0][l1]);
            float x11 = bf2f(XThi[p0 + 1][l1]) + bf2f(XTlo[p0 + 1][l1]);
            float* y0 = g_y + (size_t)(rowbase + l0) * DIN + h * HD + p0;
            float* y1 = g_y + (size_t)(rowbase + l1) * DIN + h * HD + p0;
            *(float2*)y0 = make_float2(acc[nt][0] + Dh * x00, acc[nt][1] + Dh * x01);
            *(float2*)y1 = make_float2(acc[nt][2] + Dh * x10, acc[nt][3] + Dh * x11);
        }
    }

    // ---- states = X^T @ Bw (64x32x64), 3-pass ----
    {
        int m0 = (w & 3) * 16;       // p
        int n0 = (w >> 2) * 16;      // n
        float acc[2][4];
#pragma unroll
        for (int i = 0; i < 2; i++)
#pragma unroll
            for (int q = 0; q < 4; q++) acc[i][q] = 0.f;
#pragma unroll
        for (int kt = 0; kt < 4; kt++) {
            int col = kt * 16 + 2 * tig;
            uint32_t ah[4], al[4];
            ldfragA<72>(ah, XThi, m0 + g, col);
            ldfragA<72>(al, XTlo, m0 + g, col);
#pragma unroll
            for (int nt = 0; nt < 2; nt++) {
                uint32_t bh[2], bl[2];
                ldfragB<72>(bh, BwThi, n0 + nt * 8 + g, col);
                ldfragB<72>(bl, BwTlo, n0 + nt * 8 + g, col);
                mma16816(acc[nt], ah, bh);
                mma16816(acc[nt], ah, bl);
                mma16816(acc[nt], al, bh);
            }
        }
        size_t sbase = ((size_t)((b * NC + c) * NH + h)) * (HD * DS);
#pragma unroll
        for (int nt = 0; nt < 2; nt++) {
            int nn = n0 + nt * 8 + 2 * tig;
            int p0 = m0 + g, p1 = p0 + 8;
            *(float2*)&g_states[sbase + p0 * DS + nn] = make_float2(acc[nt][0], acc[nt][1]);
            *(float2*)&g_states[sbase + p1 * DS + nn] = make_float2(acc[nt][2], acc[nt][3]);
        }
    }
}

// ---------------- inter-chunk scan: 1 elem/thread, prefetched ----------------
__global__ __launch_bounds__(256) void scan_kernel()
{
    int bh = blockIdx.x >> 3;               // b*NH + h
    int e = (blockIdx.x & 7) * 256 + threadIdx.x;   // 0..2047
    int b = bh >> 5, h = bh & 31;
    __shared__ float ec[64];
    if (threadIdx.x < 64) {
        float cs = g_acs[(size_t)bh * LSEQ + threadIdx.x * 64 + 63];
        ec[threadIdx.x] = __expf(cs);
    }
    __syncthreads();
    size_t stride = (size_t)NH * HD * DS;
    size_t base = ((size_t)(b * NC) * NH + h) * (HD * DS) + e;
    float S = 0.f;
    float nxt = g_states[base];
#pragma unroll 4
    for (int c = 0; c < NC; c++) {
        g_stin[base] = S;
        float cur = nxt;
        if (c + 1 < NC) nxt = g_states[base + stride];
        S = fmaf(S, ec[c], cur);
        base += stride;
    }
}

// ---------------- Yo = C @ S^T (64x64x32), 3-pass, y += exp(acs)*Yo ----------------
__global__ __launch_bounds__(256) void yo_kernel()
{
    int blk = blockIdx.x;
    int h = blk & 31; int bcid = blk >> 5; int c = bcid & 63; int b = bcid >> 6;
    __shared__ unsigned short Chi[64][40], Clo[64][40];   // [l][n]
    __shared__ unsigned short Shi[64][40], Slo[64][40];   // [p][n]
    __shared__ float acs[64];
    int tid = threadIdx.x;
    int rowbase = b * LSEQ + c * 64;

    if (tid < 64) {
        size_t dbase = ((size_t)(b * NH + h)) * LSEQ + c * 64;
        acs[tid] = g_acs[dbase + tid];
    }
    size_t sbase = ((size_t)((b * NC + c) * NH + h)) * (HD * DS);
    for (int i = tid; i < 2048; i += 256) {
        int l = i >> 5, n = i & 31;
        unsigned short hi, lo;
        splitbf(g_Crot[(size_t)(rowbase + l) * DS + n], hi, lo);
        Chi[l][n] = hi; Clo[l][n] = lo;
        splitbf(g_stin[sbase + i], hi, lo);
        Shi[l][n] = hi; Slo[l][n] = lo;
    }
    __syncthreads();

    int lane = tid & 31, w = tid >> 5;
    int g = lane >> 2, tig = lane & 3;
    int m0 = (w & 3) * 16, n0 = (w >> 2) * 32;
    float acc[4][4];
#pragma unroll
    for (int i = 0; i < 4; i++)
#pragma unroll
        for (int q = 0; q < 4; q++) acc[i][q] = 0.f;
#pragma unroll
    for (int kt = 0; kt < 2; kt++) {
        int col = kt * 16 + 2 * tig;
        uint32_t ah[4], al[4];
        ldfragA<40>(ah, Chi, m0 + g, col);
        ldfragA<40>(al, Clo, m0 + g, col);
#pragma unroll
        for (int nt = 0; nt < 4; nt++) {
            uint32_t bh[2], bl[2];
            ldfragB<40>(bh, Shi, n0 + nt * 8 + g, col);
            ldfragB<40>(bl, Slo, n0 + nt * 8 + g, col);
            mma16816(acc[nt], ah, bh);
            mma16816(acc[nt], ah, bl);
            mma16816(acc[nt], al, bh);
        }
    }
    int l0 = m0 + g, l1 = l0 + 8;
    float el0 = __expf(acs[l0]), el1 = __expf(acs[l1]);
#pragma unroll
    for (int nt = 0; nt < 4; nt++) {
        int p0 = n0 + nt * 8 + 2 * tig;
        float* y0 = g_y + (size_t)(rowbase + l0) * DIN + h * HD + p0;
        float* y1 = g_y + (size_t)(rowbase + l1) * DIN + h * HD + p0;
        float2 v0 = *(float2*)y0, v1 = *(float2*)y1;
        v0.x += el0 * acc[nt][0]; v0.y += el0 * acc[nt][1];
        v1.x += el1 * acc[nt][2]; v1.y += el1 * acc[nt][3];
        *(float2*)y0 = v0;
        *(float2*)y1 = v1;
    }
}

// ---------------- gate + RMSNorm ----------------
__global__ __launch_bounds__(256) void gate_kernel(const float* __restrict__ rms_w)
{
    int row = blockIdx.x;
    int tid = threadIdx.x;
    const float* yr = g_y + (size_t)row * DIN;
    const float* zr = g_zx + (size_t)row * DPROJ;
    float v[8]; float s2 = 0.f;
#pragma unroll
    for (int i = 0; i < 8; i++) {
        int idx = tid + i * 256;
        float y = yr[idx];
        float z = zr[idx];
        y *= siluf(z);
        v[i] = y;
        s2 = fmaf(y, y, s2);
    }
    for (int o = 16; o; o >>= 1) s2 += __shfl_down_sync(0xffffffffu, s2, o);
    __shared__ float red[8];
    if ((tid & 31) == 0) red[tid >> 5] = s2;
    __syncthreads();
    if (tid == 0) {
        float t = 0.f;
        for (int i = 0; i < 8; i++) t += red[i];
        red[0] = rsqrtf(t / DIN + 1e-6f);
    }
    __syncthreads();
    float sc = red[0];
    size_t base = (size_t)row * DIN;
#pragma unroll
    for (int i = 0; i < 8; i++) {
        int idx = tid + i * 256;
        float f = v[i] * sc * rms_w[idx];
        unsigned short hi, lo;
        splitbf(f, hi, lo);
        g_Ahi[base + idx] = hi;
        g_Alo[base + idx] = lo;
    }
}

// ---------------- launch ----------------
extern "C" void kernel_launch(void* const* d_in, const int* in_sizes, int n_in,
                              void* d_out, int out_size)
{
    (void)in_sizes; (void)n_in; (void)out_size;
    const float* x       = (const float*)d_in[0];
    const float* ln_w    = (const float*)d_in[1];
    const float* ln_b    = (const float*)d_in[2];
    const float* W_in    = (const float*)d_in[3];
    const float* dt_bias = (const float*)d_in[4];
    const float* A_log   = (const float*)d_in[5];
    const float* Dv      = (const float*)d_in[6];
    const float* rms_w   = (const float*)d_in[7];
    const float* W_out   = (const float*)d_in[8];
    float* out = (float*)d_out;

    void *pzx, *pAhi, *pAlo, *pBhi, *pBlo;
    cudaGetSymbolAddress(&pzx,  g_zx);
    cudaGetSymbolAddress(&pAhi, g_Ahi);
    cudaGetSymbolAddress(&pAlo, g_Alo);
    cudaGetSymbolAddress(&pBhi, g_Bthi);
    cudaGetSymbolAddress(&pBlo, g_Btlo);

    static int attr_done = 0;
    if (!attr_done) {
        cudaFuncSetAttribute(mma_gemm, cudaFuncAttributeMaxDynamicSharedMemorySize, SMEM_GEMM);
        attr_done = 1;
    }

    ln_kernel<<<MROWS, 256>>>(x, ln_w, ln_b);
    cvtT_kernel<<<dim3(DIMX / 32, NPAD_IN / 32), dim3(32, 32)>>>(W_in, DIMX, DPROJ);
    mma_gemm<<<dim3(33, 128), 256, SMEM_GEMM>>>(
        (const unsigned short*)pAhi, (const unsigned short*)pAlo,
        (const unsigned short*)pBhi, (const unsigned short*)pBlo,
        (const float*)0, (float*)pzx, DPROJ, DIMX);
    bcrope_kernel<<<MROWS / 8, 256>>>();
    dtacs_kernel<<<4 * NC, 256>>>(dt_bias, A_log);
    score_kernel<<<4 * NC, 256>>>();
    chunk_kernel<<<4 * NC * NH, 256>>>(Dv);
    scan_kernel<<<4 * NH * 8, 256>>>();
    yo_kernel<<<4 * NC * NH, 256>>>();
    gate_kernel<<<MROWS, 256>>>(rms_w);
    cvtT_kernel<<<dim3(DIN / 32, DIMX / 32), dim3(32, 32)>>>(W_out, DIN, DIMX);
    mma_gemm<<<dim3(8, 128), 256, SMEM_GEMM>>>(
        (const unsigned short*)pAhi, (const unsigned short*)pAlo,
        (const unsigned short*)pBhi, (const unsigned short*)pBlo,
        x, out, DIMX, DIN);
}

// round 10
// speedup vs baseline: 2.0928x; 1.3071x over previous
#include <cuda_runtime.h>
#include <cuda_bf16.h>
#include <cuda_fp16.h>
#include <math.h>
#include <stdint.h>

#define MROWS 16384
#define DIMX 1024
#define DPROJ 4192
#define DIN 2048
#define NH 32
#define HD 64
#define DS 32
#define LSEQ 4096
#define NC 64
#define NPAD_IN 4224

// ---------------- scratch ----------------
__device__ float g_zx[(size_t)MROWS * DPROJ];
__device__ float g_Brot[(size_t)MROWS * DS];
__device__ float g_Crot[(size_t)MROWS * DS];
__device__ float g_states[(size_t)4 * NC * NH * HD * DS];
__device__ float g_stin[(size_t)4 * NC * NH * HD * DS];
__device__ float g_y[(size_t)MROWS * DIN];
__device__ float g_scores[(size_t)4 * NC * 64 * 64];
__device__ float g_dtv[(size_t)4 * NH * LSEQ];
__device__ float g_acs[(size_t)4 * NH * LSEQ];
__device__ unsigned short g_Ahf[(size_t)MROWS * DIN];      // fp16 bits (A for GEMMs)
__device__ unsigned short g_Bthi[(size_t)NPAD_IN * 1024];  // fp16 hi
__device__ unsigned short g_Btlo[(size_t)NPAD_IN * 1024];  // fp16 lo

__device__ __forceinline__ float siluf(float x) { return x / (1.f + __expf(-x)); }

// bf16 hi/lo split (SSD kernels)
__device__ __forceinline__ void splitbf(float f, unsigned short& hi, unsigned short& lo) {
    __nv_bfloat16 h = __float2bfloat16(f);
    float r = f - __bfloat162float(h);
    __nv_bfloat16 l = __float2bfloat16(r);
    hi = *reinterpret_cast<unsigned short*>(&h);
    lo = *reinterpret_cast<unsigned short*>(&l);
}
// fp16 hi/lo split (GEMM B)
__device__ __forceinline__ void splith(float f, unsigned short& hi, unsigned short& lo) {
    __half h = __float2half(f);
    float r = f - __half2float(h);
    __half l = __float2half(r);
    hi = *reinterpret_cast<unsigned short*>(&h);
    lo = *reinterpret_cast<unsigned short*>(&l);
}
__device__ __forceinline__ unsigned short f2h(float f) {
    __half h = __float2half(f);
    return *reinterpret_cast<unsigned short*>(&h);
}
__device__ __forceinline__ float bf2f(unsigned short u) {
    __nv_bfloat16 h = *reinterpret_cast<__nv_bfloat16*>(&u);
    return __bfloat162float(h);
}

__device__ __forceinline__ uint32_t smem_u32(const void* p) {
    uint32_t a;
    asm("{ .reg .u64 t; cvta.to.shared.u64 t, %1; cvt.u32.u64 %0, t; }" : "=r"(a) : "l"(p));
    return a;
}
__device__ __forceinline__ void cpasync16(uint32_t dst, const void* src) {
    asm volatile("cp.async.cg.shared.global [%0], [%1], 16;" :: "r"(dst), "l"(src) : "memory");
}
__device__ __forceinline__ void mma16816(float* c, const uint32_t* a, const uint32_t* b) {
    asm volatile(
        "mma.sync.aligned.m16n8k16.row.col.f32.bf16.bf16.f32 "
        "{%0,%1,%2,%3}, {%4,%5,%6,%7}, {%8,%9}, {%0,%1,%2,%3};\n"
        : "+f"(c[0]), "+f"(c[1]), "+f"(c[2]), "+f"(c[3])
        : "r"(a[0]), "r"(a[1]), "r"(a[2]), "r"(a[3]), "r"(b[0]), "r"(b[1]));
}
__device__ __forceinline__ void mma16816h(float* c, const uint32_t* a, const uint32_t* b) {
    asm volatile(
        "mma.sync.aligned.m16n8k16.row.col.f32.f16.f16.f32 "
        "{%0,%1,%2,%3}, {%4,%5,%6,%7}, {%8,%9}, {%0,%1,%2,%3};\n"
        : "+f"(c[0]), "+f"(c[1]), "+f"(c[2]), "+f"(c[3])
        : "r"(a[0]), "r"(a[1]), "r"(a[2]), "r"(a[3]), "r"(b[0]), "r"(b[1]));
}
template<int P>
__device__ __forceinline__ void ldfragA(uint32_t* a, const unsigned short (*S)[P], int row, int col) {
    a[0] = *(const uint32_t*)&S[row][col];
    a[1] = *(const uint32_t*)&S[row + 8][col];
    a[2] = *(const uint32_t*)&S[row][col + 8];
    a[3] = *(const uint32_t*)&S[row + 8][col + 8];
}
template<int P>
__device__ __forceinline__ void ldfragB(uint32_t* bb, const unsigned short (*S)[P], int row, int col) {
    bb[0] = *(const uint32_t*)&S[row][col];
    bb[1] = *(const uint32_t*)&S[row][col + 8];
}

// ---------------- LayerNorm -> fp16 A ----------------
__global__ __launch_bounds__(256) void ln_kernel(const float* __restrict__ x,
                                                 const float* __restrict__ w,
                                                 const float* __restrict__ b)
{
    int row = blockIdx.x;
    int tid = threadIdx.x;
    const float* xr = x + (size_t)row * DIMX;
    float4 v = *(const float4*)(xr + tid * 4);
    float s  = v.x + v.y + v.z + v.w;
    float s2 = v.x*v.x + v.y*v.y + v.z*v.z + v.w*v.w;
    for (int o = 16; o; o >>= 1) {
        s  += __shfl_down_sync(0xffffffffu, s,  o);
        s2 += __shfl_down_sync(0xffffffffu, s2, o);
    }
    __shared__ float ss[8], ss2[8];
    if ((tid & 31) == 0) { ss[tid >> 5] = s; ss2[tid >> 5] = s2; }
    __syncthreads();
    if (tid == 0) {
        float t = 0.f, t2 = 0.f;
        for (int i = 0; i < 8; i++) { t += ss[i]; t2 += ss2[i]; }
        float mu = t / DIMX;
        ss[0]  = mu;
        ss2[0] = rsqrtf(t2 / DIMX - mu * mu + 1e-6f);
    }
    __syncthreads();
    float mu = ss[0], inv = ss2[0];
    int i0 = tid * 4;
    float4 wv = *(const float4*)(w + i0);
    float4 bv = *(const float4*)(b + i0);
    ushort4 hv;
    hv.x = f2h((v.x - mu) * inv * wv.x + bv.x);
    hv.y = f2h((v.y - mu) * inv * wv.y + bv.y);
    hv.z = f2h((v.z - mu) * inv * wv.z + bv.z);
    hv.w = f2h((v.w - mu) * inv * wv.w + bv.w);
    *(ushort4*)(g_Ahf + (size_t)row * DIMX + i0) = hv;
}

// ---------------- W[K,N] -> Bt[n][k] fp16 hi/lo ----------------
__global__ __launch_bounds__(1024) void cvtT_kernel(const float* __restrict__ W, int K, int N)
{
    __shared__ float t[32][33];
    int k0 = blockIdx.x * 32, n0 = blockIdx.y * 32;
    int tx = threadIdx.x, ty = threadIdx.y;
    int n = n0 + tx;
    t[ty][tx] = (n < N) ? W[(size_t)(k0 + ty) * N + n] : 0.f;
    __syncthreads();
    float v = t[tx][ty];
    unsigned short hi, lo;
    splith(v, hi, lo);
    size_t o = (size_t)(n0 + ty) * K + k0 + tx;
    g_Bthi[o] = hi;
    g_Btlo[o] = lo;
}

// ---------------- mma.sync fp16 GEMM, 2-pass (A plain, B hi/lo); 2 CTAs/SM ----------------
#define KSTAGE 30720
#define SMEM_GEMM (2 * KSTAGE)
__global__ __launch_bounds__(256, 2) void mma_gemm(
    const unsigned short* __restrict__ A,
    const unsigned short* __restrict__ Bhi, const unsigned short* __restrict__ Blo,
    const float* __restrict__ R, float* __restrict__ C, int N, int K)
{
    extern __shared__ char sm[];
    int tid = threadIdx.x, lane = tid & 31, wid = tid >> 5;
    int col0 = blockIdx.x * 128, row0 = blockIdx.y * 128;
    int g = lane >> 2, tig = lane & 3;
    int m0 = (wid >> 2) * 64, n0 = (wid & 3) * 32;
    uint32_t sb = smem_u32(sm);

    float acc[4][4][4];
#pragma unroll
    for (int i = 0; i < 4; i++)
#pragma unroll
        for (int j = 0; j < 4; j++)
#pragma unroll
            for (int q = 0; q < 4; q++) acc[i][j][q] = 0.f;

    const unsigned short* srcs[3] = {A, Bhi, Blo};
    int rbs[3] = {row0, col0, col0};

    int KT = K >> 5;
    {
#pragma unroll
        for (int t = 0; t < 3; t++) {
#pragma unroll
            for (int cc = 0; cc < 2; cc++) {
                int chunk = tid + cc * 256;
                int row = chunk >> 2, c4 = chunk & 3;
                const void* src = srcs[t] + (size_t)(rbs[t] + row) * K + c4 * 8;
                cpasync16(sb + t * 10240 + row * 80 + c4 * 16, src);
            }
        }
        asm volatile("cp.async.commit_group;" ::: "memory");
    }

    for (int kt = 0; kt < KT; kt++) {
        if (kt + 1 < KT) {
            int buf = (kt + 1) & 1;
#pragma unroll
            for (int t = 0; t < 3; t++) {
#pragma unroll
                for (int cc = 0; cc < 2; cc++) {
                    int chunk = tid + cc * 256;
                    int row = chunk >> 2, c4 = chunk & 3;
                    const void* src = srcs[t] + (size_t)(rbs[t] + row) * K + (kt + 1) * 32 + c4 * 8;
                    cpasync16(sb + buf * KSTAGE + t * 10240 + row * 80 + c4 * 16, src);
                }
            }
            asm volatile("cp.async.commit_group;" ::: "memory");
            asm volatile("cp.async.wait_group 1;" ::: "memory");
        } else {
            asm volatile("cp.async.wait_group 0;" ::: "memory");
        }
        __syncthreads();

        const char* stb = sm + (kt & 1) * KSTAGE;
#pragma unroll
        for (int ks = 0; ks < 2; ks++) {
            int wb = (ks * 8 + tig) * 4;
            uint32_t bh[4][2], bl[4][2];
#pragma unroll
            for (int nt = 0; nt < 4; nt++) {
                const char* pb = stb + 10240 + (n0 + nt * 8 + g) * 80 + wb;
                bh[nt][0] = *(const uint32_t*)(pb);
                bh[nt][1] = *(const uint32_t*)(pb + 16);
                bl[nt][0] = *(const uint32_t*)(pb + 10240);
                bl[nt][1] = *(const uint32_t*)(pb + 10240 + 16);
            }
#pragma unroll
            for (int mt = 0; mt < 4; mt++) {
                const char* pa = stb + (m0 + mt * 16 + g) * 80 + wb;
                uint32_t ah[4];
                ah[0] = *(const uint32_t*)(pa);
                ah[1] = *(const uint32_t*)(pa + 8 * 80);
                ah[2] = *(const uint32_t*)(pa + 16);
                ah[3] = *(const uint32_t*)(pa + 8 * 80 + 16);
#pragma unroll
                for (int nt = 0; nt < 4; nt++) {
                    mma16816h(acc[mt][nt], ah, bh[nt]);
                    mma16816h(acc[mt][nt], ah, bl[nt]);
                }
            }
        }
        __syncthreads();
    }

#pragma unroll
    for (int mt = 0; mt < 4; mt++) {
        int r0i = row0 + m0 + mt * 16 + g;
#pragma unroll
        for (int nt = 0; nt < 4; nt++) {
            int cc = col0 + n0 + nt * 8 + tig * 2;
            if (cc < N) {
                float* p0 = C + (size_t)r0i * N + cc;
                float* p1 = C + (size_t)(r0i + 8) * N + cc;
                float2 v0 = make_float2(acc[mt][nt][0], acc[mt][nt][1]);
                float2 v1 = make_float2(acc[mt][nt][2], acc[mt][nt][3]);
                if (R) {
                    const float* q0 = R + (size_t)r0i * N + cc;
                    const float* q1 = R + (size_t)(r0i + 8) * N + cc;
                    v0.x += q0[0]; v0.y += q0[1];
                    v1.x += q1[0]; v1.y += q1[1];
                }
                *(float2*)p0 = v0;
                *(float2*)p1 = v1;
            }
        }
    }
}

// ---------------- silu + RoPE ----------------
__global__ __launch_bounds__(256) void bcrope_kernel()
{
    int tid = threadIdx.x;
    int r8 = tid >> 5, n = tid & 31;
    int row = blockIdx.x * 8 + r8;
    int t = row & (LSEQ - 1);
    const float* base = g_zx + (size_t)row * DPROJ;
    float bo, co;
    if (n < 16) {
        int j = n >> 1;
        double invd = exp(-((double)j) * (log(10000.0) / 8.0));
        float inv = (float)invd;
        float ang = (float)t * inv;
        float sn, cs;
        sincosf(ang, &sn, &cs);
        float b1 = siluf(base[4096 + 2 * j]);
        float b2 = siluf(base[4096 + 2 * j + 1]);
        float c1 = siluf(base[4128 + 2 * j]);
        float c2 = siluf(base[4128 + 2 * j + 1]);
        if (n & 1) { bo = b1 * sn + b2 * cs; co = c1 * sn + c2 * cs; }
        else       { bo = b1 * cs - b2 * sn; co = c1 * cs - c2 * sn; }
    } else {
        bo = siluf(base[4096 + n]);
        co = siluf(base[4128 + n]);
    }
    g_Brot[(size_t)row * DS + n] = bo;
    g_Crot[(size_t)row * DS + n] = co;
}

// ---------------- dt + A-cumsum precompute ----------------
__global__ __launch_bounds__(256) void dtacs_kernel(const float* __restrict__ dt_bias,
                                                    const float* __restrict__ A_log)
{
    int bc = blockIdx.x;
    int b = bc >> 6, c = bc & 63;
    int warp = threadIdx.x >> 5, lane = threadIdx.x & 31;
    int rowbase = b * LSEQ + c * 64;
#pragma unroll
    for (int i = 0; i < 4; i++) {
        int h = warp * 4 + i;
        float A = -__expf(A_log[h]);
        float bias = dt_bias[h];
        float raw0 = g_zx[(size_t)(rowbase + lane) * DPROJ + 4160 + h] + bias;
        float raw1 = g_zx[(size_t)(rowbase + 32 + lane) * DPROJ + 4160 + h] + bias;
        float dt0 = (raw0 > 20.f) ? raw0 : log1pf(__expf(raw0));
        float dt1 = (raw1 > 20.f) ? raw1 : log1pf(__expf(raw1));
        float a0 = dt0 * A, a1 = dt1 * A;
#pragma unroll
        for (int o = 1; o < 32; o <<= 1) {
            float t = __shfl_up_sync(0xffffffffu, a0, o);
            if (lane >= o) a0 += t;
        }
#pragma unroll
        for (int o = 1; o < 32; o <<= 1) {
            float t = __shfl_up_sync(0xffffffffu, a1, o);
            if (lane >= o) a1 += t;
        }
        a1 += __shfl_sync(0xffffffffu, a0, 31);
        size_t base = ((size_t)(b * NH + h)) * LSEQ + c * 64;
        g_dtv[base + lane] = dt0;      g_dtv[base + 32 + lane] = dt1;
        g_acs[base + lane] = a0;       g_acs[base + 32 + lane] = a1;
    }
}

// ---------------- scores: per (b,c), masked C.B^T ----------------
__global__ __launch_bounds__(256) void score_kernel()
{
    int bc = blockIdx.x;
    int b = bc >> 6, c = bc & 63;
    __shared__ float Cs[64][33], Bsm[64][33];
    int tid = threadIdx.x;
    int rowbase = b * LSEQ + c * 64;
    for (int i = tid; i < 64 * 32; i += 256) {
        int l = i >> 5, n = i & 31;
        Bsm[l][n] = g_Brot[(size_t)(rowbase + l) * DS + n];
        Cs[l][n]  = g_Crot[(size_t)(rowbase + l) * DS + n];
    }
    __syncthreads();
    int l = tid >> 2, sq = tid & 3;
    float cr[32];
#pragma unroll
    for (int n = 0; n < 32; n++) cr[n] = Cs[l][n];
    float out[16];
#pragma unroll
    for (int k = 0; k < 16; k++) {
        int s = sq * 16 + k;
        float d = 0.f;
        if (s <= l) {
#pragma unroll
            for (int n = 0; n < 32; n++) d = fmaf(cr[n], Bsm[s][n], d);
        }
        out[k] = d;
    }
    float* dst = g_scores + (size_t)bc * 4096 + l * 64 + sq * 16;
#pragma unroll
    for (int k = 0; k < 16; k += 4)
        *(float4*)(dst + k) = make_float4(out[k], out[k + 1], out[k + 2], out[k + 3]);
}

// ---------------- SSD intra-chunk: tensor-core Yd + states (bf16 3-pass) ----------------
__global__ __launch_bounds__(256) void chunk_kernel(const float* __restrict__ Dv)
{
    int blk = blockIdx.x;
    int h = blk & 31; int bcid = blk >> 5; int c = bcid & 63; int b = bcid >> 6;
    __shared__ unsigned short Mhi[64][72], Mlo[64][72];
    __shared__ unsigned short XThi[64][72], XTlo[64][72];   // [p][l]
    __shared__ unsigned short BwThi[32][72], BwTlo[32][72]; // [n][l]
    __shared__ float acs[64], dtv[64], wvv[64];
    int tid = threadIdx.x;
    int rowbase = b * LSEQ + c * 64;

    if (tid < 64) {
        size_t dbase = ((size_t)(b * NH + h)) * LSEQ + c * 64;
        dtv[tid] = g_dtv[dbase + tid];
        acs[tid] = g_acs[dbase + tid];
    }
    __syncthreads();
    if (tid < 64) wvv[tid] = dtv[tid] * __expf(acs[63] - acs[tid]);
    for (int i = tid; i < 4096; i += 256) {
        int l = i >> 6, p = i & 63;
        float v = siluf(g_zx[(size_t)(rowbase + l) * DPROJ + 2048 + h * 64 + p]);
        unsigned short hi, lo; splitbf(v, hi, lo);
        XThi[p][l] = hi; XTlo[p][l] = lo;
    }
    const float* psrc = g_scores + (size_t)(b * NC + c) * 4096;
    for (int i = tid; i < 4096; i += 256) {
        int l = i >> 6, s = i & 63;
        float m = 0.f;
        if (s <= l) m = psrc[i] * __expf(acs[l] - acs[s]) * dtv[s];
        unsigned short hi, lo; splitbf(m, hi, lo);
        Mhi[l][s] = hi; Mlo[l][s] = lo;
    }
    __syncthreads();   // wvv ready
    for (int i = tid; i < 2048; i += 256) {
        int l = i >> 5, n = i & 31;
        float v = g_Brot[(size_t)(rowbase + l) * DS + n] * wvv[l];
        unsigned short hi, lo; splitbf(v, hi, lo);
        BwThi[n][l] = hi; BwTlo[n][l] = lo;
    }
    __syncthreads();

    int lane = tid & 31, w = tid >> 5;
    int g = lane >> 2, tig = lane & 3;

    // ---- Yd = M @ X (64x64x64), 3-pass ----
    {
        int m0 = (w & 3) * 16, n0 = (w >> 2) * 32;
        float acc[4][4];
#pragma unroll
        for (int i = 0; i < 4; i++)
#pragma unroll
            for (int q = 0; q < 4; q++) acc[i][q] = 0.f;
#pragma unroll
        for (int kt = 0; kt < 4; kt++) {
            int col = kt * 16 + 2 * tig;
            uint32_t ah[4], al[4];
            ldfragA<72>(ah, Mhi, m0 + g, col);
            ldfragA<72>(al, Mlo, m0 + g, col);
#pragma unroll
            for (int nt = 0; nt < 4; nt++) {
                uint32_t bh[2], bl[2];
                ldfragB<72>(bh, XThi, n0 + nt * 8 + g, col);
                ldfragB<72>(bl, XTlo, n0 + nt * 8 + g, col);
                mma16816(acc[nt], ah, bh);
                mma16816(acc[nt], ah, bl);
                mma16816(acc[nt], al, bh);
            }
        }
        float Dh = Dv[h];
#pragma unroll
        for (int nt = 0; nt < 4; nt++) {
            int p0 = n0 + nt * 8 + 2 * tig;
            int l0 = m0 + g, l1 = l0 + 8;
            float x00 = bf2f(XThi[p0][l0]) + bf2f(XTlo[p0][l0]);
            float x01 = bf2f(XThi[p0 + 1][l0]) + bf2f(XTlo[p0 + 1][l0]);
            float x10 = bf2f(XThi[p0][l1]) + bf2f(XTlo[p0][l1]);
            float x11 = bf2f(XThi[p0 + 1][l1]) + bf2f(XTlo[p0 + 1][l1]);
            float* y0 = g_y + (size_t)(rowbase + l0) * DIN + h * HD + p0;
            float* y1 = g_y + (size_t)(rowbase + l1) * DIN + h * HD + p0;
            *(float2*)y0 = make_float2(acc[nt][0] + Dh * x00, acc[nt][1] + Dh * x01);
            *(float2*)y1 = make_float2(acc[nt][2] + Dh * x10, acc[nt][3] + Dh * x11);
        }
    }

    // ---- states = X^T @ Bw (64x32x64), 3-pass ----
    {
        int m0 = (w & 3) * 16;       // p
        int n0 = (w >> 2) * 16;      // n
        float acc[2][4];
#pragma unroll
        for (int i = 0; i < 2; i++)
#pragma unroll
            for (int q = 0; q < 4; q++) acc[i][q] = 0.f;
#pragma unroll
        for (int kt = 0; kt < 4; kt++) {
            int col = kt * 16 + 2 * tig;
            uint32_t ah[4], al[4];
            ldfragA<72>(ah, XThi, m0 + g, col);
            ldfragA<72>(al, XTlo, m0 + g, col);
#pragma unroll
            for (int nt = 0; nt < 2; nt++) {
                uint32_t bh[2], bl[2];
                ldfragB<72>(bh, BwThi, n0 + nt * 8 + g, col);
                ldfragB<72>(bl, BwTlo, n0 + nt * 8 + g, col);
                mma16816(acc[nt], ah, bh);
                mma16816(acc[nt], ah, bl);
                mma16816(acc[nt], al, bh);
            }
        }
        size_t sbase = ((size_t)((b * NC + c) * NH + h)) * (HD * DS);
#pragma unroll
        for (int nt = 0; nt < 2; nt++) {
            int nn = n0 + nt * 8 + 2 * tig;
            int p0 = m0 + g, p1 = p0 + 8;
            *(float2*)&g_states[sbase + p0 * DS + nn] = make_float2(acc[nt][0], acc[nt][1]);
            *(float2*)&g_states[sbase + p1 * DS + nn] = make_float2(acc[nt][2], acc[nt][3]);
        }
    }
}

// ---------------- inter-chunk scan: 1 elem/thread, prefetched ----------------
__global__ __launch_bounds__(256) void scan_kernel()
{
    int bh = blockIdx.x >> 3;
    int e = (blockIdx.x & 7) * 256 + threadIdx.x;
    int b = bh >> 5, h = bh & 31;
    __shared__ float ec[64];
    if (threadIdx.x < 64) {
        float cs = g_acs[(size_t)bh * LSEQ + threadIdx.x * 64 + 63];
        ec[threadIdx.x] = __expf(cs);
    }
    __syncthreads();
    size_t stride = (size_t)NH * HD * DS;
    size_t base = ((size_t)(b * NC) * NH + h) * (HD * DS) + e;
    float S = 0.f;
    float nxt = g_states[base];
#pragma unroll 4
    for (int c = 0; c < NC; c++) {
        g_stin[base] = S;
        float cur = nxt;
        if (c + 1 < NC) nxt = g_states[base + stride];
        S = fmaf(S, ec[c], cur);
        base += stride;
    }
}

// ---------------- Yo = C @ S^T (64x64x32), bf16 3-pass, y += exp(acs)*Yo ----------------
__global__ __launch_bounds__(256) void yo_kernel()
{
    int blk = blockIdx.x;
    int h = blk & 31; int bcid = blk >> 5; int c = bcid & 63; int b = bcid >> 6;
    __shared__ unsigned short Chi[64][40], Clo[64][40];
    __shared__ unsigned short Shi[64][40], Slo[64][40];
    __shared__ float acs[64];
    int tid = threadIdx.x;
    int rowbase = b * LSEQ + c * 64;

    if (tid < 64) {
        size_t dbase = ((size_t)(b * NH + h)) * LSEQ + c * 64;
        acs[tid] = g_acs[dbase + tid];
    }
    size_t sbase = ((size_t)((b * NC + c) * NH + h)) * (HD * DS);
    for (int i = tid; i < 2048; i += 256) {
        int l = i >> 5, n = i & 31;
        unsigned short hi, lo;
        splitbf(g_Crot[(size_t)(rowbase + l) * DS + n], hi, lo);
        Chi[l][n] = hi; Clo[l][n] = lo;
        splitbf(g_stin[sbase + i], hi, lo);
        Shi[l][n] = hi; Slo[l][n] = lo;
    }
    __syncthreads();

    int lane = tid & 31, w = tid >> 5;
    int g = lane >> 2, tig = lane & 3;
    int m0 = (w & 3) * 16, n0 = (w >> 2) * 32;
    float acc[4][4];
#pragma unroll
    for (int i = 0; i < 4; i++)
#pragma unroll
        for (int q = 0; q < 4; q++) acc[i][q] = 0.f;
#pragma unroll
    for (int kt = 0; kt < 2; kt++) {
        int col = kt * 16 + 2 * tig;
        uint32_t ah[4], al[4];
        ldfragA<40>(ah, Chi, m0 + g, col);
        ldfragA<40>(al, Clo, m0 + g, col);
#pragma unroll
        for (int nt = 0; nt < 4; nt++) {
            uint32_t bh[2], bl[2];
            ldfragB<40>(bh, Shi, n0 + nt * 8 + g, col);
            ldfragB<40>(bl, Slo, n0 + nt * 8 + g, col);
            mma16816(acc[nt], ah, bh);
            mma16816(acc[nt], ah, bl);
            mma16816(acc[nt], al, bh);
        }
    }
    int l0 = m0 + g, l1 = l0 + 8;
    float el0 = __expf(acs[l0]), el1 = __expf(acs[l1]);
#pragma unroll
    for (int nt = 0; nt < 4; nt++) {
        int p0 = n0 + nt * 8 + 2 * tig;
        float* y0 = g_y + (size_t)(rowbase + l0) * DIN + h * HD + p0;
        float* y1 = g_y + (size_t)(rowbase + l1) * DIN + h * HD + p0;
        float2 v0 = *(float2*)y0, v1 = *(float2*)y1;
        v0.x += el0 * acc[nt][0]; v0.y += el0 * acc[nt][1];
        v1.x += el1 * acc[nt][2]; v1.y += el1 * acc[nt][3];
        *(float2*)y0 = v0;
        *(float2*)y1 = v1;
    }
}

// ---------------- gate + RMSNorm -> fp16 A ----------------
__global__ __launch_bounds__(256) void gate_kernel(const float* __restrict__ rms_w)
{
    int row = blockIdx.x;
    int tid = threadIdx.x;
    const float* yr = g_y + (size_t)row * DIN;
    const float* zr = g_zx + (size_t)row * DPROJ;
    float v[8]; float s2 = 0.f;
#pragma unroll
    for (int i = 0; i < 8; i++) {
        int idx = tid + i * 256;
        float y = yr[idx];
        float z = zr[idx];
        y *= siluf(z);
        v[i] = y;
        s2 = fmaf(y, y, s2);
    }
    for (int o = 16; o; o >>= 1) s2 += __shfl_down_sync(0xffffffffu, s2, o);
    __shared__ float red[8];
    if ((tid & 31) == 0) red[tid >> 5] = s2;
    __syncthreads();
    if (tid == 0) {
        float t = 0.f;
        for (int i = 0; i < 8; i++) t += red[i];
        red[0] = rsqrtf(t / DIN + 1e-6f);
    }
    __syncthreads();
    float sc = red[0];
    size_t base = (size_t)row * DIN;
#pragma unroll
    for (int i = 0; i < 8; i++) {
        int idx = tid + i * 256;
        g_Ahf[base + idx] = f2h(v[i] * sc * rms_w[idx]);
    }
}

// ---------------- launch ----------------
extern "C" void kernel_launch(void* const* d_in, const int* in_sizes, int n_in,
                              void* d_out, int out_size)
{
    (void)in_sizes; (void)n_in; (void)out_size;
    const float* x       = (const float*)d_in[0];
    const float* ln_w    = (const float*)d_in[1];
    const float* ln_b    = (const float*)d_in[2];
    const float* W_in    = (const float*)d_in[3];
    const float* dt_bias = (const float*)d_in[4];
    const float* A_log   = (const float*)d_in[5];
    const float* Dv      = (const float*)d_in[6];
    const float* rms_w   = (const float*)d_in[7];
    const float* W_out   = (const float*)d_in[8];
    float* out = (float*)d_out;

    void *pzx, *pA, *pBhi, *pBlo;
    cudaGetSymbolAddress(&pzx, g_zx);
    cudaGetSymbolAddress(&pA,  g_Ahf);
    cudaGetSymbolAddress(&pBhi, g_Bthi);
    cudaGetSymbolAddress(&pBlo, g_Btlo);

    static int attr_done = 0;
    if (!attr_done) {
        cudaFuncSetAttribute(mma_gemm, cudaFuncAttributeMaxDynamicSharedMemorySize, SMEM_GEMM);
        attr_done = 1;
    }

    ln_kernel<<<MROWS, 256>>>(x, ln_w, ln_b);
    cvtT_kernel<<<dim3(DIMX / 32, NPAD_IN / 32), dim3(32, 32)>>>(W_in, DIMX, DPROJ);
    mma_gemm<<<dim3(33, 128), 256, SMEM_GEMM>>>(
        (const unsigned short*)pA,
        (const unsigned short*)pBhi, (const unsigned short*)pBlo,
        (const float*)0, (float*)pzx, DPROJ, DIMX);
    bcrope_kernel<<<MROWS / 8, 256>>>();
    dtacs_kernel<<<4 * NC, 256>>>(dt_bias, A_log);
    score_kernel<<<4 * NC, 256>>>();
    chunk_kernel<<<4 * NC * NH, 256>>>(Dv);
    scan_kernel<<<4 * NH * 8, 256>>>();
    yo_kernel<<<4 * NC * NH, 256>>>();
    gate_kernel<<<MROWS, 256>>>(rms_w);
    cvtT_kernel<<<dim3(DIN / 32, DIMX / 32), dim3(32, 32)>>>(W_out, DIN, DIMX);
    mma_gemm<<<dim3(8, 128), 256, SMEM_GEMM>>>(
        (const unsigned short*)pA,
        (const unsigned short*)pBhi, (const unsigned short*)pBlo,
        x, out, DIMX, DIN);
}

// round 11
// speedup vs baseline: 2.1918x; 1.0473x over previous
#include <cuda_runtime.h>
#include <cuda_bf16.h>
#include <cuda_fp16.h>
#include <math.h>
#include <stdint.h>

#define MROWS 16384
#define DIMX 1024
#define DPROJ 4192
#define DIN 2048
#define NH 32
#define HD 64
#define DS 32
#define LSEQ 4096
#define NC 64
#define NPAD_IN 4224

// ---------------- scratch ----------------
__device__ float g_zx[(size_t)MROWS * DPROJ];
__device__ float g_Brot[(size_t)MROWS * DS];
__device__ float g_Crot[(size_t)MROWS * DS];
__device__ float g_states[(size_t)4 * NC * NH * HD * DS];
__device__ float g_stin[(size_t)4 * NC * NH * HD * DS];
__device__ float g_y[(size_t)MROWS * DIN];
__device__ float g_scores[(size_t)4 * NC * 64 * 64];
__device__ float g_dtv[(size_t)4 * NH * LSEQ];
__device__ float g_acs[(size_t)4 * NH * LSEQ];
__device__ unsigned short g_Ahf[(size_t)MROWS * DIN];      // fp16 bits (A for GEMMs)
__device__ unsigned short g_Bthi[(size_t)NPAD_IN * 1024];  // fp16 hi
__device__ unsigned short g_Btlo[(size_t)NPAD_IN * 1024];  // fp16 lo

__device__ __forceinline__ float siluf(float x) { return x / (1.f + __expf(-x)); }

// fp16 hi/lo split
__device__ __forceinline__ void splith(float f, unsigned short& hi, unsigned short& lo) {
    __half h = __float2half(f);
    float r = f - __half2float(h);
    __half l = __float2half(r);
    hi = *reinterpret_cast<unsigned short*>(&h);
    lo = *reinterpret_cast<unsigned short*>(&l);
}
__device__ __forceinline__ unsigned short f2h(float f) {
    __half h = __float2half(f);
    return *reinterpret_cast<unsigned short*>(&h);
}
__device__ __forceinline__ float h2f(unsigned short u) {
    __half h = *reinterpret_cast<__half*>(&u);
    return __half2float(h);
}

__device__ __forceinline__ uint32_t smem_u32(const void* p) {
    uint32_t a;
    asm("{ .reg .u64 t; cvta.to.shared.u64 t, %1; cvt.u32.u64 %0, t; }" : "=r"(a) : "l"(p));
    return a;
}
__device__ __forceinline__ void cpasync16(uint32_t dst, const void* src) {
    asm volatile("cp.async.cg.shared.global [%0], [%1], 16;" :: "r"(dst), "l"(src) : "memory");
}
__device__ __forceinline__ void mma16816h(float* c, const uint32_t* a, const uint32_t* b) {
    asm volatile(
        "mma.sync.aligned.m16n8k16.row.col.f32.f16.f16.f32 "
        "{%0,%1,%2,%3}, {%4,%5,%6,%7}, {%8,%9}, {%0,%1,%2,%3};\n"
        : "+f"(c[0]), "+f"(c[1]), "+f"(c[2]), "+f"(c[3])
        : "r"(a[0]), "r"(a[1]), "r"(a[2]), "r"(a[3]), "r"(b[0]), "r"(b[1]));
}
template<int P>
__device__ __forceinline__ void ldfragA(uint32_t* a, const unsigned short (*S)[P], int row, int col) {
    a[0] = *(const uint32_t*)&S[row][col];
    a[1] = *(const uint32_t*)&S[row + 8][col];
    a[2] = *(const uint32_t*)&S[row][col + 8];
    a[3] = *(const uint32_t*)&S[row + 8][col + 8];
}
template<int P>
__device__ __forceinline__ void ldfragB(uint32_t* bb, const unsigned short (*S)[P], int row, int col) {
    bb[0] = *(const uint32_t*)&S[row][col];
    bb[1] = *(const uint32_t*)&S[row][col + 8];
}

// ---------------- LayerNorm -> fp16 A ----------------
__global__ __launch_bounds__(256) void ln_kernel(const float* __restrict__ x,
                                                 const float* __restrict__ w,
                                                 const float* __restrict__ b)
{
    int row = blockIdx.x;
    int tid = threadIdx.x;
    const float* xr = x + (size_t)row * DIMX;
    float4 v = *(const float4*)(xr + tid * 4);
    float s  = v.x + v.y + v.z + v.w;
    float s2 = v.x*v.x + v.y*v.y + v.z*v.z + v.w*v.w;
    for (int o = 16; o; o >>= 1) {
        s  += __shfl_down_sync(0xffffffffu, s,  o);
        s2 += __shfl_down_sync(0xffffffffu, s2, o);
    }
    __shared__ float ss[8], ss2[8];
    if ((tid & 31) == 0) { ss[tid >> 5] = s; ss2[tid >> 5] = s2; }
    __syncthreads();
    if (tid == 0) {
        float t = 0.f, t2 = 0.f;
        for (int i = 0; i < 8; i++) { t += ss[i]; t2 += ss2[i]; }
        float mu = t / DIMX;
        ss[0]  = mu;
        ss2[0] = rsqrtf(t2 / DIMX - mu * mu + 1e-6f);
    }
    __syncthreads();
    float mu = ss[0], inv = ss2[0];
    int i0 = tid * 4;
    float4 wv = *(const float4*)(w + i0);
    float4 bv = *(const float4*)(b + i0);
    ushort4 hv;
    hv.x = f2h((v.x - mu) * inv * wv.x + bv.x);
    hv.y = f2h((v.y - mu) * inv * wv.y + bv.y);
    hv.z = f2h((v.z - mu) * inv * wv.z + bv.z);
    hv.w = f2h((v.w - mu) * inv * wv.w + bv.w);
    *(ushort4*)(g_Ahf + (size_t)row * DIMX + i0) = hv;
}

// ---------------- W[K,N] -> Bt[n][k] fp16 hi/lo ----------------
__global__ __launch_bounds__(1024) void cvtT_kernel(const float* __restrict__ W, int K, int N)
{
    __shared__ float t[32][33];
    int k0 = blockIdx.x * 32, n0 = blockIdx.y * 32;
    int tx = threadIdx.x, ty = threadIdx.y;
    int n = n0 + tx;
    t[ty][tx] = (n < N) ? W[(size_t)(k0 + ty) * N + n] : 0.f;
    __syncthreads();
    float v = t[tx][ty];
    unsigned short hi, lo;
    splith(v, hi, lo);
    size_t o = (size_t)(n0 + ty) * K + k0 + tx;
    g_Bthi[o] = hi;
    g_Btlo[o] = lo;
}

// ---------------- mma.sync fp16 GEMM, 2-pass; 2 CTAs/SM ----------------
#define KSTAGE 30720
#define SMEM_GEMM (2 * KSTAGE)
__global__ __launch_bounds__(256, 2) void mma_gemm(
    const unsigned short* __restrict__ A,
    const unsigned short* __restrict__ Bhi, const unsigned short* __restrict__ Blo,
    const float* __restrict__ R, float* __restrict__ C, int N, int K)
{
    extern __shared__ char sm[];
    int tid = threadIdx.x, lane = tid & 31, wid = tid >> 5;
    int col0 = blockIdx.x * 128, row0 = blockIdx.y * 128;
    int g = lane >> 2, tig = lane & 3;
    int m0 = (wid >> 2) * 64, n0 = (wid & 3) * 32;
    uint32_t sb = smem_u32(sm);

    float acc[4][4][4];
#pragma unroll
    for (int i = 0; i < 4; i++)
#pragma unroll
        for (int j = 0; j < 4; j++)
#pragma unroll
            for (int q = 0; q < 4; q++) acc[i][j][q] = 0.f;

    const unsigned short* srcs[3] = {A, Bhi, Blo};
    int rbs[3] = {row0, col0, col0};

    int KT = K >> 5;
    {
#pragma unroll
        for (int t = 0; t < 3; t++) {
#pragma unroll
            for (int cc = 0; cc < 2; cc++) {
                int chunk = tid + cc * 256;
                int row = chunk >> 2, c4 = chunk & 3;
                const void* src = srcs[t] + (size_t)(rbs[t] + row) * K + c4 * 8;
                cpasync16(sb + t * 10240 + row * 80 + c4 * 16, src);
            }
        }
        asm volatile("cp.async.commit_group;" ::: "memory");
    }

    for (int kt = 0; kt < KT; kt++) {
        if (kt + 1 < KT) {
            int buf = (kt + 1) & 1;
#pragma unroll
            for (int t = 0; t < 3; t++) {
#pragma unroll
                for (int cc = 0; cc < 2; cc++) {
                    int chunk = tid + cc * 256;
                    int row = chunk >> 2, c4 = chunk & 3;
                    const void* src = srcs[t] + (size_t)(rbs[t] + row) * K + (kt + 1) * 32 + c4 * 8;
                    cpasync16(sb + buf * KSTAGE + t * 10240 + row * 80 + c4 * 16, src);
                }
            }
            asm volatile("cp.async.commit_group;" ::: "memory");
            asm volatile("cp.async.wait_group 1;" ::: "memory");
        } else {
            asm volatile("cp.async.wait_group 0;" ::: "memory");
        }
        __syncthreads();

        const char* stb = sm + (kt & 1) * KSTAGE;
#pragma unroll
        for (int ks = 0; ks < 2; ks++) {
            int wb = (ks * 8 + tig) * 4;
            uint32_t bh[4][2], bl[4][2];
#pragma unroll
            for (int nt = 0; nt < 4; nt++) {
                const char* pb = stb + 10240 + (n0 + nt * 8 + g) * 80 + wb;
                bh[nt][0] = *(const uint32_t*)(pb);
                bh[nt][1] = *(const uint32_t*)(pb + 16);
                bl[nt][0] = *(const uint32_t*)(pb + 10240);
                bl[nt][1] = *(const uint32_t*)(pb + 10240 + 16);
            }
#pragma unroll
            for (int mt = 0; mt < 4; mt++) {
                const char* pa = stb + (m0 + mt * 16 + g) * 80 + wb;
                uint32_t ah[4];
                ah[0] = *(const uint32_t*)(pa);
                ah[1] = *(const uint32_t*)(pa + 8 * 80);
                ah[2] = *(const uint32_t*)(pa + 16);
                ah[3] = *(const uint32_t*)(pa + 8 * 80 + 16);
#pragma unroll
                for (int nt = 0; nt < 4; nt++) {
                    mma16816h(acc[mt][nt], ah, bh[nt]);
                    mma16816h(acc[mt][nt], ah, bl[nt]);
                }
            }
        }
        __syncthreads();
    }

#pragma unroll
    for (int mt = 0; mt < 4; mt++) {
        int r0i = row0 + m0 + mt * 16 + g;
#pragma unroll
        for (int nt = 0; nt < 4; nt++) {
            int cc = col0 + n0 + nt * 8 + tig * 2;
            if (cc < N) {
                float* p0 = C + (size_t)r0i * N + cc;
                float* p1 = C + (size_t)(r0i + 8) * N + cc;
                float2 v0 = make_float2(acc[mt][nt][0], acc[mt][nt][1]);
                float2 v1 = make_float2(acc[mt][nt][2], acc[mt][nt][3]);
                if (R) {
                    const float* q0 = R + (size_t)r0i * N + cc;
                    const float* q1 = R + (size_t)(r0i + 8) * N + cc;
                    v0.x += q0[0]; v0.y += q0[1];
                    v1.x += q1[0]; v1.y += q1[1];
                }
                *(float2*)p0 = v0;
                *(float2*)p1 = v1;
            }
        }
    }
}

// ---------------- silu + RoPE ----------------
__global__ __launch_bounds__(256) void bcrope_kernel()
{
    int tid = threadIdx.x;
    int r8 = tid >> 5, n = tid & 31;
    int row = blockIdx.x * 8 + r8;
    int t = row & (LSEQ - 1);
    const float* base = g_zx + (size_t)row * DPROJ;
    float bo, co;
    if (n < 16) {
        int j = n >> 1;
        double invd = exp(-((double)j) * (log(10000.0) / 8.0));
        float inv = (float)invd;
        float ang = (float)t * inv;
        float sn, cs;
        sincosf(ang, &sn, &cs);
        float b1 = siluf(base[4096 + 2 * j]);
        float b2 = siluf(base[4096 + 2 * j + 1]);
        float c1 = siluf(base[4128 + 2 * j]);
        float c2 = siluf(base[4128 + 2 * j + 1]);
        if (n & 1) { bo = b1 * sn + b2 * cs; co = c1 * sn + c2 * cs; }
        else       { bo = b1 * cs - b2 * sn; co = c1 * cs - c2 * sn; }
    } else {
        bo = siluf(base[4096 + n]);
        co = siluf(base[4128 + n]);
    }
    g_Brot[(size_t)row * DS + n] = bo;
    g_Crot[(size_t)row * DS + n] = co;
}

// ---------------- dt + A-cumsum precompute ----------------
__global__ __launch_bounds__(256) void dtacs_kernel(const float* __restrict__ dt_bias,
                                                    const float* __restrict__ A_log)
{
    int bc = blockIdx.x;
    int b = bc >> 6, c = bc & 63;
    int warp = threadIdx.x >> 5, lane = threadIdx.x & 31;
    int rowbase = b * LSEQ + c * 64;
#pragma unroll
    for (int i = 0; i < 4; i++) {
        int h = warp * 4 + i;
        float A = -__expf(A_log[h]);
        float bias = dt_bias[h];
        float raw0 = g_zx[(size_t)(rowbase + lane) * DPROJ + 4160 + h] + bias;
        float raw1 = g_zx[(size_t)(rowbase + 32 + lane) * DPROJ + 4160 + h] + bias;
        float dt0 = (raw0 > 20.f) ? raw0 : log1pf(__expf(raw0));
        float dt1 = (raw1 > 20.f) ? raw1 : log1pf(__expf(raw1));
        float a0 = dt0 * A, a1 = dt1 * A;
#pragma unroll
        for (int o = 1; o < 32; o <<= 1) {
            float t = __shfl_up_sync(0xffffffffu, a0, o);
            if (lane >= o) a0 += t;
        }
#pragma unroll
        for (int o = 1; o < 32; o <<= 1) {
            float t = __shfl_up_sync(0xffffffffu, a1, o);
            if (lane >= o) a1 += t;
        }
        a1 += __shfl_sync(0xffffffffu, a0, 31);
        size_t base = ((size_t)(b * NH + h)) * LSEQ + c * 64;
        g_dtv[base + lane] = dt0;      g_dtv[base + 32 + lane] = dt1;
        g_acs[base + lane] = a0;       g_acs[base + 32 + lane] = a1;
    }
}

// ---------------- scores: per (b,c), masked C.B^T ----------------
__global__ __launch_bounds__(256) void score_kernel()
{
    int bc = blockIdx.x;
    int b = bc >> 6, c = bc & 63;
    __shared__ float Cs[64][33], Bsm[64][33];
    int tid = threadIdx.x;
    int rowbase = b * LSEQ + c * 64;
    for (int i = tid; i < 64 * 32; i += 256) {
        int l = i >> 5, n = i & 31;
        Bsm[l][n] = g_Brot[(size_t)(rowbase + l) * DS + n];
        Cs[l][n]  = g_Crot[(size_t)(rowbase + l) * DS + n];
    }
    __syncthreads();
    int l = tid >> 2, sq = tid & 3;
    float cr[32];
#pragma unroll
    for (int n = 0; n < 32; n++) cr[n] = Cs[l][n];
    float out[16];
#pragma unroll
    for (int k = 0; k < 16; k++) {
        int s = sq * 16 + k;
        float d = 0.f;
        if (s <= l) {
#pragma unroll
            for (int n = 0; n < 32; n++) d = fmaf(cr[n], Bsm[s][n], d);
        }
        out[k] = d;
    }
    float* dst = g_scores + (size_t)bc * 4096 + l * 64 + sq * 16;
#pragma unroll
    for (int k = 0; k < 16; k += 4)
        *(float4*)(dst + k) = make_float4(out[k], out[k + 1], out[k + 2], out[k + 3]);
}

// ---------------- SSD intra-chunk: fp16 2-pass Yd + states ----------------
__global__ __launch_bounds__(256) void chunk_kernel(const float* __restrict__ Dv)
{
    int blk = blockIdx.x;
    int h = blk & 31; int bcid = blk >> 5; int c = bcid & 63; int b = bcid >> 6;
    __shared__ unsigned short Mh[64][72];                   // plain fp16
    __shared__ unsigned short XThi[64][72], XTlo[64][72];   // [p][l] fp16 hi/lo
    __shared__ unsigned short BwThi[32][72], BwTlo[32][72]; // [n][l] fp16 hi/lo
    __shared__ float acs[64], dtv[64], wvv[64];
    int tid = threadIdx.x;
    int rowbase = b * LSEQ + c * 64;

    if (tid < 64) {
        size_t dbase = ((size_t)(b * NH + h)) * LSEQ + c * 64;
        dtv[tid] = g_dtv[dbase + tid];
        acs[tid] = g_acs[dbase + tid];
    }
    __syncthreads();
    if (tid < 64) wvv[tid] = dtv[tid] * __expf(acs[63] - acs[tid]);
    for (int i = tid; i < 4096; i += 256) {
        int l = i >> 6, p = i & 63;
        float v = siluf(g_zx[(size_t)(rowbase + l) * DPROJ + 2048 + h * 64 + p]);
        unsigned short hi, lo; splith(v, hi, lo);
        XThi[p][l] = hi; XTlo[p][l] = lo;
    }
    const float* psrc = g_scores + (size_t)(b * NC + c) * 4096;
    for (int i = tid; i < 4096; i += 256) {
        int l = i >> 6, s = i & 63;
        float m = 0.f;
        if (s <= l) m = psrc[i] * __expf(acs[l] - acs[s]) * dtv[s];
        Mh[l][s] = f2h(m);
    }
    __syncthreads();   // wvv ready
    for (int i = tid; i < 2048; i += 256) {
        int l = i >> 5, n = i & 31;
        float v = g_Brot[(size_t)(rowbase + l) * DS + n] * wvv[l];
        unsigned short hi, lo; splith(v, hi, lo);
        BwThi[n][l] = hi; BwTlo[n][l] = lo;
    }
    __syncthreads();

    int lane = tid & 31, w = tid >> 5;
    int g = lane >> 2, tig = lane & 3;

    // ---- Yd = M @ X (64x64x64), 2-pass ----
    {
        int m0 = (w & 3) * 16, n0 = (w >> 2) * 32;
        float acc[4][4];
#pragma unroll
        for (int i = 0; i < 4; i++)
#pragma unroll
            for (int q = 0; q < 4; q++) acc[i][q] = 0.f;
#pragma unroll
        for (int kt = 0; kt < 4; kt++) {
            int col = kt * 16 + 2 * tig;
            uint32_t ah[4];
            ldfragA<72>(ah, Mh, m0 + g, col);
#pragma unroll
            for (int nt = 0; nt < 4; nt++) {
                uint32_t bh[2], bl[2];
                ldfragB<72>(bh, XThi, n0 + nt * 8 + g, col);
                ldfragB<72>(bl, XTlo, n0 + nt * 8 + g, col);
                mma16816h(acc[nt], ah, bh);
                mma16816h(acc[nt], ah, bl);
            }
        }
        float Dh = Dv[h];
#pragma unroll
        for (int nt = 0; nt < 4; nt++) {
            int p0 = n0 + nt * 8 + 2 * tig;
            int l0 = m0 + g, l1 = l0 + 8;
            float x00 = h2f(XThi[p0][l0]) + h2f(XTlo[p0][l0]);
            float x01 = h2f(XThi[p0 + 1][l0]) + h2f(XTlo[p0 + 1][l0]);
            float x10 = h2f(XThi[p0][l1]) + h2f(XTlo[p0][l1]);
            float x11 = h2f(XThi[p0 + 1][l1]) + h2f(XTlo[p0 + 1][l1]);
            float* y0 = g_y + (size_t)(rowbase + l0) * DIN + h * HD + p0;
            float* y1 = g_y + (size_t)(rowbase + l1) * DIN + h * HD + p0;
            *(float2*)y0 = make_float2(acc[nt][0] + Dh * x00, acc[nt][1] + Dh * x01);
            *(float2*)y1 = make_float2(acc[nt][2] + Dh * x10, acc[nt][3] + Dh * x11);
        }
    }

    // ---- states = X^T @ Bw (64x32x64), 2-pass (A = Xhi plain) ----
    {
        int m0 = (w & 3) * 16;       // p
        int n0 = (w >> 2) * 16;      // n
        float acc[2][4];
#pragma unroll
        for (int i = 0; i < 2; i++)
#pragma unroll
            for (int q = 0; q < 4; q++) acc[i][q] = 0.f;
#pragma unroll
        for (int kt = 0; kt < 4; kt++) {
            int col = kt * 16 + 2 * tig;
            uint32_t ah[4];
            ldfragA<72>(ah, XThi, m0 + g, col);
#pragma unroll
            for (int nt = 0; nt < 2; nt++) {
                uint32_t bh[2], bl[2];
                ldfragB<72>(bh, BwThi, n0 + nt * 8 + g, col);
                ldfragB<72>(bl, BwTlo, n0 + nt * 8 + g, col);
                mma16816h(acc[nt], ah, bh);
                mma16816h(acc[nt], ah, bl);
            }
        }
        size_t sbase = ((size_t)((b * NC + c) * NH + h)) * (HD * DS);
#pragma unroll
        for (int nt = 0; nt < 2; nt++) {
            int nn = n0 + nt * 8 + 2 * tig;
            int p0 = m0 + g, p1 = p0 + 8;
            *(float2*)&g_states[sbase + p0 * DS + nn] = make_float2(acc[nt][0], acc[nt][1]);
            *(float2*)&g_states[sbase + p1 * DS + nn] = make_float2(acc[nt][2], acc[nt][3]);
        }
    }
}

// ---------------- inter-chunk scan: 1 elem/thread, prefetched ----------------
__global__ __launch_bounds__(256) void scan_kernel()
{
    int bh = blockIdx.x >> 3;
    int e = (blockIdx.x & 7) * 256 + threadIdx.x;
    int b = bh >> 5, h = bh & 31;
    __shared__ float ec[64];
    if (threadIdx.x < 64) {
        float cs = g_acs[(size_t)bh * LSEQ + threadIdx.x * 64 + 63];
        ec[threadIdx.x] = __expf(cs);
    }
    __syncthreads();
    size_t stride = (size_t)NH * HD * DS;
    size_t base = ((size_t)(b * NC) * NH + h) * (HD * DS) + e;
    float S = 0.f;
    float nxt = g_states[base];
#pragma unroll 4
    for (int c = 0; c < NC; c++) {
        g_stin[base] = S;
        float cur = nxt;
        if (c + 1 < NC) nxt = g_states[base + stride];
        S = fmaf(S, ec[c], cur);
        base += stride;
    }
}

// ---------------- Yo = C @ S^T (64x64x32), fp16 2-pass, y += exp(acs)*Yo ----------------
__global__ __launch_bounds__(256) void yo_kernel()
{
    int blk = blockIdx.x;
    int h = blk & 31; int bcid = blk >> 5; int c = bcid & 63; int b = bcid >> 6;
    __shared__ unsigned short Ch[64][40];                 // plain fp16
    __shared__ unsigned short Shi[64][40], Slo[64][40];   // fp16 hi/lo
    __shared__ float acs[64];
    int tid = threadIdx.x;
    int rowbase = b * LSEQ + c * 64;

    if (tid < 64) {
        size_t dbase = ((size_t)(b * NH + h)) * LSEQ + c * 64;
        acs[tid] = g_acs[dbase + tid];
    }
    size_t sbase = ((size_t)((b * NC + c) * NH + h)) * (HD * DS);
    for (int i = tid; i < 2048; i += 256) {
        int l = i >> 5, n = i & 31;
        Ch[l][n] = f2h(g_Crot[(size_t)(rowbase + l) * DS + n]);
        unsigned short hi, lo;
        splith(g_stin[sbase + i], hi, lo);
        Shi[l][n] = hi; Slo[l][n] = lo;
    }
    __syncthreads();

    int lane = tid & 31, w = tid >> 5;
    int g = lane >> 2, tig = lane & 3;
    int m0 = (w & 3) * 16, n0 = (w >> 2) * 32;
    float acc[4][4];
#pragma unroll
    for (int i = 0; i < 4; i++)
#pragma unroll
        for (int q = 0; q < 4; q++) acc[i][q] = 0.f;
#pragma unroll
    for (int kt = 0; kt < 2; kt++) {
        int col = kt * 16 + 2 * tig;
        uint32_t ah[4];
        ldfragA<40>(ah, Ch, m0 + g, col);
#pragma unroll
        for (int nt = 0; nt < 4; nt++) {
            uint32_t bh[2], bl[2];
            ldfragB<40>(bh, Shi, n0 + nt * 8 + g, col);
            ldfragB<40>(bl, Slo, n0 + nt * 8 + g, col);
            mma16816h(acc[nt], ah, bh);
            mma16816h(acc[nt], ah, bl);
        }
    }
    int l0 = m0 + g, l1 = l0 + 8;
    float el0 = __expf(acs[l0]), el1 = __expf(acs[l1]);
#pragma unroll
    for (int nt = 0; nt < 4; nt++) {
        int p0 = n0 + nt * 8 + 2 * tig;
        float* y0 = g_y + (size_t)(rowbase + l0) * DIN + h * HD + p0;
        float* y1 = g_y + (size_t)(rowbase + l1) * DIN + h * HD + p0;
        float2 v0 = *(float2*)y0, v1 = *(float2*)y1;
        v0.x += el0 * acc[nt][0]; v0.y += el0 * acc[nt][1];
        v1.x += el1 * acc[nt][2]; v1.y += el1 * acc[nt][3];
        *(float2*)y0 = v0;
        *(float2*)y1 = v1;
    }
}

// ---------------- gate + RMSNorm -> fp16 A ----------------
__global__ __launch_bounds__(256) void gate_kernel(const float* __restrict__ rms_w)
{
    int row = blockIdx.x;
    int tid = threadIdx.x;
    const float* yr = g_y + (size_t)row * DIN;
    const float* zr = g_zx + (size_t)row * DPROJ;
    float v[8]; float s2 = 0.f;
#pragma unroll
    for (int i = 0; i < 8; i++) {
        int idx = tid + i * 256;
        float y = yr[idx];
        float z = zr[idx];
        y *= siluf(z);
        v[i] = y;
        s2 = fmaf(y, y, s2);
    }
    for (int o = 16; o; o >>= 1) s2 += __shfl_down_sync(0xffffffffu, s2, o);
    __shared__ float red[8];
    if ((tid & 31) == 0) red[tid >> 5] = s2;
    __syncthreads();
    if (tid == 0) {
        float t = 0.f;
        for (int i = 0; i < 8; i++) t += red[i];
        red[0] = rsqrtf(t / DIN + 1e-6f);
    }
    __syncthreads();
    float sc = red[0];
    size_t base = (size_t)row * DIN;
#pragma unroll
    for (int i = 0; i < 8; i++) {
        int idx = tid + i * 256;
        g_Ahf[base + idx] = f2h(v[i] * sc * rms_w[idx]);
    }
}

// ---------------- launch ----------------
extern "C" void kernel_launch(void* const* d_in, const int* in_sizes, int n_in,
                              void* d_out, int out_size)
{
    (void)in_sizes; (void)n_in; (void)out_size;
    const float* x       = (const float*)d_in[0];
    const float* ln_w    = (const float*)d_in[1];
    const float* ln_b    = (const float*)d_in[2];
    const float* W_in    = (const float*)d_in[3];
    const float* dt_bias = (const float*)d_in[4];
    const float* A_log   = (const float*)d_in[5];
    const float* Dv      = (const float*)d_in[6];
    const float* rms_w   = (const float*)d_in[7];
    const float* W_out   = (const float*)d_in[8];
    float* out = (float*)d_out;

    void *pzx, *pA, *pBhi, *pBlo;
    cudaGetSymbolAddress(&pzx, g_zx);
    cudaGetSymbolAddress(&pA,  g_Ahf);
    cudaGetSymbolAddress(&pBhi, g_Bthi);
    cudaGetSymbolAddress(&pBlo, g_Btlo);

    static int attr_done = 0;
    if (!attr_done) {
        cudaFuncSetAttribute(mma_gemm, cudaFuncAttributeMaxDynamicSharedMemorySize, SMEM_GEMM);
        attr_done = 1;
    }

    ln_kernel<<<MROWS, 256>>>(x, ln_w, ln_b);
    cvtT_kernel<<<dim3(DIMX / 32, NPAD_IN / 32), dim3(32, 32)>>>(W_in, DIMX, DPROJ);
    mma_gemm<<<dim3(33, 128), 256, SMEM_GEMM>>>(
        (const unsigned short*)pA,
        (const unsigned short*)pBhi, (const unsigned short*)pBlo,
        (const float*)0, (float*)pzx, DPROJ, DIMX);
    bcrope_kernel<<<MROWS / 8, 256>>>();
    dtacs_kernel<<<4 * NC, 256>>>(dt_bias, A_log);
    score_kernel<<<4 * NC, 256>>>();
    chunk_kernel<<<4 * NC * NH, 256>>>(Dv);
    scan_kernel<<<4 * NH * 8, 256>>>();
    yo_kernel<<<4 * NC * NH, 256>>>();
    gate_kernel<<<MROWS, 256>>>(rms_w);
    cvtT_kernel<<<dim3(DIN / 32, DIMX / 32), dim3(32, 32)>>>(W_out, DIN, DIMX);
    mma_gemm<<<dim3(8, 128), 256, SMEM_GEMM>>>(
        (const unsigned short*)pA,
        (const unsigned short*)pBhi, (const unsigned short*)pBlo,
        x, out, DIMX, DIN);
}

// round 12
// speedup vs baseline: 2.9532x; 1.3474x over previous
#include <cuda_runtime.h>
#include <cuda_bf16.h>
#include <cuda_fp16.h>
#include <math.h>
#include <stdint.h>

#define MROWS 16384
#define DIMX 1024
#define DPROJ 4192
#define DIN 2048
#define NH 32
#define HD 64
#define DS 32
#define LSEQ 4096
#define NC 64
#define NPAD_IN 4224

// ---------------- scratch ----------------
__device__ float g_zx[(size_t)MROWS * DPROJ];
__device__ float g_Brot[(size_t)MROWS * DS];
__device__ float g_Crot[(size_t)MROWS * DS];
__device__ float g_states[(size_t)4 * NC * NH * HD * DS];
__device__ float g_stin[(size_t)4 * NC * NH * HD * DS];
__device__ float g_y[(size_t)MROWS * DIN];
__device__ float g_scores[(size_t)4 * NC * 64 * 64];
__device__ float g_dtv[(size_t)4 * NH * LSEQ];
__device__ float g_acs[(size_t)4 * NH * LSEQ];
__device__ unsigned short g_Ahf[(size_t)MROWS * DIN];      // fp16 bits (A for GEMMs)
__device__ unsigned short g_Bthi[(size_t)NPAD_IN * 1024];  // fp16 weights (transposed)

__device__ __forceinline__ float siluf(float x) { return x / (1.f + __expf(-x)); }

// fp16 hi/lo split (SSD B-operands)
__device__ __forceinline__ void splith(float f, unsigned short& hi, unsigned short& lo) {
    __half h = __float2half(f);
    float r = f - __half2float(h);
    __half l = __float2half(r);
    hi = *reinterpret_cast<unsigned short*>(&h);
    lo = *reinterpret_cast<unsigned short*>(&l);
}
__device__ __forceinline__ unsigned short f2h(float f) {
    __half h = __float2half(f);
    return *reinterpret_cast<unsigned short*>(&h);
}
__device__ __forceinline__ float h2f(unsigned short u) {
    __half h = *reinterpret_cast<__half*>(&u);
    return __half2float(h);
}

__device__ __forceinline__ uint32_t smem_u32(const void* p) {
    uint32_t a;
    asm("{ .reg .u64 t; cvta.to.shared.u64 t, %1; cvt.u32.u64 %0, t; }" : "=r"(a) : "l"(p));
    return a;
}
__device__ __forceinline__ void cpasync16(uint32_t dst, const void* src) {
    asm volatile("cp.async.cg.shared.global [%0], [%1], 16;" :: "r"(dst), "l"(src) : "memory");
}
__device__ __forceinline__ void mma16816h(float* c, const uint32_t* a, const uint32_t* b) {
    asm volatile(
        "mma.sync.aligned.m16n8k16.row.col.f32.f16.f16.f32 "
        "{%0,%1,%2,%3}, {%4,%5,%6,%7}, {%8,%9}, {%0,%1,%2,%3};\n"
        : "+f"(c[0]), "+f"(c[1]), "+f"(c[2]), "+f"(c[3])
        : "r"(a[0]), "r"(a[1]), "r"(a[2]), "r"(a[3]), "r"(b[0]), "r"(b[1]));
}
template<int P>
__device__ __forceinline__ void ldfragA(uint32_t* a, const unsigned short (*S)[P], int row, int col) {
    a[0] = *(const uint32_t*)&S[row][col];
    a[1] = *(const uint32_t*)&S[row + 8][col];
    a[2] = *(const uint32_t*)&S[row][col + 8];
    a[3] = *(const uint32_t*)&S[row + 8][col + 8];
}
template<int P>
__device__ __forceinline__ void ldfragB(uint32_t* bb, const unsigned short (*S)[P], int row, int col) {
    bb[0] = *(const uint32_t*)&S[row][col];
    bb[1] = *(const uint32_t*)&S[row][col + 8];
}

// ---------------- LayerNorm -> fp16 A ----------------
__global__ __launch_bounds__(256) void ln_kernel(const float* __restrict__ x,
                                                 const float* __restrict__ w,
                                                 const float* __restrict__ b)
{
    int row = blockIdx.x;
    int tid = threadIdx.x;
    const float* xr = x + (size_t)row * DIMX;
    float4 v = *(const float4*)(xr + tid * 4);
    float s  = v.x + v.y + v.z + v.w;
    float s2 = v.x*v.x + v.y*v.y + v.z*v.z + v.w*v.w;
    for (int o = 16; o; o >>= 1) {
        s  += __shfl_down_sync(0xffffffffu, s,  o);
        s2 += __shfl_down_sync(0xffffffffu, s2, o);
    }
    __shared__ float ss[8], ss2[8];
    if ((tid & 31) == 0) { ss[tid >> 5] = s; ss2[tid >> 5] = s2; }
    __syncthreads();
    if (tid == 0) {
        float t = 0.f, t2 = 0.f;
        for (int i = 0; i < 8; i++) { t += ss[i]; t2 += ss2[i]; }
        float mu = t / DIMX;
        ss[0]  = mu;
        ss2[0] = rsqrtf(t2 / DIMX - mu * mu + 1e-6f);
    }
    __syncthreads();
    float mu = ss[0], inv = ss2[0];
    int i0 = tid * 4;
    float4 wv = *(const float4*)(w + i0);
    float4 bv = *(const float4*)(b + i0);
    ushort4 hv;
    hv.x = f2h((v.x - mu) * inv * wv.x + bv.x);
    hv.y = f2h((v.y - mu) * inv * wv.y + bv.y);
    hv.z = f2h((v.z - mu) * inv * wv.z + bv.z);
    hv.w = f2h((v.w - mu) * inv * wv.w + bv.w);
    *(ushort4*)(g_Ahf + (size_t)row * DIMX + i0) = hv;
}

// ---------------- W[K,N] -> Bt[n][k] fp16 ----------------
__global__ __launch_bounds__(1024) void cvtT_kernel(const float* __restrict__ W, int K, int N)
{
    __shared__ float t[32][33];
    int k0 = blockIdx.x * 32, n0 = blockIdx.y * 32;
    int tx = threadIdx.x, ty = threadIdx.y;
    int n = n0 + tx;
    t[ty][tx] = (n < N) ? W[(size_t)(k0 + ty) * N + n] : 0.f;
    __syncthreads();
    g_Bthi[(size_t)(n0 + ty) * K + k0 + tx] = f2h(t[tx][ty]);
}

// ---------------- mma.sync fp16 GEMM, 1-pass; 2 CTAs/SM ----------------
#define KSTAGE 20480
#define SMEM_GEMM (2 * KSTAGE)
__global__ __launch_bounds__(256, 2) void mma_gemm(
    const unsigned short* __restrict__ A,
    const unsigned short* __restrict__ B,
    const float* __restrict__ R, float* __restrict__ C, int N, int K)
{
    extern __shared__ char sm[];
    int tid = threadIdx.x, lane = tid & 31, wid = tid >> 5;
    int col0 = blockIdx.x * 128, row0 = blockIdx.y * 128;
    int g = lane >> 2, tig = lane & 3;
    int m0 = (wid >> 2) * 64, n0 = (wid & 3) * 32;
    uint32_t sb = smem_u32(sm);

    float acc[4][4][4];
#pragma unroll
    for (int i = 0; i < 4; i++)
#pragma unroll
        for (int j = 0; j < 4; j++)
#pragma unroll
            for (int q = 0; q < 4; q++) acc[i][j][q] = 0.f;

    const unsigned short* srcs[2] = {A, B};
    int rbs[2] = {row0, col0};

    int KT = K >> 5;
    {
#pragma unroll
        for (int t = 0; t < 2; t++) {
#pragma unroll
            for (int cc = 0; cc < 2; cc++) {
                int chunk = tid + cc * 256;
                int row = chunk >> 2, c4 = chunk & 3;
                const void* src = srcs[t] + (size_t)(rbs[t] + row) * K + c4 * 8;
                cpasync16(sb + t * 10240 + row * 80 + c4 * 16, src);
            }
        }
        asm volatile("cp.async.commit_group;" ::: "memory");
    }

    for (int kt = 0; kt < KT; kt++) {
        if (kt + 1 < KT) {
            int buf = (kt + 1) & 1;
#pragma unroll
            for (int t = 0; t < 2; t++) {
#pragma unroll
                for (int cc = 0; cc < 2; cc++) {
                    int chunk = tid + cc * 256;
                    int row = chunk >> 2, c4 = chunk & 3;
                    const void* src = srcs[t] + (size_t)(rbs[t] + row) * K + (kt + 1) * 32 + c4 * 8;
                    cpasync16(sb + buf * KSTAGE + t * 10240 + row * 80 + c4 * 16, src);
                }
            }
            asm volatile("cp.async.commit_group;" ::: "memory");
            asm volatile("cp.async.wait_group 1;" ::: "memory");
        } else {
            asm volatile("cp.async.wait_group 0;" ::: "memory");
        }
        __syncthreads();

        const char* stb = sm + (kt & 1) * KSTAGE;
#pragma unroll
        for (int ks = 0; ks < 2; ks++) {
            int wb = (ks * 8 + tig) * 4;
            uint32_t bh[4][2];
#pragma unroll
            for (int nt = 0; nt < 4; nt++) {
                const char* pb = stb + 10240 + (n0 + nt * 8 + g) * 80 + wb;
                bh[nt][0] = *(const uint32_t*)(pb);
                bh[nt][1] = *(const uint32_t*)(pb + 16);
            }
#pragma unroll
            for (int mt = 0; mt < 4; mt++) {
                const char* pa = stb + (m0 + mt * 16 + g) * 80 + wb;
                uint32_t ah[4];
                ah[0] = *(const uint32_t*)(pa);
                ah[1] = *(const uint32_t*)(pa + 8 * 80);
                ah[2] = *(const uint32_t*)(pa + 16);
                ah[3] = *(const uint32_t*)(pa + 8 * 80 + 16);
#pragma unroll
                for (int nt = 0; nt < 4; nt++)
                    mma16816h(acc[mt][nt], ah, bh[nt]);
            }
        }
        __syncthreads();
    }

#pragma unroll
    for (int mt = 0; mt < 4; mt++) {
        int r0i = row0 + m0 + mt * 16 + g;
#pragma unroll
        for (int nt = 0; nt < 4; nt++) {
            int cc = col0 + n0 + nt * 8 + tig * 2;
            if (cc < N) {
                float* p0 = C + (size_t)r0i * N + cc;
                float* p1 = C + (size_t)(r0i + 8) * N + cc;
                float2 v0 = make_float2(acc[mt][nt][0], acc[mt][nt][1]);
                float2 v1 = make_float2(acc[mt][nt][2], acc[mt][nt][3]);
                if (R) {
                    const float* q0 = R + (size_t)r0i * N + cc;
                    const float* q1 = R + (size_t)(r0i + 8) * N + cc;
                    v0.x += q0[0]; v0.y += q0[1];
                    v1.x += q1[0]; v1.y += q1[1];
                }
                *(float2*)p0 = v0;
                *(float2*)p1 = v1;
            }
        }
    }
}

// ---------------- silu + RoPE ----------------
__global__ __launch_bounds__(256) void bcrope_kernel()
{
    int tid = threadIdx.x;
    int r8 = tid >> 5, n = tid & 31;
    int row = blockIdx.x * 8 + r8;
    int t = row & (LSEQ - 1);
    const float* base = g_zx + (size_t)row * DPROJ;
    float bo, co;
    if (n < 16) {
        int j = n >> 1;
        double invd = exp(-((double)j) * (log(10000.0) / 8.0));
        float inv = (float)invd;
        float ang = (float)t * inv;
        float sn, cs;
        sincosf(ang, &sn, &cs);
        float b1 = siluf(base[4096 + 2 * j]);
        float b2 = siluf(base[4096 + 2 * j + 1]);
        float c1 = siluf(base[4128 + 2 * j]);
        float c2 = siluf(base[4128 + 2 * j + 1]);
        if (n & 1) { bo = b1 * sn + b2 * cs; co = c1 * sn + c2 * cs; }
        else       { bo = b1 * cs - b2 * sn; co = c1 * cs - c2 * sn; }
    } else {
        bo = siluf(base[4096 + n]);
        co = siluf(base[4128 + n]);
    }
    g_Brot[(size_t)row * DS + n] = bo;
    g_Crot[(size_t)row * DS + n] = co;
}

// ---------------- dt + A-cumsum precompute ----------------
__global__ __launch_bounds__(256) void dtacs_kernel(const float* __restrict__ dt_bias,
                                                    const float* __restrict__ A_log)
{
    int bc = blockIdx.x;
    int b = bc >> 6, c = bc & 63;
    int warp = threadIdx.x >> 5, lane = threadIdx.x & 31;
    int rowbase = b * LSEQ + c * 64;
#pragma unroll
    for (int i = 0; i < 4; i++) {
        int h = warp * 4 + i;
        float A = -__expf(A_log[h]);
        float bias = dt_bias[h];
        float raw0 = g_zx[(size_t)(rowbase + lane) * DPROJ + 4160 + h] + bias;
        float raw1 = g_zx[(size_t)(rowbase + 32 + lane) * DPROJ + 4160 + h] + bias;
        float dt0 = (raw0 > 20.f) ? raw0 : log1pf(__expf(raw0));
        float dt1 = (raw1 > 20.f) ? raw1 : log1pf(__expf(raw1));
        float a0 = dt0 * A, a1 = dt1 * A;
#pragma unroll
        for (int o = 1; o < 32; o <<= 1) {
            float t = __shfl_up_sync(0xffffffffu, a0, o);
            if (lane >= o) a0 += t;
        }
#pragma unroll
        for (int o = 1; o < 32; o <<= 1) {
            float t = __shfl_up_sync(0xffffffffu, a1, o);
            if (lane >= o) a1 += t;
        }
        a1 += __shfl_sync(0xffffffffu, a0, 31);
        size_t base = ((size_t)(b * NH + h)) * LSEQ + c * 64;
        g_dtv[base + lane] = dt0;      g_dtv[base + 32 + lane] = dt1;
        g_acs[base + lane] = a0;       g_acs[base + 32 + lane] = a1;
    }
}

// ---------------- scores: per (b,c), masked C.B^T ----------------
__global__ __launch_bounds__(256) void score_kernel()
{
    int bc = blockIdx.x;
    int b = bc >> 6, c = bc & 63;
    __shared__ float Cs[64][33], Bsm[64][33];
    int tid = threadIdx.x;
    int rowbase = b * LSEQ + c * 64;
    for (int i = tid; i < 64 * 32; i += 256) {
        int l = i >> 5, n = i & 31;
        Bsm[l][n] = g_Brot[(size_t)(rowbase + l) * DS + n];
        Cs[l][n]  = g_Crot[(size_t)(rowbase + l) * DS + n];
    }
    __syncthreads();
    int l = tid >> 2, sq = tid & 3;
    float cr[32];
#pragma unroll
    for (int n = 0; n < 32; n++) cr[n] = Cs[l][n];
    float out[16];
#pragma unroll
    for (int k = 0; k < 16; k++) {
        int s = sq * 16 + k;
        float d = 0.f;
        if (s <= l) {
#pragma unroll
            for (int n = 0; n < 32; n++) d = fmaf(cr[n], Bsm[s][n], d);
        }
        out[k] = d;
    }
    float* dst = g_scores + (size_t)bc * 4096 + l * 64 + sq * 16;
#pragma unroll
    for (int k = 0; k < 16; k += 4)
        *(float4*)(dst + k) = make_float4(out[k], out[k + 1], out[k + 2], out[k + 3]);
}

// ---------------- SSD intra-chunk: fp16 2-pass Yd + states ----------------
__global__ __launch_bounds__(256) void chunk_kernel(const float* __restrict__ Dv)
{
    int blk = blockIdx.x;
    int h = blk & 31; int bcid = blk >> 5; int c = bcid & 63; int b = bcid >> 6;
    __shared__ unsigned short Mh[64][72];                   // plain fp16
    __shared__ unsigned short XThi[64][72], XTlo[64][72];   // [p][l] fp16 hi/lo
    __shared__ unsigned short BwThi[32][72], BwTlo[32][72]; // [n][l] fp16 hi/lo
    __shared__ float acs[64], dtv[64], wvv[64];
    int tid = threadIdx.x;
    int rowbase = b * LSEQ + c * 64;

    if (tid < 64) {
        size_t dbase = ((size_t)(b * NH + h)) * LSEQ + c * 64;
        dtv[tid] = g_dtv[dbase + tid];
        acs[tid] = g_acs[dbase + tid];
    }
    __syncthreads();
    if (tid < 64) wvv[tid] = dtv[tid] * __expf(acs[63] - acs[tid]);
    for (int i = tid; i < 4096; i += 256) {
        int l = i >> 6, p = i & 63;
        float v = siluf(g_zx[(size_t)(rowbase + l) * DPROJ + 2048 + h * 64 + p]);
        unsigned short hi, lo; splith(v, hi, lo);
        XThi[p][l] = hi; XTlo[p][l] = lo;
    }
    const float* psrc = g_scores + (size_t)(b * NC + c) * 4096;
    for (int i = tid; i < 4096; i += 256) {
        int l = i >> 6, s = i & 63;
        float m = 0.f;
        if (s <= l) m = psrc[i] * __expf(acs[l] - acs[s]) * dtv[s];
        Mh[l][s] = f2h(m);
    }
    __syncthreads();   // wvv ready
    for (int i = tid; i < 2048; i += 256) {
        int l = i >> 5, n = i & 31;
        float v = g_Brot[(size_t)(rowbase + l) * DS + n] * wvv[l];
        unsigned short hi, lo; splith(v, hi, lo);
        BwThi[n][l] = hi; BwTlo[n][l] = lo;
    }
    __syncthreads();

    int lane = tid & 31, w = tid >> 5;
    int g = lane >> 2, tig = lane & 3;

    // ---- Yd = M @ X (64x64x64), 2-pass ----
    {
        int m0 = (w & 3) * 16, n0 = (w >> 2) * 32;
        float acc[4][4];
#pragma unroll
        for (int i = 0; i < 4; i++)
#pragma unroll
            for (int q = 0; q < 4; q++) acc[i][q] = 0.f;
#pragma unroll
        for (int kt = 0; kt < 4; kt++) {
            int col = kt * 16 + 2 * tig;
            uint32_t ah[4];
            ldfragA<72>(ah, Mh, m0 + g, col);
#pragma unroll
            for (int nt = 0; nt < 4; nt++) {
                uint32_t bh[2], bl[2];
                ldfragB<72>(bh, XThi, n0 + nt * 8 + g, col);
                ldfragB<72>(bl, XTlo, n0 + nt * 8 + g, col);
                mma16816h(acc[nt], ah, bh);
                mma16816h(acc[nt], ah, bl);
            }
        }
        float Dh = Dv[h];
#pragma unroll
        for (int nt = 0; nt < 4; nt++) {
            int p0 = n0 + nt * 8 + 2 * tig;
            int l0 = m0 + g, l1 = l0 + 8;
            float x00 = h2f(XThi[p0][l0]) + h2f(XTlo[p0][l0]);
            float x01 = h2f(XThi[p0 + 1][l0]) + h2f(XTlo[p0 + 1][l0]);
            float x10 = h2f(XThi[p0][l1]) + h2f(XTlo[p0][l1]);
            float x11 = h2f(XThi[p0 + 1][l1]) + h2f(XTlo[p0 + 1][l1]);
            float* y0 = g_y + (size_t)(rowbase + l0) * DIN + h * HD + p0;
            float* y1 = g_y + (size_t)(rowbase + l1) * DIN + h * HD + p0;
            *(float2*)y0 = make_float2(acc[nt][0] + Dh * x00, acc[nt][1] + Dh * x01);
            *(float2*)y1 = make_float2(acc[nt][2] + Dh * x10, acc[nt][3] + Dh * x11);
        }
    }

    // ---- states = X^T @ Bw (64x32x64), 2-pass (A = Xhi plain) ----
    {
        int m0 = (w & 3) * 16;       // p
        int n0 = (w >> 2) * 16;      // n
        float acc[2][4];
#pragma unroll
        for (int i = 0; i < 2; i++)
#pragma unroll
            for (int q = 0; q < 4; q++) acc[i][q] = 0.f;
#pragma unroll
        for (int kt = 0; kt < 4; kt++) {
            int col = kt * 16 + 2 * tig;
            uint32_t ah[4];
            ldfragA<72>(ah, XThi, m0 + g, col);
#pragma unroll
            for (int nt = 0; nt < 2; nt++) {
                uint32_t bh[2], bl[2];
                ldfragB<72>(bh, BwThi, n0 + nt * 8 + g, col);
                ldfragB<72>(bl, BwTlo, n0 + nt * 8 + g, col);
                mma16816h(acc[nt], ah, bh);
                mma16816h(acc[nt], ah, bl);
            }
        }
        size_t sbase = ((size_t)((b * NC + c) * NH + h)) * (HD * DS);
#pragma unroll
        for (int nt = 0; nt < 2; nt++) {
            int nn = n0 + nt * 8 + 2 * tig;
            int p0 = m0 + g, p1 = p0 + 8;
            *(float2*)&g_states[sbase + p0 * DS + nn] = make_float2(acc[nt][0], acc[nt][1]);
            *(float2*)&g_states[sbase + p1 * DS + nn] = make_float2(acc[nt][2], acc[nt][3]);
        }
    }
}

// ---------------- inter-chunk scan: 1 elem/thread, prefetched ----------------
__global__ __launch_bounds__(256) void scan_kernel()
{
    int bh = blockIdx.x >> 3;
    int e = (blockIdx.x & 7) * 256 + threadIdx.x;
    int b = bh >> 5, h = bh & 31;
    __shared__ float ec[64];
    if (threadIdx.x < 64) {
        float cs = g_acs[(size_t)bh * LSEQ + threadIdx.x * 64 + 63];
        ec[threadIdx.x] = __expf(cs);
    }
    __syncthreads();
    size_t stride = (size_t)NH * HD * DS;
    size_t base = ((size_t)(b * NC) * NH + h) * (HD * DS) + e;
    float S = 0.f;
    float nxt = g_states[base];
#pragma unroll 4
    for (int c = 0; c < NC; c++) {
        g_stin[base] = S;
        float cur = nxt;
        if (c + 1 < NC) nxt = g_states[base + stride];
        S = fmaf(S, ec[c], cur);
        base += stride;
    }
}

// ---------------- Yo = C @ S^T (64x64x32), fp16 2-pass, y += exp(acs)*Yo ----------------
__global__ __launch_bounds__(256) void yo_kernel()
{
    int blk = blockIdx.x;
    int h = blk & 31; int bcid = blk >> 5; int c = bcid & 63; int b = bcid >> 6;
    __shared__ unsigned short Ch[64][40];                 // plain fp16
    __shared__ unsigned short Shi[64][40], Slo[64][40];   // fp16 hi/lo
    __shared__ float acs[64];
    int tid = threadIdx.x;
    int rowbase = b * LSEQ + c * 64;

    if (tid < 64) {
        size_t dbase = ((size_t)(b * NH + h)) * LSEQ + c * 64;
        acs[tid] = g_acs[dbase + tid];
    }
    size_t sbase = ((size_t)((b * NC + c) * NH + h)) * (HD * DS);
    for (int i = tid; i < 2048; i += 256) {
        int l = i >> 5, n = i & 31;
        Ch[l][n] = f2h(g_Crot[(size_t)(rowbase + l) * DS + n]);
        unsigned short hi, lo;
        splith(g_stin[sbase + i], hi, lo);
        Shi[l][n] = hi; Slo[l][n] = lo;
    }
    __syncthreads();

    int lane = tid & 31, w = tid >> 5;
    int g = lane >> 2, tig = lane & 3;
    int m0 = (w & 3) * 16, n0 = (w >> 2) * 32;
    float acc[4][4];
#pragma unroll
    for (int i = 0; i < 4; i++)
#pragma unroll
        for (int q = 0; q < 4; q++) acc[i][q] = 0.f;
#pragma unroll
    for (int kt = 0; kt < 2; kt++) {
        int col = kt * 16 + 2 * tig;
        uint32_t ah[4];
        ldfragA<40>(ah, Ch, m0 + g, col);
#pragma unroll
        for (int nt = 0; nt < 4; nt++) {
            uint32_t bh[2], bl[2];
            ldfragB<40>(bh, Shi, n0 + nt * 8 + g, col);
            ldfragB<40>(bl, Slo, n0 + nt * 8 + g, col);
            mma16816h(acc[nt], ah, bh);
            mma16816h(acc[nt], ah, bl);
        }
    }
    int l0 = m0 + g, l1 = l0 + 8;
    float el0 = __expf(acs[l0]), el1 = __expf(acs[l1]);
#pragma unroll
    for (int nt = 0; nt < 4; nt++) {
        int p0 = n0 + nt * 8 + 2 * tig;
        float* y0 = g_y + (size_t)(rowbase + l0) * DIN + h * HD + p0;
        float* y1 = g_y + (size_t)(rowbase + l1) * DIN + h * HD + p0;
        float2 v0 = *(float2*)y0, v1 = *(float2*)y1;
        v0.x += el0 * acc[nt][0]; v0.y += el0 * acc[nt][1];
        v1.x += el1 * acc[nt][2]; v1.y += el1 * acc[nt][3];
        *(float2*)y0 = v0;
        *(float2*)y1 = v1;
    }
}

// ---------------- gate + RMSNorm -> fp16 A ----------------
__global__ __launch_bounds__(256) void gate_kernel(const float* __restrict__ rms_w)
{
    int row = blockIdx.x;
    int tid = threadIdx.x;
    const float* yr = g_y + (size_t)row * DIN;
    const float* zr = g_zx + (size_t)row * DPROJ;
    float v[8]; float s2 = 0.f;
#pragma unroll
    for (int i = 0; i < 8; i++) {
        int idx = tid + i * 256;
        float y = yr[idx];
        float z = zr[idx];
        y *= siluf(z);
        v[i] = y;
        s2 = fmaf(y, y, s2);
    }
    for (int o = 16; o; o >>= 1) s2 += __shfl_down_sync(0xffffffffu, s2, o);
    __shared__ float red[8];
    if ((tid & 31) == 0) red[tid >> 5] = s2;
    __syncthreads();
    if (tid == 0) {
        float t = 0.f;
        for (int i = 0; i < 8; i++) t += red[i];
        red[0] = rsqrtf(t / DIN + 1e-6f);
    }
    __syncthreads();
    float sc = red[0];
    size_t base = (size_t)row * DIN;
#pragma unroll
    for (int i = 0; i < 8; i++) {
        int idx = tid + i * 256;
        g_Ahf[base + idx] = f2h(v[i] * sc * rms_w[idx]);
    }
}

// ---------------- launch ----------------
extern "C" void kernel_launch(void* const* d_in, const int* in_sizes, int n_in,
                              void* d_out, int out_size)
{
    (void)in_sizes; (void)n_in; (void)out_size;
    const float* x       = (const float*)d_in[0];
    const float* ln_w    = (const float*)d_in[1];
    const float* ln_b    = (const float*)d_in[2];
    const float* W_in    = (const float*)d_in[3];
    const float* dt_bias = (const float*)d_in[4];
    const float* A_log   = (const float*)d_in[5];
    const float* Dv      = (const float*)d_in[6];
    const float* rms_w   = (const float*)d_in[7];
    const float* W_out   = (const float*)d_in[8];
    float* out = (float*)d_out;

    void *pzx, *pA, *pB;
    cudaGetSymbolAddress(&pzx, g_zx);
    cudaGetSymbolAddress(&pA,  g_Ahf);
    cudaGetSymbolAddress(&pB,  g_Bthi);

    static int attr_done = 0;
    if (!attr_done) {
        cudaFuncSetAttribute(mma_gemm, cudaFuncAttributeMaxDynamicSharedMemorySize, SMEM_GEMM);
        attr_done = 1;
    }

    ln_kernel<<<MROWS, 256>>>(x, ln_w, ln_b);
    cvtT_kernel<<<dim3(DIMX / 32, NPAD_IN / 32), dim3(32, 32)>>>(W_in, DIMX, DPROJ);
    mma_gemm<<<dim3(33, 128), 256, SMEM_GEMM>>>(
        (const unsigned short*)pA, (const unsigned short*)pB,
        (const float*)0, (float*)pzx, DPROJ, DIMX);
    bcrope_kernel<<<MROWS / 8, 256>>>();
    dtacs_kernel<<<4 * NC, 256>>>(dt_bias, A_log);
    score_kernel<<<4 * NC, 256>>>();
    chunk_kernel<<<4 * NC * NH, 256>>>(Dv);
    scan_kernel<<<4 * NH * 8, 256>>>();
    yo_kernel<<<4 * NC * NH, 256>>>();
    gate_kernel<<<MROWS, 256>>>(rms_w);
    cvtT_kernel<<<dim3(DIN / 32, DIMX / 32), dim3(32, 32)>>>(W_out, DIN, DIMX);
    mma_gemm<<<dim3(8, 128), 256, SMEM_GEMM>>>(
        (const unsigned short*)pA, (const unsigned short*)pB,
        x, out, DIMX, DIN);
}

// round 13
// speedup vs baseline: 3.1032x; 1.0508x over previous
#include <cuda_runtime.h>
#include <cuda_bf16.h>
#include <cuda_fp16.h>
#include <math.h>
#include <stdint.h>

#define MROWS 16384
#define DIMX 1024
#define DPROJ 4192
#define DIN 2048
#define NH 32
#define HD 64
#define DS 32
#define LSEQ 4096
#define NC 64
#define NPAD_IN 4224

// ---------------- scratch ----------------
__device__ float g_zx[(size_t)MROWS * DPROJ];
__device__ float g_Brot[(size_t)MROWS * DS];
__device__ float g_Crot[(size_t)MROWS * DS];
__device__ float g_states[(size_t)4 * NC * NH * HD * DS];
__device__ float g_stin[(size_t)4 * NC * NH * HD * DS];
__device__ float g_y[(size_t)MROWS * DIN];
__device__ float g_scores[(size_t)4 * NC * 64 * 64];
__device__ float g_dtv[(size_t)4 * NH * LSEQ];
__device__ float g_acs[(size_t)4 * NH * LSEQ];
__device__ unsigned short g_Ahf[(size_t)MROWS * DIN];      // fp16 bits (A for GEMMs)
__device__ unsigned short g_Bthi[(size_t)NPAD_IN * 1024];  // fp16 weights (transposed)

__device__ __forceinline__ float siluf(float x) { return x / (1.f + __expf(-x)); }

__device__ __forceinline__ unsigned short f2h(float f) {
    __half h = __float2half(f);
    return *reinterpret_cast<unsigned short*>(&h);
}
__device__ __forceinline__ float h2f(unsigned short u) {
    __half h = *reinterpret_cast<__half*>(&u);
    return __half2float(h);
}

__device__ __forceinline__ uint32_t smem_u32(const void* p) {
    uint32_t a;
    asm("{ .reg .u64 t; cvta.to.shared.u64 t, %1; cvt.u32.u64 %0, t; }" : "=r"(a) : "l"(p));
    return a;
}
__device__ __forceinline__ void cpasync16(uint32_t dst, const void* src) {
    asm volatile("cp.async.cg.shared.global [%0], [%1], 16;" :: "r"(dst), "l"(src) : "memory");
}
__device__ __forceinline__ void mma16816h(float* c, const uint32_t* a, const uint32_t* b) {
    asm volatile(
        "mma.sync.aligned.m16n8k16.row.col.f32.f16.f16.f32 "
        "{%0,%1,%2,%3}, {%4,%5,%6,%7}, {%8,%9}, {%0,%1,%2,%3};\n"
        : "+f"(c[0]), "+f"(c[1]), "+f"(c[2]), "+f"(c[3])
        : "r"(a[0]), "r"(a[1]), "r"(a[2]), "r"(a[3]), "r"(b[0]), "r"(b[1]));
}
template<int P>
__device__ __forceinline__ void ldfragA(uint32_t* a, const unsigned short (*S)[P], int row, int col) {
    a[0] = *(const uint32_t*)&S[row][col];
    a[1] = *(const uint32_t*)&S[row + 8][col];
    a[2] = *(const uint32_t*)&S[row][col + 8];
    a[3] = *(const uint32_t*)&S[row + 8][col + 8];
}
template<int P>
__device__ __forceinline__ void ldfragB(uint32_t* bb, const unsigned short (*S)[P], int row, int col) {
    bb[0] = *(const uint32_t*)&S[row][col];
    bb[1] = *(const uint32_t*)&S[row][col + 8];
}

// ---------------- LayerNorm -> fp16 A ----------------
__global__ __launch_bounds__(256) void ln_kernel(const float* __restrict__ x,
                                                 const float* __restrict__ w,
                                                 const float* __restrict__ b)
{
    int row = blockIdx.x;
    int tid = threadIdx.x;
    const float* xr = x + (size_t)row * DIMX;
    float4 v = *(const float4*)(xr + tid * 4);
    float s  = v.x + v.y + v.z + v.w;
    float s2 = v.x*v.x + v.y*v.y + v.z*v.z + v.w*v.w;
    for (int o = 16; o; o >>= 1) {
        s  += __shfl_down_sync(0xffffffffu, s,  o);
        s2 += __shfl_down_sync(0xffffffffu, s2, o);
    }
    __shared__ float ss[8], ss2[8];
    if ((tid & 31) == 0) { ss[tid >> 5] = s; ss2[tid >> 5] = s2; }
    __syncthreads();
    if (tid == 0) {
        float t = 0.f, t2 = 0.f;
        for (int i = 0; i < 8; i++) { t += ss[i]; t2 += ss2[i]; }
        float mu = t / DIMX;
        ss[0]  = mu;
        ss2[0] = rsqrtf(t2 / DIMX - mu * mu + 1e-6f);
    }
    __syncthreads();
    float mu = ss[0], inv = ss2[0];
    int i0 = tid * 4;
    float4 wv = *(const float4*)(w + i0);
    float4 bv = *(const float4*)(b + i0);
    ushort4 hv;
    hv.x = f2h((v.x - mu) * inv * wv.x + bv.x);
    hv.y = f2h((v.y - mu) * inv * wv.y + bv.y);
    hv.z = f2h((v.z - mu) * inv * wv.z + bv.z);
    hv.w = f2h((v.w - mu) * inv * wv.w + bv.w);
    *(ushort4*)(g_Ahf + (size_t)row * DIMX + i0) = hv;
}

// ---------------- W[K,N] -> Bt[n][k] fp16 ----------------
__global__ __launch_bounds__(1024) void cvtT_kernel(const float* __restrict__ W, int K, int N)
{
    __shared__ float t[32][33];
    int k0 = blockIdx.x * 32, n0 = blockIdx.y * 32;
    int tx = threadIdx.x, ty = threadIdx.y;
    int n = n0 + tx;
    t[ty][tx] = (n < N) ? W[(size_t)(k0 + ty) * N + n] : 0.f;
    __syncthreads();
    g_Bthi[(size_t)(n0 + ty) * K + k0 + tx] = f2h(t[tx][ty]);
}

// ---------------- mma.sync fp16 GEMM, 1-pass; 2 CTAs/SM ----------------
#define KSTAGE 20480
#define SMEM_GEMM (2 * KSTAGE)
__global__ __launch_bounds__(256, 2) void mma_gemm(
    const unsigned short* __restrict__ A,
    const unsigned short* __restrict__ B,
    const float* __restrict__ R, float* __restrict__ C, int N, int K)
{
    extern __shared__ char sm[];
    int tid = threadIdx.x, lane = tid & 31, wid = tid >> 5;
    int col0 = blockIdx.x * 128, row0 = blockIdx.y * 128;
    int g = lane >> 2, tig = lane & 3;
    int m0 = (wid >> 2) * 64, n0 = (wid & 3) * 32;
    uint32_t sb = smem_u32(sm);

    float acc[4][4][4];
#pragma unroll
    for (int i = 0; i < 4; i++)
#pragma unroll
        for (int j = 0; j < 4; j++)
#pragma unroll
            for (int q = 0; q < 4; q++) acc[i][j][q] = 0.f;

    const unsigned short* srcs[2] = {A, B};
    int rbs[2] = {row0, col0};

    int KT = K >> 5;
    {
#pragma unroll
        for (int t = 0; t < 2; t++) {
#pragma unroll
            for (int cc = 0; cc < 2; cc++) {
                int chunk = tid + cc * 256;
                int row = chunk >> 2, c4 = chunk & 3;
                const void* src = srcs[t] + (size_t)(rbs[t] + row) * K + c4 * 8;
                cpasync16(sb + t * 10240 + row * 80 + c4 * 16, src);
            }
        }
        asm volatile("cp.async.commit_group;" ::: "memory");
    }

    for (int kt = 0; kt < KT; kt++) {
        if (kt + 1 < KT) {
            int buf = (kt + 1) & 1;
#pragma unroll
            for (int t = 0; t < 2; t++) {
#pragma unroll
                for (int cc = 0; cc < 2; cc++) {
                    int chunk = tid + cc * 256;
                    int row = chunk >> 2, c4 = chunk & 3;
                    const void* src = srcs[t] + (size_t)(rbs[t] + row) * K + (kt + 1) * 32 + c4 * 8;
                    cpasync16(sb + buf * KSTAGE + t * 10240 + row * 80 + c4 * 16, src);
                }
            }
            asm volatile("cp.async.commit_group;" ::: "memory");
            asm volatile("cp.async.wait_group 1;" ::: "memory");
        } else {
            asm volatile("cp.async.wait_group 0;" ::: "memory");
        }
        __syncthreads();

        const char* stb = sm + (kt & 1) * KSTAGE;
#pragma unroll
        for (int ks = 0; ks < 2; ks++) {
            int wb = (ks * 8 + tig) * 4;
            uint32_t bh[4][2];
#pragma unroll
            for (int nt = 0; nt < 4; nt++) {
                const char* pb = stb + 10240 + (n0 + nt * 8 + g) * 80 + wb;
                bh[nt][0] = *(const uint32_t*)(pb);
                bh[nt][1] = *(const uint32_t*)(pb + 16);
            }
#pragma unroll
            for (int mt = 0; mt < 4; mt++) {
                const char* pa = stb + (m0 + mt * 16 + g) * 80 + wb;
                uint32_t ah[4];
                ah[0] = *(const uint32_t*)(pa);
                ah[1] = *(const uint32_t*)(pa + 8 * 80);
                ah[2] = *(const uint32_t*)(pa + 16);
                ah[3] = *(const uint32_t*)(pa + 8 * 80 + 16);
#pragma unroll
                for (int nt = 0; nt < 4; nt++)
                    mma16816h(acc[mt][nt], ah, bh[nt]);
            }
        }
        __syncthreads();
    }

#pragma unroll
    for (int mt = 0; mt < 4; mt++) {
        int r0i = row0 + m0 + mt * 16 + g;
#pragma unroll
        for (int nt = 0; nt < 4; nt++) {
            int cc = col0 + n0 + nt * 8 + tig * 2;
            if (cc < N) {
                float* p0 = C + (size_t)r0i * N + cc;
                float* p1 = C + (size_t)(r0i + 8) * N + cc;
                float2 v0 = make_float2(acc[mt][nt][0], acc[mt][nt][1]);
                float2 v1 = make_float2(acc[mt][nt][2], acc[mt][nt][3]);
                if (R) {
                    const float* q0 = R + (size_t)r0i * N + cc;
                    const float* q1 = R + (size_t)(r0i + 8) * N + cc;
                    v0.x += q0[0]; v0.y += q0[1];
                    v1.x += q1[0]; v1.y += q1[1];
                }
                *(float2*)p0 = v0;
                *(float2*)p1 = v1;
            }
        }
    }
}

// ---------------- silu + RoPE ----------------
__global__ __launch_bounds__(256) void bcrope_kernel()
{
    int tid = threadIdx.x;
    int r8 = tid >> 5, n = tid & 31;
    int row = blockIdx.x * 8 + r8;
    int t = row & (LSEQ - 1);
    const float* base = g_zx + (size_t)row * DPROJ;
    float bo, co;
    if (n < 16) {
        int j = n >> 1;
        double invd = exp(-((double)j) * (log(10000.0) / 8.0));
        float inv = (float)invd;
        float ang = (float)t * inv;
        float sn, cs;
        sincosf(ang, &sn, &cs);
        float b1 = siluf(base[4096 + 2 * j]);
        float b2 = siluf(base[4096 + 2 * j + 1]);
        float c1 = siluf(base[4128 + 2 * j]);
        float c2 = siluf(base[4128 + 2 * j + 1]);
        if (n & 1) { bo = b1 * sn + b2 * cs; co = c1 * sn + c2 * cs; }
        else       { bo = b1 * cs - b2 * sn; co = c1 * cs - c2 * sn; }
    } else {
        bo = siluf(base[4096 + n]);
        co = siluf(base[4128 + n]);
    }
    g_Brot[(size_t)row * DS + n] = bo;
    g_Crot[(size_t)row * DS + n] = co;
}

// ---------------- dt + A-cumsum precompute ----------------
__global__ __launch_bounds__(256) void dtacs_kernel(const float* __restrict__ dt_bias,
                                                    const float* __restrict__ A_log)
{
    int bc = blockIdx.x;
    int b = bc >> 6, c = bc & 63;
    int warp = threadIdx.x >> 5, lane = threadIdx.x & 31;
    int rowbase = b * LSEQ + c * 64;
#pragma unroll
    for (int i = 0; i < 4; i++) {
        int h = warp * 4 + i;
        float A = -__expf(A_log[h]);
        float bias = dt_bias[h];
        float raw0 = g_zx[(size_t)(rowbase + lane) * DPROJ + 4160 + h] + bias;
        float raw1 = g_zx[(size_t)(rowbase + 32 + lane) * DPROJ + 4160 + h] + bias;
        float dt0 = (raw0 > 20.f) ? raw0 : log1pf(__expf(raw0));
        float dt1 = (raw1 > 20.f) ? raw1 : log1pf(__expf(raw1));
        float a0 = dt0 * A, a1 = dt1 * A;
#pragma unroll
        for (int o = 1; o < 32; o <<= 1) {
            float t = __shfl_up_sync(0xffffffffu, a0, o);
            if (lane >= o) a0 += t;
        }
#pragma unroll
        for (int o = 1; o < 32; o <<= 1) {
            float t = __shfl_up_sync(0xffffffffu, a1, o);
            if (lane >= o) a1 += t;
        }
        a1 += __shfl_sync(0xffffffffu, a0, 31);
        size_t base = ((size_t)(b * NH + h)) * LSEQ + c * 64;
        g_dtv[base + lane] = dt0;      g_dtv[base + 32 + lane] = dt1;
        g_acs[base + lane] = a0;       g_acs[base + 32 + lane] = a1;
    }
}

// ---------------- scores: per (b,c), masked C.B^T ----------------
__global__ __launch_bounds__(256) void score_kernel()
{
    int bc = blockIdx.x;
    int b = bc >> 6, c = bc & 63;
    __shared__ float Cs[64][33], Bsm[64][33];
    int tid = threadIdx.x;
    int rowbase = b * LSEQ + c * 64;
    for (int i = tid; i < 64 * 32; i += 256) {
        int l = i >> 5, n = i & 31;
        Bsm[l][n] = g_Brot[(size_t)(rowbase + l) * DS + n];
        Cs[l][n]  = g_Crot[(size_t)(rowbase + l) * DS + n];
    }
    __syncthreads();
    int l = tid >> 2, sq = tid & 3;
    float cr[32];
#pragma unroll
    for (int n = 0; n < 32; n++) cr[n] = Cs[l][n];
    float out[16];
#pragma unroll
    for (int k = 0; k < 16; k++) {
        int s = sq * 16 + k;
        float d = 0.f;
        if (s <= l) {
#pragma unroll
            for (int n = 0; n < 32; n++) d = fmaf(cr[n], Bsm[s][n], d);
        }
        out[k] = d;
    }
    float* dst = g_scores + (size_t)bc * 4096 + l * 64 + sq * 16;
#pragma unroll
    for (int k = 0; k < 16; k += 4)
        *(float4*)(dst + k) = make_float4(out[k], out[k + 1], out[k + 2], out[k + 3]);
}

// ---------------- SSD intra-chunk: fp16 1-pass Yd + states ----------------
__global__ __launch_bounds__(256) void chunk_kernel(const float* __restrict__ Dv)
{
    int blk = blockIdx.x;
    int h = blk & 31; int bcid = blk >> 5; int c = bcid & 63; int b = bcid >> 6;
    __shared__ unsigned short Mh[64][72];       // plain fp16
    __shared__ unsigned short XTh[64][72];      // [p][l] plain fp16
    __shared__ unsigned short BwTh[32][72];     // [n][l] plain fp16
    __shared__ float acs[64], dtv[64], wvv[64];
    int tid = threadIdx.x;
    int rowbase = b * LSEQ + c * 64;

    if (tid < 64) {
        size_t dbase = ((size_t)(b * NH + h)) * LSEQ + c * 64;
        dtv[tid] = g_dtv[dbase + tid];
        acs[tid] = g_acs[dbase + tid];
    }
    __syncthreads();
    if (tid < 64) wvv[tid] = dtv[tid] * __expf(acs[63] - acs[tid]);
    for (int i = tid; i < 4096; i += 256) {
        int l = i >> 6, p = i & 63;
        float v = siluf(g_zx[(size_t)(rowbase + l) * DPROJ + 2048 + h * 64 + p]);
        XTh[p][l] = f2h(v);
    }
    const float* psrc = g_scores + (size_t)(b * NC + c) * 4096;
    for (int i = tid; i < 4096; i += 256) {
        int l = i >> 6, s = i & 63;
        float m = 0.f;
        if (s <= l) m = psrc[i] * __expf(acs[l] - acs[s]) * dtv[s];
        Mh[l][s] = f2h(m);
    }
    __syncthreads();   // wvv ready
    for (int i = tid; i < 2048; i += 256) {
        int l = i >> 5, n = i & 31;
        float v = g_Brot[(size_t)(rowbase + l) * DS + n] * wvv[l];
        BwTh[n][l] = f2h(v);
    }
    __syncthreads();

    int lane = tid & 31, w = tid >> 5;
    int g = lane >> 2, tig = lane & 3;

    // ---- Yd = M @ X (64x64x64), 1-pass ----
    {
        int m0 = (w & 3) * 16, n0 = (w >> 2) * 32;
        float acc[4][4];
#pragma unroll
        for (int i = 0; i < 4; i++)
#pragma unroll
            for (int q = 0; q < 4; q++) acc[i][q] = 0.f;
#pragma unroll
        for (int kt = 0; kt < 4; kt++) {
            int col = kt * 16 + 2 * tig;
            uint32_t ah[4];
            ldfragA<72>(ah, Mh, m0 + g, col);
#pragma unroll
            for (int nt = 0; nt < 4; nt++) {
                uint32_t bh[2];
                ldfragB<72>(bh, XTh, n0 + nt * 8 + g, col);
                mma16816h(acc[nt], ah, bh);
            }
        }
        float Dh = Dv[h];
#pragma unroll
        for (int nt = 0; nt < 4; nt++) {
            int p0 = n0 + nt * 8 + 2 * tig;
            int l0 = m0 + g, l1 = l0 + 8;
            float x00 = h2f(XTh[p0][l0]);
            float x01 = h2f(XTh[p0 + 1][l0]);
            float x10 = h2f(XTh[p0][l1]);
            float x11 = h2f(XTh[p0 + 1][l1]);
            float* y0 = g_y + (size_t)(rowbase + l0) * DIN + h * HD + p0;
            float* y1 = g_y + (size_t)(rowbase + l1) * DIN + h * HD + p0;
            *(float2*)y0 = make_float2(acc[nt][0] + Dh * x00, acc[nt][1] + Dh * x01);
            *(float2*)y1 = make_float2(acc[nt][2] + Dh * x10, acc[nt][3] + Dh * x11);
        }
    }

    // ---- states = X^T @ Bw (64x32x64), 1-pass ----
    {
        int m0 = (w & 3) * 16;       // p
        int n0 = (w >> 2) * 16;      // n
        float acc[2][4];
#pragma unroll
        for (int i = 0; i < 2; i++)
#pragma unroll
            for (int q = 0; q < 4; q++) acc[i][q] = 0.f;
#pragma unroll
        for (int kt = 0; kt < 4; kt++) {
            int col = kt * 16 + 2 * tig;
            uint32_t ah[4];
            ldfragA<72>(ah, XTh, m0 + g, col);
#pragma unroll
            for (int nt = 0; nt < 2; nt++) {
                uint32_t bh[2];
                ldfragB<72>(bh, BwTh, n0 + nt * 8 + g, col);
                mma16816h(acc[nt], ah, bh);
            }
        }
        size_t sbase = ((size_t)((b * NC + c) * NH + h)) * (HD * DS);
#pragma unroll
        for (int nt = 0; nt < 2; nt++) {
            int nn = n0 + nt * 8 + 2 * tig;
            int p0 = m0 + g, p1 = p0 + 8;
            *(float2*)&g_states[sbase + p0 * DS + nn] = make_float2(acc[nt][0], acc[nt][1]);
            *(float2*)&g_states[sbase + p1 * DS + nn] = make_float2(acc[nt][2], acc[nt][3]);
        }
    }
}

// ---------------- inter-chunk scan: 1 elem/thread, prefetched ----------------
__global__ __launch_bounds__(256) void scan_kernel()
{
    int bh = blockIdx.x >> 3;
    int e = (blockIdx.x & 7) * 256 + threadIdx.x;
    int b = bh >> 5, h = bh & 31;
    __shared__ float ec[64];
    if (threadIdx.x < 64) {
        float cs = g_acs[(size_t)bh * LSEQ + threadIdx.x * 64 + 63];
        ec[threadIdx.x] = __expf(cs);
    }
    __syncthreads();
    size_t stride = (size_t)NH * HD * DS;
    size_t base = ((size_t)(b * NC) * NH + h) * (HD * DS) + e;
    float S = 0.f;
    float nxt = g_states[base];
#pragma unroll 4
    for (int c = 0; c < NC; c++) {
        g_stin[base] = S;
        float cur = nxt;
        if (c + 1 < NC) nxt = g_states[base + stride];
        S = fmaf(S, ec[c], cur);
        base += stride;
    }
}

// ---------------- Yo = C @ S^T (64x64x32), fp16 1-pass, y += exp(acs)*Yo ----------------
__global__ __launch_bounds__(256) void yo_kernel()
{
    int blk = blockIdx.x;
    int h = blk & 31; int bcid = blk >> 5; int c = bcid & 63; int b = bcid >> 6;
    __shared__ unsigned short Ch[64][40];   // plain fp16
    __shared__ unsigned short Sh[64][40];   // plain fp16
    __shared__ float acs[64];
    int tid = threadIdx.x;
    int rowbase = b * LSEQ + c * 64;

    if (tid < 64) {
        size_t dbase = ((size_t)(b * NH + h)) * LSEQ + c * 64;
        acs[tid] = g_acs[dbase + tid];
    }
    size_t sbase = ((size_t)((b * NC + c) * NH + h)) * (HD * DS);
    for (int i = tid; i < 2048; i += 256) {
        int l = i >> 5, n = i & 31;
        Ch[l][n] = f2h(g_Crot[(size_t)(rowbase + l) * DS + n]);
        Sh[l][n] = f2h(g_stin[sbase + i]);
    }
    __syncthreads();

    int lane = tid & 31, w = tid >> 5;
    int g = lane >> 2, tig = lane & 3;
    int m0 = (w & 3) * 16, n0 = (w >> 2) * 32;
    float acc[4][4];
#pragma unroll
    for (int i = 0; i < 4; i++)
#pragma unroll
        for (int q = 0; q < 4; q++) acc[i][q] = 0.f;
#pragma unroll
    for (int kt = 0; kt < 2; kt++) {
        int col = kt * 16 + 2 * tig;
        uint32_t ah[4];
        ldfragA<40>(ah, Ch, m0 + g, col);
#pragma unroll
        for (int nt = 0; nt < 4; nt++) {
            uint32_t bh[2];
            ldfragB<40>(bh, Sh, n0 + nt * 8 + g, col);
            mma16816h(acc[nt], ah, bh);
        }
    }
    int l0 = m0 + g, l1 = l0 + 8;
    float el0 = __expf(acs[l0]), el1 = __expf(acs[l1]);
#pragma unroll
    for (int nt = 0; nt < 4; nt++) {
        int p0 = n0 + nt * 8 + 2 * tig;
        float* y0 = g_y + (size_t)(rowbase + l0) * DIN + h * HD + p0;
        float* y1 = g_y + (size_t)(rowbase + l1) * DIN + h * HD + p0;
        float2 v0 = *(float2*)y0, v1 = *(float2*)y1;
        v0.x += el0 * acc[nt][0]; v0.y += el0 * acc[nt][1];
        v1.x += el1 * acc[nt][2]; v1.y += el1 * acc[nt][3];
        *(float2*)y0 = v0;
        *(float2*)y1 = v1;
    }
}

// ---------------- gate + RMSNorm -> fp16 A ----------------
__global__ __launch_bounds__(256) void gate_kernel(const float* __restrict__ rms_w)
{
    int row = blockIdx.x;
    int tid = threadIdx.x;
    const float* yr = g_y + (size_t)row * DIN;
    const float* zr = g_zx + (size_t)row * DPROJ;
    float v[8]; float s2 = 0.f;
#pragma unroll
    for (int i = 0; i < 8; i++) {
        int idx = tid + i * 256;
        float y = yr[idx];
        float z = zr[idx];
        y *= siluf(z);
        v[i] = y;
        s2 = fmaf(y, y, s2);
    }
    for (int o = 16; o; o >>= 1) s2 += __shfl_down_sync(0xffffffffu, s2, o);
    __shared__ float red[8];
    if ((tid & 31) == 0) red[tid >> 5] = s2;
    __syncthreads();
    if (tid == 0) {
        float t = 0.f;
        for (int i = 0; i < 8; i++) t += red[i];
        red[0] = rsqrtf(t / DIN + 1e-6f);
    }
    __syncthreads();
    float sc = red[0];
    size_t base = (size_t)row * DIN;
#pragma unroll
    for (int i = 0; i < 8; i++) {
        int idx = tid + i * 256;
        g_Ahf[base + idx] = f2h(v[i] * sc * rms_w[idx]);
    }
}

// ---------------- launch ----------------
extern "C" void kernel_launch(void* const* d_in, const int* in_sizes, int n_in,
                              void* d_out, int out_size)
{
    (void)in_sizes; (void)n_in; (void)out_size;
    const float* x       = (const float*)d_in[0];
    const float* ln_w    = (const float*)d_in[1];
    const float* ln_b    = (const float*)d_in[2];
    const float* W_in    = (const float*)d_in[3];
    const float* dt_bias = (const float*)d_in[4];
    const float* A_log   = (const float*)d_in[5];
    const float* Dv      = (const float*)d_in[6];
    const float* rms_w   = (const float*)d_in[7];
    const float* W_out   = (const float*)d_in[8];
    float* out = (float*)d_out;

    void *pzx, *pA, *pB;
    cudaGetSymbolAddress(&pzx, g_zx);
    cudaGetSymbolAddress(&pA,  g_Ahf);
    cudaGetSymbolAddress(&pB,  g_Bthi);

    static int attr_done = 0;
    if (!attr_done) {
        cudaFuncSetAttribute(mma_gemm, cudaFuncAttributeMaxDynamicSharedMemorySize, SMEM_GEMM);
        attr_done = 1;
    }

    ln_kernel<<<MROWS, 256>>>(x, ln_w, ln_b);
    cvtT_kernel<<<dim3(DIMX / 32, NPAD_IN / 32), dim3(32, 32)>>>(W_in, DIMX, DPROJ);
    mma_gemm<<<dim3(33, 128), 256, SMEM_GEMM>>>(
        (const unsigned short*)pA, (const unsigned short*)pB,
        (const float*)0, (float*)pzx, DPROJ, DIMX);
    bcrope_kernel<<<MROWS / 8, 256>>>();
    dtacs_kernel<<<4 * NC, 256>>>(dt_bias, A_log);
    score_kernel<<<4 * NC, 256>>>();
    chunk_kernel<<<4 * NC * NH, 256>>>(Dv);
    scan_kernel<<<4 * NH * 8, 256>>>();
    yo_kernel<<<4 * NC * NH, 256>>>();
    gate_kernel<<<MROWS, 256>>>(rms_w);
    cvtT_kernel<<<dim3(DIN / 32, DIMX / 32), dim3(32, 32)>>>(W_out, DIN, DIMX);
    mma_gemm<<<dim3(8, 128), 256, SMEM_GEMM>>>(
        (const unsigned short*)pA, (const unsigned short*)pB,
        x, out, DIMX, DIN);
}

// round 14
// speedup vs baseline: 3.1424x; 1.0126x over previous
#include <cuda_runtime.h>
#include <cuda_bf16.h>
#include <cuda_fp16.h>
#include <math.h>
#include <stdint.h>

#define MROWS 16384
#define DIMX 1024
#define DPROJ 4192
#define DIN 2048
#define NH 32
#define HD 64
#define DS 32
#define LSEQ 4096
#define NC 64
#define NPAD_IN 4224

// ---------------- scratch ----------------
__device__ unsigned short g_zxh[(size_t)MROWS * DPROJ];    // fp16 in-proj output
__device__ float g_dtraw[(size_t)MROWS * 32];              // fp32 dt columns
__device__ float g_Brot[(size_t)MROWS * DS];
__device__ float g_Crot[(size_t)MROWS * DS];
__device__ float g_states[(size_t)4 * NC * NH * HD * DS];
__device__ float g_stin[(size_t)4 * NC * NH * HD * DS];
__device__ float g_y[(size_t)MROWS * DIN];
__device__ float g_scores[(size_t)4 * NC * 64 * 64];
__device__ float g_dtv[(size_t)4 * NH * LSEQ];
__device__ float g_acs[(size_t)4 * NH * LSEQ];
__device__ unsigned short g_Ahf[(size_t)MROWS * DIN];
__device__ unsigned short g_Bthi[(size_t)NPAD_IN * 1024];

__device__ __forceinline__ float siluf(float x) { return x / (1.f + __expf(-x)); }

__device__ __forceinline__ unsigned short f2h(float f) {
    __half h = __float2half(f);
    return *reinterpret_cast<unsigned short*>(&h);
}
__device__ __forceinline__ float h2f(unsigned short u) {
    __half h = *reinterpret_cast<__half*>(&u);
    return __half2float(h);
}

__device__ __forceinline__ uint32_t smem_u32(const void* p) {
    uint32_t a;
    asm("{ .reg .u64 t; cvta.to.shared.u64 t, %1; cvt.u32.u64 %0, t; }" : "=r"(a) : "l"(p));
    return a;
}
__device__ __forceinline__ void cpasync16(uint32_t dst, const void* src) {
    asm volatile("cp.async.cg.shared.global [%0], [%1], 16;" :: "r"(dst), "l"(src) : "memory");
}
__device__ __forceinline__ void mma16816h(float* c, const uint32_t* a, const uint32_t* b) {
    asm volatile(
        "mma.sync.aligned.m16n8k16.row.col.f32.f16.f16.f32 "
        "{%0,%1,%2,%3}, {%4,%5,%6,%7}, {%8,%9}, {%0,%1,%2,%3};\n"
        : "+f"(c[0]), "+f"(c[1]), "+f"(c[2]), "+f"(c[3])
        : "r"(a[0]), "r"(a[1]), "r"(a[2]), "r"(a[3]), "r"(b[0]), "r"(b[1]));
}
template<int P>
__device__ __forceinline__ void ldfragA(uint32_t* a, const unsigned short (*S)[P], int row, int col) {
    a[0] = *(const uint32_t*)&S[row][col];
    a[1] = *(const uint32_t*)&S[row + 8][col];
    a[2] = *(const uint32_t*)&S[row][col + 8];
    a[3] = *(const uint32_t*)&S[row + 8][col + 8];
}
template<int P>
__device__ __forceinline__ void ldfragB(uint32_t* bb, const unsigned short (*S)[P], int row, int col) {
    bb[0] = *(const uint32_t*)&S[row][col];
    bb[1] = *(const uint32_t*)&S[row][col + 8];
}

// ---------------- LayerNorm -> fp16 A ----------------
__global__ __launch_bounds__(256) void ln_kernel(const float* __restrict__ x,
                                                 const float* __restrict__ w,
                                                 const float* __restrict__ b)
{
    int row = blockIdx.x;
    int tid = threadIdx.x;
    const float* xr = x + (size_t)row * DIMX;
    float4 v = *(const float4*)(xr + tid * 4);
    float s  = v.x + v.y + v.z + v.w;
    float s2 = v.x*v.x + v.y*v.y + v.z*v.z + v.w*v.w;
    for (int o = 16; o; o >>= 1) {
        s  += __shfl_down_sync(0xffffffffu, s,  o);
        s2 += __shfl_down_sync(0xffffffffu, s2, o);
    }
    __shared__ float ss[8], ss2[8];
    if ((tid & 31) == 0) { ss[tid >> 5] = s; ss2[tid >> 5] = s2; }
    __syncthreads();
    if (tid == 0) {
        float t = 0.f, t2 = 0.f;
        for (int i = 0; i < 8; i++) { t += ss[i]; t2 += ss2[i]; }
        float mu = t / DIMX;
        ss[0]  = mu;
        ss2[0] = rsqrtf(t2 / DIMX - mu * mu + 1e-6f);
    }
    __syncthreads();
    float mu = ss[0], inv = ss2[0];
    int i0 = tid * 4;
    float4 wv = *(const float4*)(w + i0);
    float4 bv = *(const float4*)(b + i0);
    ushort4 hv;
    hv.x = f2h((v.x - mu) * inv * wv.x + bv.x);
    hv.y = f2h((v.y - mu) * inv * wv.y + bv.y);
    hv.z = f2h((v.z - mu) * inv * wv.z + bv.z);
    hv.w = f2h((v.w - mu) * inv * wv.w + bv.w);
    *(ushort4*)(g_Ahf + (size_t)row * DIMX + i0) = hv;
}

// ---------------- W[K,N] -> Bt[n][k] fp16 ----------------
__global__ __launch_bounds__(1024) void cvtT_kernel(const float* __restrict__ W, int K, int N)
{
    __shared__ float t[32][33];
    int k0 = blockIdx.x * 32, n0 = blockIdx.y * 32;
    int tx = threadIdx.x, ty = threadIdx.y;
    int n = n0 + tx;
    t[ty][tx] = (n < N) ? W[(size_t)(k0 + ty) * N + n] : 0.f;
    __syncthreads();
    g_Bthi[(size_t)(n0 + ty) * K + k0 + tx] = f2h(t[tx][ty]);
}

// ---------------- mma.sync fp16 GEMM, 1-pass; 2 CTAs/SM ----------------
// If Ch != null: store fp16 to Ch; cols >= 4160 also stored fp32 to dtraw.
// Else: store fp32 to Cf (+ optional residual R).
#define KSTAGE 20480
#define SMEM_GEMM (2 * KSTAGE)
__global__ __launch_bounds__(256, 2) void mma_gemm(
    const unsigned short* __restrict__ A,
    const unsigned short* __restrict__ B,
    const float* __restrict__ R, float* __restrict__ Cf,
    unsigned short* __restrict__ Ch, float* __restrict__ dtraw,
    int N, int K)
{
    extern __shared__ char sm[];
    int tid = threadIdx.x, lane = tid & 31, wid = tid >> 5;
    int col0 = blockIdx.x * 128, row0 = blockIdx.y * 128;
    int g = lane >> 2, tig = lane & 3;
    int m0 = (wid >> 2) * 64, n0 = (wid & 3) * 32;
    uint32_t sb = smem_u32(sm);

    float acc[4][4][4];
#pragma unroll
    for (int i = 0; i < 4; i++)
#pragma unroll
        for (int j = 0; j < 4; j++)
#pragma unroll
            for (int q = 0; q < 4; q++) acc[i][j][q] = 0.f;

    const unsigned short* srcs[2] = {A, B};
    int rbs[2] = {row0, col0};

    int KT = K >> 5;
    {
#pragma unroll
        for (int t = 0; t < 2; t++) {
#pragma unroll
            for (int cc = 0; cc < 2; cc++) {
                int chunk = tid + cc * 256;
                int row = chunk >> 2, c4 = chunk & 3;
                const void* src = srcs[t] + (size_t)(rbs[t] + row) * K + c4 * 8;
                cpasync16(sb + t * 10240 + row * 80 + c4 * 16, src);
            }
        }
        asm volatile("cp.async.commit_group;" ::: "memory");
    }

    for (int kt = 0; kt < KT; kt++) {
        if (kt + 1 < KT) {
            int buf = (kt + 1) & 1;
#pragma unroll
            for (int t = 0; t < 2; t++) {
#pragma unroll
                for (int cc = 0; cc < 2; cc++) {
                    int chunk = tid + cc * 256;
                    int row = chunk >> 2, c4 = chunk & 3;
                    const void* src = srcs[t] + (size_t)(rbs[t] + row) * K + (kt + 1) * 32 + c4 * 8;
                    cpasync16(sb + buf * KSTAGE + t * 10240 + row * 80 + c4 * 16, src);
                }
            }
            asm volatile("cp.async.commit_group;" ::: "memory");
            asm volatile("cp.async.wait_group 1;" ::: "memory");
        } else {
            asm volatile("cp.async.wait_group 0;" ::: "memory");
        }
        __syncthreads();

        const char* stb = sm + (kt & 1) * KSTAGE;
#pragma unroll
        for (int ks = 0; ks < 2; ks++) {
            int wb = (ks * 8 + tig) * 4;
            uint32_t bh[4][2];
#pragma unroll
            for (int nt = 0; nt < 4; nt++) {
                const char* pb = stb + 10240 + (n0 + nt * 8 + g) * 80 + wb;
                bh[nt][0] = *(const uint32_t*)(pb);
                bh[nt][1] = *(const uint32_t*)(pb + 16);
            }
#pragma unroll
            for (int mt = 0; mt < 4; mt++) {
                const char* pa = stb + (m0 + mt * 16 + g) * 80 + wb;
                uint32_t ah[4];
                ah[0] = *(const uint32_t*)(pa);
                ah[1] = *(const uint32_t*)(pa + 8 * 80);
                ah[2] = *(const uint32_t*)(pa + 16);
                ah[3] = *(const uint32_t*)(pa + 8 * 80 + 16);
#pragma unroll
                for (int nt = 0; nt < 4; nt++)
                    mma16816h(acc[mt][nt], ah, bh[nt]);
            }
        }
        __syncthreads();
    }

#pragma unroll
    for (int mt = 0; mt < 4; mt++) {
        int r0i = row0 + m0 + mt * 16 + g;
#pragma unroll
        for (int nt = 0; nt < 4; nt++) {
            int cc = col0 + n0 + nt * 8 + tig * 2;
            if (cc < N) {
                if (Ch) {
                    uint32_t p0 = (uint32_t)f2h(acc[mt][nt][0]) | ((uint32_t)f2h(acc[mt][nt][1]) << 16);
                    uint32_t p1 = (uint32_t)f2h(acc[mt][nt][2]) | ((uint32_t)f2h(acc[mt][nt][3]) << 16);
                    *(uint32_t*)&Ch[(size_t)r0i * N + cc]       = p0;
                    *(uint32_t*)&Ch[(size_t)(r0i + 8) * N + cc] = p1;
                    if (cc >= 4160) {
                        int dc = cc - 4160;
                        *(float2*)&dtraw[(size_t)r0i * 32 + dc] =
                            make_float2(acc[mt][nt][0], acc[mt][nt][1]);
                        *(float2*)&dtraw[(size_t)(r0i + 8) * 32 + dc] =
                            make_float2(acc[mt][nt][2], acc[mt][nt][3]);
                    }
                } else {
                    float* p0 = Cf + (size_t)r0i * N + cc;
                    float* p1 = Cf + (size_t)(r0i + 8) * N + cc;
                    float2 v0 = make_float2(acc[mt][nt][0], acc[mt][nt][1]);
                    float2 v1 = make_float2(acc[mt][nt][2], acc[mt][nt][3]);
                    if (R) {
                        const float* q0 = R + (size_t)r0i * N + cc;
                        const float* q1 = R + (size_t)(r0i + 8) * N + cc;
                        v0.x += q0[0]; v0.y += q0[1];
                        v1.x += q1[0]; v1.y += q1[1];
                    }
                    *(float2*)p0 = v0;
                    *(float2*)p1 = v1;
                }
            }
        }
    }
}

// ---------------- silu + RoPE (fp16 in) ----------------
__global__ __launch_bounds__(256) void bcrope_kernel()
{
    int tid = threadIdx.x;
    int r8 = tid >> 5, n = tid & 31;
    int row = blockIdx.x * 8 + r8;
    int t = row & (LSEQ - 1);
    const unsigned short* base = g_zxh + (size_t)row * DPROJ;
    float bo, co;
    if (n < 16) {
        int j = n >> 1;
        double invd = exp(-((double)j) * (log(10000.0) / 8.0));
        float inv = (float)invd;
        float ang = (float)t * inv;
        float sn, cs;
        sincosf(ang, &sn, &cs);
        float b1 = siluf(h2f(base[4096 + 2 * j]));
        float b2 = siluf(h2f(base[4096 + 2 * j + 1]));
        float c1 = siluf(h2f(base[4128 + 2 * j]));
        float c2 = siluf(h2f(base[4128 + 2 * j + 1]));
        if (n & 1) { bo = b1 * sn + b2 * cs; co = c1 * sn + c2 * cs; }
        else       { bo = b1 * cs - b2 * sn; co = c1 * cs - c2 * sn; }
    } else {
        bo = siluf(h2f(base[4096 + n]));
        co = siluf(h2f(base[4128 + n]));
    }
    g_Brot[(size_t)row * DS + n] = bo;
    g_Crot[(size_t)row * DS + n] = co;
}

// ---------------- dt + A-cumsum precompute (fp32 dt) ----------------
__global__ __launch_bounds__(256) void dtacs_kernel(const float* __restrict__ dt_bias,
                                                    const float* __restrict__ A_log)
{
    int bc = blockIdx.x;
    int b = bc >> 6, c = bc & 63;
    int warp = threadIdx.x >> 5, lane = threadIdx.x & 31;
    int rowbase = b * LSEQ + c * 64;
#pragma unroll
    for (int i = 0; i < 4; i++) {
        int h = warp * 4 + i;
        float A = -__expf(A_log[h]);
        float bias = dt_bias[h];
        float raw0 = g_dtraw[(size_t)(rowbase + lane) * 32 + h] + bias;
        float raw1 = g_dtraw[(size_t)(rowbase + 32 + lane) * 32 + h] + bias;
        float dt0 = (raw0 > 20.f) ? raw0 : log1pf(__expf(raw0));
        float dt1 = (raw1 > 20.f) ? raw1 : log1pf(__expf(raw1));
        float a0 = dt0 * A, a1 = dt1 * A;
#pragma unroll
        for (int o = 1; o < 32; o <<= 1) {
            float t = __shfl_up_sync(0xffffffffu, a0, o);
            if (lane >= o) a0 += t;
        }
#pragma unroll
        for (int o = 1; o < 32; o <<= 1) {
            float t = __shfl_up_sync(0xffffffffu, a1, o);
            if (lane >= o) a1 += t;
        }
        a1 += __shfl_sync(0xffffffffu, a0, 31);
        size_t base = ((size_t)(b * NH + h)) * LSEQ + c * 64;
        g_dtv[base + lane] = dt0;      g_dtv[base + 32 + lane] = dt1;
        g_acs[base + lane] = a0;       g_acs[base + 32 + lane] = a1;
    }
}

// ---------------- scores: per (b,c), masked C.B^T ----------------
__global__ __launch_bounds__(256) void score_kernel()
{
    int bc = blockIdx.x;
    int b = bc >> 6, c = bc & 63;
    __shared__ float Cs[64][33], Bsm[64][33];
    int tid = threadIdx.x;
    int rowbase = b * LSEQ + c * 64;
    for (int i = tid; i < 64 * 32; i += 256) {
        int l = i >> 5, n = i & 31;
        Bsm[l][n] = g_Brot[(size_t)(rowbase + l) * DS + n];
        Cs[l][n]  = g_Crot[(size_t)(rowbase + l) * DS + n];
    }
    __syncthreads();
    int l = tid >> 2, sq = tid & 3;
    float cr[32];
#pragma unroll
    for (int n = 0; n < 32; n++) cr[n] = Cs[l][n];
    float out[16];
#pragma unroll
    for (int k = 0; k < 16; k++) {
        int s = sq * 16 + k;
        float d = 0.f;
        if (s <= l) {
#pragma unroll
            for (int n = 0; n < 32; n++) d = fmaf(cr[n], Bsm[s][n], d);
        }
        out[k] = d;
    }
    float* dst = g_scores + (size_t)bc * 4096 + l * 64 + sq * 16;
#pragma unroll
    for (int k = 0; k < 16; k += 4)
        *(float4*)(dst + k) = make_float4(out[k], out[k + 1], out[k + 2], out[k + 3]);
}

// ---------------- SSD intra-chunk: fp16 1-pass Yd + states ----------------
__global__ __launch_bounds__(256) void chunk_kernel(const float* __restrict__ Dv)
{
    int blk = blockIdx.x;
    int h = blk & 31; int bcid = blk >> 5; int c = bcid & 63; int b = bcid >> 6;
    __shared__ unsigned short Mh[64][72];
    __shared__ unsigned short XTh[64][72];
    __shared__ unsigned short BwTh[32][72];
    __shared__ float acs[64], dtv[64], wvv[64];
    int tid = threadIdx.x;
    int rowbase = b * LSEQ + c * 64;

    if (tid < 64) {
        size_t dbase = ((size_t)(b * NH + h)) * LSEQ + c * 64;
        dtv[tid] = g_dtv[dbase + tid];
        acs[tid] = g_acs[dbase + tid];
    }
    __syncthreads();
    if (tid < 64) wvv[tid] = dtv[tid] * __expf(acs[63] - acs[tid]);
    for (int i = tid; i < 4096; i += 256) {
        int l = i >> 6, p = i & 63;
        float v = siluf(h2f(g_zxh[(size_t)(rowbase + l) * DPROJ + 2048 + h * 64 + p]));
        XTh[p][l] = f2h(v);
    }
    const float* psrc = g_scores + (size_t)(b * NC + c) * 4096;
    for (int i = tid; i < 4096; i += 256) {
        int l = i >> 6, s = i & 63;
        float m = 0.f;
        if (s <= l) m = psrc[i] * __expf(acs[l] - acs[s]) * dtv[s];
        Mh[l][s] = f2h(m);
    }
    __syncthreads();
    for (int i = tid; i < 2048; i += 256) {
        int l = i >> 5, n = i & 31;
        float v = g_Brot[(size_t)(rowbase + l) * DS + n] * wvv[l];
        BwTh[n][l] = f2h(v);
    }
    __syncthreads();

    int lane = tid & 31, w = tid >> 5;
    int g = lane >> 2, tig = lane & 3;

    // ---- Yd = M @ X (64x64x64), 1-pass ----
    {
        int m0 = (w & 3) * 16, n0 = (w >> 2) * 32;
        float acc[4][4];
#pragma unroll
        for (int i = 0; i < 4; i++)
#pragma unroll
            for (int q = 0; q < 4; q++) acc[i][q] = 0.f;
#pragma unroll
        for (int kt = 0; kt < 4; kt++) {
            int col = kt * 16 + 2 * tig;
            uint32_t ah[4];
            ldfragA<72>(ah, Mh, m0 + g, col);
#pragma unroll
            for (int nt = 0; nt < 4; nt++) {
                uint32_t bh[2];
                ldfragB<72>(bh, XTh, n0 + nt * 8 + g, col);
                mma16816h(acc[nt], ah, bh);
            }
        }
        float Dh = Dv[h];
#pragma unroll
        for (int nt = 0; nt < 4; nt++) {
            int p0 = n0 + nt * 8 + 2 * tig;
            int l0 = m0 + g, l1 = l0 + 8;
            float x00 = h2f(XTh[p0][l0]);
            float x01 = h2f(XTh[p0 + 1][l0]);
            float x10 = h2f(XTh[p0][l1]);
            float x11 = h2f(XTh[p0 + 1][l1]);
            float* y0 = g_y + (size_t)(rowbase + l0) * DIN + h * HD + p0;
            float* y1 = g_y + (size_t)(rowbase + l1) * DIN + h * HD + p0;
            *(float2*)y0 = make_float2(acc[nt][0] + Dh * x00, acc[nt][1] + Dh * x01);
            *(float2*)y1 = make_float2(acc[nt][2] + Dh * x10, acc[nt][3] + Dh * x11);
        }
    }

    // ---- states = X^T @ Bw (64x32x64), 1-pass ----
    {
        int m0 = (w & 3) * 16;
        int n0 = (w >> 2) * 16;
        float acc[2][4];
#pragma unroll
        for (int i = 0; i < 2; i++)
#pragma unroll
            for (int q = 0; q < 4; q++) acc[i][q] = 0.f;
#pragma unroll
        for (int kt = 0; kt < 4; kt++) {
            int col = kt * 16 + 2 * tig;
            uint32_t ah[4];
            ldfragA<72>(ah, XTh, m0 + g, col);
#pragma unroll
            for (int nt = 0; nt < 2; nt++) {
                uint32_t bh[2];
                ldfragB<72>(bh, BwTh, n0 + nt * 8 + g, col);
                mma16816h(acc[nt], ah, bh);
            }
        }
        size_t sbase = ((size_t)((b * NC + c) * NH + h)) * (HD * DS);
#pragma unroll
        for (int nt = 0; nt < 2; nt++) {
            int nn = n0 + nt * 8 + 2 * tig;
            int p0 = m0 + g, p1 = p0 + 8;
            *(float2*)&g_states[sbase + p0 * DS + nn] = make_float2(acc[nt][0], acc[nt][1]);
            *(float2*)&g_states[sbase + p1 * DS + nn] = make_float2(acc[nt][2], acc[nt][3]);
        }
    }
}

// ---------------- inter-chunk scan ----------------
__global__ __launch_bounds__(256) void scan_kernel()
{
    int bh = blockIdx.x >> 3;
    int e = (blockIdx.x & 7) * 256 + threadIdx.x;
    int b = bh >> 5, h = bh & 31;
    __shared__ float ec[64];
    if (threadIdx.x < 64) {
        float cs = g_acs[(size_t)bh * LSEQ + threadIdx.x * 64 + 63];
        ec[threadIdx.x] = __expf(cs);
    }
    __syncthreads();
    size_t stride = (size_t)NH * HD * DS;
    size_t base = ((size_t)(b * NC) * NH + h) * (HD * DS) + e;
    float S = 0.f;
    float nxt = g_states[base];
#pragma unroll 4
    for (int c = 0; c < NC; c++) {
        g_stin[base] = S;
        float cur = nxt;
        if (c + 1 < NC) nxt = g_states[base + stride];
        S = fmaf(S, ec[c], cur);
        base += stride;
    }
}

// ---------------- Yo = C @ S^T, fp16 1-pass, y += exp(acs)*Yo ----------------
__global__ __launch_bounds__(256) void yo_kernel()
{
    int blk = blockIdx.x;
    int h = blk & 31; int bcid = blk >> 5; int c = bcid & 63; int b = bcid >> 6;
    __shared__ unsigned short Ch[64][40];
    __shared__ unsigned short Sh[64][40];
    __shared__ float acs[64];
    int tid = threadIdx.x;
    int rowbase = b * LSEQ + c * 64;

    if (tid < 64) {
        size_t dbase = ((size_t)(b * NH + h)) * LSEQ + c * 64;
        acs[tid] = g_acs[dbase + tid];
    }
    size_t sbase = ((size_t)((b * NC + c) * NH + h)) * (HD * DS);
    for (int i = tid; i < 2048; i += 256) {
        int l = i >> 5, n = i & 31;
        Ch[l][n] = f2h(g_Crot[(size_t)(rowbase + l) * DS + n]);
        Sh[l][n] = f2h(g_stin[sbase + i]);
    }
    __syncthreads();

    int lane = tid & 31, w = tid >> 5;
    int g = lane >> 2, tig = lane & 3;
    int m0 = (w & 3) * 16, n0 = (w >> 2) * 32;
    float acc[4][4];
#pragma unroll
    for (int i = 0; i < 4; i++)
#pragma unroll
        for (int q = 0; q < 4; q++) acc[i][q] = 0.f;
#pragma unroll
    for (int kt = 0; kt < 2; kt++) {
        int col = kt * 16 + 2 * tig;
        uint32_t ah[4];
        ldfragA<40>(ah, Ch, m0 + g, col);
#pragma unroll
        for (int nt = 0; nt < 4; nt++) {
            uint32_t bh[2];
            ldfragB<40>(bh, Sh, n0 + nt * 8 + g, col);
            mma16816h(acc[nt], ah, bh);
        }
    }
    int l0 = m0 + g, l1 = l0 + 8;
    float el0 = __expf(acs[l0]), el1 = __expf(acs[l1]);
#pragma unroll
    for (int nt = 0; nt < 4; nt++) {
        int p0 = n0 + nt * 8 + 2 * tig;
        float* y0 = g_y + (size_t)(rowbase + l0) * DIN + h * HD + p0;
        float* y1 = g_y + (size_t)(rowbase + l1) * DIN + h * HD + p0;
        float2 v0 = *(float2*)y0, v1 = *(float2*)y1;
        v0.x += el0 * acc[nt][0]; v0.y += el0 * acc[nt][1];
        v1.x += el1 * acc[nt][2]; v1.y += el1 * acc[nt][3];
        *(float2*)y0 = v0;
        *(float2*)y1 = v1;
    }
}

// ---------------- gate + RMSNorm -> fp16 A (fp16 z in) ----------------
__global__ __launch_bounds__(256) void gate_kernel(const float* __restrict__ rms_w)
{
    int row = blockIdx.x;
    int tid = threadIdx.x;
    const float* yr = g_y + (size_t)row * DIN;
    const unsigned short* zr = g_zxh + (size_t)row * DPROJ;
    float v[8]; float s2 = 0.f;
#pragma unroll
    for (int i = 0; i < 8; i++) {
        int idx = tid + i * 256;
        float y = yr[idx];
        float z = h2f(zr[idx]);
        y *= siluf(z);
        v[i] = y;
        s2 = fmaf(y, y, s2);
    }
    for (int o = 16; o; o >>= 1) s2 += __shfl_down_sync(0xffffffffu, s2, o);
    __shared__ float red[8];
    if ((tid & 31) == 0) red[tid >> 5] = s2;
    __syncthreads();
    if (tid == 0) {
        float t = 0.f;
        for (int i = 0; i < 8; i++) t += red[i];
        red[0] = rsqrtf(t / DIN + 1e-6f);
    }
    __syncthreads();
    float sc = red[0];
    size_t base = (size_t)row * DIN;
#pragma unroll
    for (int i = 0; i < 8; i++) {
        int idx = tid + i * 256;
        g_Ahf[base + idx] = f2h(v[i] * sc * rms_w[idx]);
    }
}

// ---------------- launch ----------------
extern "C" void kernel_launch(void* const* d_in, const int* in_sizes, int n_in,
                              void* d_out, int out_size)
{
    (void)in_sizes; (void)n_in; (void)out_size;
    const float* x       = (const float*)d_in[0];
    const float* ln_w    = (const float*)d_in[1];
    const float* ln_b    = (const float*)d_in[2];
    const float* W_in    = (const float*)d_in[3];
    const float* dt_bias = (const float*)d_in[4];
    const float* A_log   = (const float*)d_in[5];
    const float* Dv      = (const float*)d_in[6];
    const float* rms_w   = (const float*)d_in[7];
    const float* W_out   = (const float*)d_in[8];
    float* out = (float*)d_out;

    void *pzxh, *pdt, *pA, *pB;
    cudaGetSymbolAddress(&pzxh, g_zxh);
    cudaGetSymbolAddress(&pdt,  g_dtraw);
    cudaGetSymbolAddress(&pA,   g_Ahf);
    cudaGetSymbolAddress(&pB,   g_Bthi);

    static int attr_done = 0;
    if (!attr_done) {
        cudaFuncSetAttribute(mma_gemm, cudaFuncAttributeMaxDynamicSharedMemorySize, SMEM_GEMM);
        attr_done = 1;
    }

    ln_kernel<<<MROWS, 256>>>(x, ln_w, ln_b);
    cvtT_kernel<<<dim3(DIMX / 32, NPAD_IN / 32), dim3(32, 32)>>>(W_in, DIMX, DPROJ);
    mma_gemm<<<dim3(33, 128), 256, SMEM_GEMM>>>(
        (const unsigned short*)pA, (const unsigned short*)pB,
        (const float*)0, (float*)0,
        (unsigned short*)pzxh, (float*)pdt, DPROJ, DIMX);
    bcrope_kernel<<<MROWS / 8, 256>>>();
    dtacs_kernel<<<4 * NC, 256>>>(dt_bias, A_log);
    score_kernel<<<4 * NC, 256>>>();
    chunk_kernel<<<4 * NC * NH, 256>>>(Dv);
    scan_kernel<<<4 * NH * 8, 256>>>();
    yo_kernel<<<4 * NC * NH, 256>>>();
    gate_kernel<<<MROWS, 256>>>(rms_w);
    cvtT_kernel<<<dim3(DIN / 32, DIMX / 32), dim3(32, 32)>>>(W_out, DIN, DIMX);
    mma_gemm<<<dim3(8, 128), 256, SMEM_GEMM>>>(
        (const unsigned short*)pA, (const unsigned short*)pB,
        x, out, (unsigned short*)0, (float*)0, DIMX, DIN);
}